// round 1
// baseline (speedup 1.0000x reference)
#include <cuda_runtime.h>
#include <math.h>

#define B_  2
#define S_  2048
#define D_  1024
#define H_  16
#define DH_ 64
#define QKDIM 2048           // 2*H*Dh
#define NEGV (-1000000000.0f)
#define LAMBDA_INIT 0.8f
#define EPS_ 1e-5f

// ---------------- scratch (device globals; no cudaMalloc allowed) ----------
__device__ float g_q[(size_t)B_ * S_ * QKDIM];    // [4096, 2048]
__device__ float g_k[(size_t)B_ * S_ * QKDIM];    // [4096, 2048]
__device__ float g_v[(size_t)B_ * S_ * H_ * DH_]; // [4096, 1024]
__device__ float g_o[(size_t)B_ * S_ * H_ * DH_]; // attention out [4096, 1024]
__device__ float g_n[(size_t)B_ * S_ * H_ * DH_]; // normed        [4096, 1024]
__device__ float g_lambda;
__device__ float g_stats[B_ * H_ * 2];            // mean, inv_std per (b,h)

// ---------------- lambda = exp(q1.k1) - exp(q2.k2) + 0.8 -------------------
__global__ void lam_kernel(const float* __restrict__ lq1, const float* __restrict__ lq2,
                           const float* __restrict__ lk1, const float* __restrict__ lk2) {
    float d1 = 0.f, d2 = 0.f;
    for (int i = 0; i < DH_; i++) { d1 += lq1[i] * lk1[i]; d2 += lq2[i] * lk2[i]; }
    g_lambda = expf(d1) - expf(d2) + LAMBDA_INIT;
}

// ---------------- SGEMM: C[M,N] = A[M,K] * B[N,K]^T (all row-major) --------
// BM=BN=128, BK=16, 256 threads, 8x8 micro-tile. M,N,K multiples of 128/128/16.
__global__ void __launch_bounds__(256) sgemm_nt(const float* __restrict__ A,
                                                const float* __restrict__ Bm,
                                                float* __restrict__ C,
                                                int M, int N, int K) {
    __shared__ float As[16][128];
    __shared__ float Bs[16][128];
    const int tid = threadIdx.x;
    const int bm = blockIdx.y * 128, bn = blockIdx.x * 128;
    const int tx = tid & 15, ty = tid >> 4;
    const int lrow = tid >> 2;        // 0..63
    const int lcol4 = (tid & 3) * 4;  // 0,4,8,12

    float acc[8][8];
#pragma unroll
    for (int i = 0; i < 8; i++)
#pragma unroll
        for (int j = 0; j < 8; j++) acc[i][j] = 0.f;

    for (int k0 = 0; k0 < K; k0 += 16) {
#pragma unroll
        for (int p = 0; p < 2; p++) {
            int r = lrow + p * 64;
            float4 va = *(const float4*)&A[(size_t)(bm + r) * K + k0 + lcol4];
            As[lcol4 + 0][r] = va.x; As[lcol4 + 1][r] = va.y;
            As[lcol4 + 2][r] = va.z; As[lcol4 + 3][r] = va.w;
            float4 vb = *(const float4*)&Bm[(size_t)(bn + r) * K + k0 + lcol4];
            Bs[lcol4 + 0][r] = vb.x; Bs[lcol4 + 1][r] = vb.y;
            Bs[lcol4 + 2][r] = vb.z; Bs[lcol4 + 3][r] = vb.w;
        }
        __syncthreads();
#pragma unroll
        for (int kk = 0; kk < 16; kk++) {
            float ra[8], rb[8];
#pragma unroll
            for (int i = 0; i < 4; i++) {
                ((float4*)ra)[0] = *(const float4*)&As[kk][ty * 8];
                ((float4*)ra)[1] = *(const float4*)&As[kk][ty * 8 + 4];
                ((float4*)rb)[0] = *(const float4*)&Bs[kk][tx * 8];
                ((float4*)rb)[1] = *(const float4*)&Bs[kk][tx * 8 + 4];
                break;
            }
#pragma unroll
            for (int i = 0; i < 8; i++)
#pragma unroll
                for (int j = 0; j < 8; j++) acc[i][j] += ra[i] * rb[j];
        }
        __syncthreads();
    }
#pragma unroll
    for (int i = 0; i < 8; i++) {
        float* crow = &C[(size_t)(bm + ty * 8 + i) * N + bn + tx * 8];
        *(float4*)&crow[0] = make_float4(acc[i][0], acc[i][1], acc[i][2], acc[i][3]);
        *(float4*)&crow[4] = make_float4(acc[i][4], acc[i][5], acc[i][6], acc[i][7]);
    }
}

// ---------------- dual flash attention -------------------------------------
// grid: (S/64, B*H). block 256. One 64-query tile; loops causal 64-key tiles.
// Two independent online softmaxes (components 1 & 2); epilogue combines with
// lambda. Positions are the sequence indices (token_indices == arange here).
#define LD 65
#define TSZ (64 * LD)

__global__ void __launch_bounds__(256) flash_kernel(const float* __restrict__ amask) {
    extern __shared__ float sm[];
    float* Q1s = sm;
    float* Q2s = Q1s + TSZ;
    float* K1s = Q2s + TSZ;
    float* K2s = K1s + TSZ;
    float* Vs  = K2s + TSZ;
    float* S1s = Vs  + TSZ;
    float* S2s = S1s + TSZ;

    const int qt = blockIdx.x;
    const int bh = blockIdx.y;
    const int b = bh / H_, h = bh % H_;
    const int tid = threadIdx.x;
    const int r = tid >> 2;          // 0..63 query row in tile
    const int g = tid & 3;           // d-col group (16 cols each)
    const float slope = exp2f(-8.0f * (float)(h + 1) / (float)H_);
    const float scale = 0.125f;      // 1/sqrt(64)
    const int qg = qt * 64 + r;      // global query row for this thread

    // load Q tile (64 rows x 128 cols -> Q1s/Q2s)
    {
        const float* qb = g_q + (size_t)(b * S_ + qt * 64) * QKDIM + h * 128;
#pragma unroll
        for (int i = 0; i < 8; i++) {
            int f = tid + i * 256;            // float4 index 0..2047
            int rr = f >> 5, c = (f & 31) * 4;
            float4 v = *(const float4*)&qb[(size_t)rr * QKDIM + c];
            float* dst = (c < 64) ? &Q1s[rr * LD + c] : &Q2s[rr * LD + c - 64];
            dst[0] = v.x; dst[1] = v.y; dst[2] = v.z; dst[3] = v.w;
        }
    }

    float m1 = -INFINITY, l1 = 0.f, m2 = -INFINITY, l2 = 0.f;
    float acc1[16], acc2[16];
#pragma unroll
    for (int j = 0; j < 16; j++) { acc1[j] = 0.f; acc2[j] = 0.f; }

    for (int kt = 0; kt <= qt; kt++) {
        __syncthreads();  // previous iter done with K/V/S tiles
        // load K tile
        const float* kb = g_k + (size_t)(b * S_ + kt * 64) * QKDIM + h * 128;
#pragma unroll
        for (int i = 0; i < 8; i++) {
            int f = tid + i * 256;
            int rr = f >> 5, c = (f & 31) * 4;
            float4 v = *(const float4*)&kb[(size_t)rr * QKDIM + c];
            float* dst = (c < 64) ? &K1s[rr * LD + c] : &K2s[rr * LD + c - 64];
            dst[0] = v.x; dst[1] = v.y; dst[2] = v.z; dst[3] = v.w;
        }
        // load V tile
        const float* vb = g_v + (size_t)(b * S_ + kt * 64) * (H_ * DH_) + h * DH_;
#pragma unroll
        for (int i = 0; i < 4; i++) {
            int f = tid + i * 256;            // 0..1023
            int rr = f >> 4, c = (f & 15) * 4;
            float4 v = *(const float4*)&vb[(size_t)rr * (H_ * DH_) + c];
            float* dst = &Vs[rr * LD + c];
            dst[0] = v.x; dst[1] = v.y; dst[2] = v.z; dst[3] = v.w;
        }
        __syncthreads();

        // scores for this thread's row r, cols g*16..g*16+15 (both components)
        {
            float s1[16], s2[16];
#pragma unroll
            for (int j = 0; j < 16; j++) { s1[j] = 0.f; s2[j] = 0.f; }
#pragma unroll 8
            for (int d = 0; d < 64; d++) {
                float q1 = Q1s[r * LD + d];
                float q2 = Q2s[r * LD + d];
#pragma unroll
                for (int j = 0; j < 16; j++) {
                    int c = g * 16 + j;
                    s1[j] += q1 * K1s[c * LD + d];
                    s2[j] += q2 * K2s[c * LD + d];
                }
            }
#pragma unroll
            for (int j = 0; j < 16; j++) {
                int c = g * 16 + j;
                int kg = kt * 64 + c;
                float add = -slope * (float)(qg - kg);
                if (kg > qg) add += NEGV;                       // causal
                add += (1.0f - amask[b * S_ + kg]) * NEGV;       // attention mask
                S1s[r * LD + c] = s1[j] * scale + add;
                S2s[r * LD + c] = s2[j] * scale + add;
            }
        }
        __syncthreads();

        // online softmax update for both components
#pragma unroll
        for (int comp = 0; comp < 2; comp++) {
            float* Ss = comp ? S2s : S1s;
            float m = comp ? m2 : m1;
            float l = comp ? l2 : l1;
            float* acc = comp ? acc2 : acc1;

            float tmax = -INFINITY;
#pragma unroll 16
            for (int k = 0; k < 64; k++) tmax = fmaxf(tmax, Ss[r * LD + k]);
            float mn = fmaxf(m, tmax);
            float alpha = __expf(m - mn);
            l *= alpha;
#pragma unroll
            for (int j = 0; j < 16; j++) acc[j] *= alpha;
#pragma unroll 4
            for (int k = 0; k < 64; k++) {
                float p = __expf(Ss[r * LD + k] - mn);
                l += p;
                const float* vrow = &Vs[k * LD + g * 16];
#pragma unroll
                for (int j = 0; j < 16; j++) acc[j] += p * vrow[j];
            }
            if (comp) { m2 = mn; l2 = l; } else { m1 = mn; l1 = l; }
        }
    }

    // epilogue: o = acc1/l1 - lambda * acc2/l2
    const float lam = g_lambda;
    const float i1 = 1.0f / l1, i2 = 1.0f / l2;
    float* ob = g_o + (size_t)(b * S_ + qg) * (H_ * DH_) + h * DH_ + g * 16;
#pragma unroll
    for (int j = 0; j < 16; j += 4) {
        float4 v = make_float4(acc1[j] * i1 - lam * acc2[j] * i2,
                               acc1[j + 1] * i1 - lam * acc2[j + 1] * i2,
                               acc1[j + 2] * i1 - lam * acc2[j + 2] * i2,
                               acc1[j + 3] * i1 - lam * acc2[j + 3] * i2);
        *(float4*)ob = v;
        ob += 4;
    }
}

// ---------------- group norm stats: per (b,h) over (S, Dh) ------------------
__global__ void __launch_bounds__(256) gn_stats_kernel() {
    const int bh = blockIdx.x;
    const int b = bh / H_, h = bh % H_;
    double s = 0.0, ss = 0.0;
    for (int f = threadIdx.x; f < S_ * (DH_ / 4); f += blockDim.x) {
        int row = f >> 4, c = (f & 15) * 4;
        float4 v = *(const float4*)&g_o[(size_t)(b * S_ + row) * (H_ * DH_) + h * DH_ + c];
        s += (double)v.x + v.y + v.z + v.w;
        ss += (double)v.x * v.x + (double)v.y * v.y + (double)v.z * v.z + (double)v.w * v.w;
    }
    __shared__ double sh_s[256], sh_ss[256];
    sh_s[threadIdx.x] = s; sh_ss[threadIdx.x] = ss;
    __syncthreads();
    for (int st = 128; st > 0; st >>= 1) {
        if (threadIdx.x < st) {
            sh_s[threadIdx.x] += sh_s[threadIdx.x + st];
            sh_ss[threadIdx.x] += sh_ss[threadIdx.x + st];
        }
        __syncthreads();
    }
    if (threadIdx.x == 0) {
        double n = (double)S_ * DH_;
        double mean = sh_s[0] / n;
        double var = sh_ss[0] / n - mean * mean;
        g_stats[bh * 2 + 0] = (float)mean;
        g_stats[bh * 2 + 1] = rsqrtf((float)var + EPS_);
    }
}

// ---------------- normalize: g_n = ((o-mean)*inv*gamma+beta) * 0.2 ----------
__global__ void __launch_bounds__(256) gn_apply_kernel(const float* __restrict__ gamma,
                                                       const float* __restrict__ beta) {
    int f = blockIdx.x * blockDim.x + threadIdx.x;         // float4 index
    if (f >= (B_ * S_ * H_ * DH_) / 4) return;
    int e = f * 4;
    int row = e / (H_ * DH_);
    int c = e % (H_ * DH_);
    int b = row / S_;
    int h = c / DH_;
    float mean = g_stats[(b * H_ + h) * 2 + 0];
    float inv  = g_stats[(b * H_ + h) * 2 + 1];
    float4 x = *(const float4*)&g_o[e];
    float4 gm = *(const float4*)&gamma[c];
    float4 bt = *(const float4*)&beta[c];
    const float post = 1.0f - LAMBDA_INIT;
    float4 y;
    y.x = ((x.x - mean) * inv * gm.x + bt.x) * post;
    y.y = ((x.y - mean) * inv * gm.y + bt.y) * post;
    y.z = ((x.z - mean) * inv * gm.z + bt.z) * post;
    y.w = ((x.w - mean) * inv * gm.w + bt.w) * post;
    *(float4*)&g_n[e] = y;
}

// ---------------- launch ----------------------------------------------------
extern "C" void kernel_launch(void* const* d_in, const int* in_sizes, int n_in,
                              void* d_out, int out_size) {
    const float* x     = (const float*)d_in[0];
    const float* amask = (const float*)d_in[1];
    // d_in[2] = token_indices (== arange; positions derived from indices, not read)
    const float* Wq = (const float*)d_in[3];
    const float* Wk = (const float*)d_in[4];
    const float* Wv = (const float*)d_in[5];
    const float* Wo = (const float*)d_in[6];
    const float* lq1 = (const float*)d_in[7];
    const float* lq2 = (const float*)d_in[8];
    const float* lk1 = (const float*)d_in[9];
    const float* lk2 = (const float*)d_in[10];
    const float* gam = (const float*)d_in[11];
    const float* bet = (const float*)d_in[12];
    float* out = (float*)d_out;

    float *qb, *kb, *vb, *nb;
    cudaGetSymbolAddress((void**)&qb, g_q);
    cudaGetSymbolAddress((void**)&kb, g_k);
    cudaGetSymbolAddress((void**)&vb, g_v);
    cudaGetSymbolAddress((void**)&nb, g_n);

    const int M = B_ * S_;   // 4096

    lam_kernel<<<1, 1>>>(lq1, lq2, lk1, lk2);

    // projections
    sgemm_nt<<<dim3(QKDIM / 128, M / 128), 256>>>(x, Wq, qb, M, QKDIM, D_);
    sgemm_nt<<<dim3(QKDIM / 128, M / 128), 256>>>(x, Wk, kb, M, QKDIM, D_);
    sgemm_nt<<<dim3((H_ * DH_) / 128, M / 128), 256>>>(x, Wv, vb, M, H_ * DH_, D_);

    // attention
    static int smem_set = 0;
    int smem = 7 * TSZ * sizeof(float);  // 116480
    if (!smem_set) {
        cudaFuncSetAttribute(flash_kernel, cudaFuncAttributeMaxDynamicSharedMemorySize, smem);
        smem_set = 1;
    }
    flash_kernel<<<dim3(S_ / 64, B_ * H_), 256, smem>>>(amask);

    // group norm + scale
    gn_stats_kernel<<<B_ * H_, 256>>>();
    gn_apply_kernel<<<(B_ * S_ * H_ * DH_ / 4 + 255) / 256, 256>>>(gam, bet);

    // output projection -> d_out
    sgemm_nt<<<dim3(D_ / 128, M / 128), 256>>>(nb, Wo, out, M, D_, H_ * DH_);
}

// round 2
// speedup vs baseline: 2.4410x; 2.4410x over previous
#include <cuda_runtime.h>
#include <math.h>

#define B_  2
#define S_  2048
#define D_  1024
#define H_  16
#define DH_ 64
#define QKDIM 2048           // 2*H*Dh
#define NEGV (-1000000000.0f)
#define LAMBDA_INIT 0.8f
#define EPS_ 1e-5f

// ---------------- scratch (device globals; no cudaMalloc allowed) ----------
__device__ float g_q [(size_t)B_ * S_ * QKDIM];    // [4096, 2048]
__device__ float g_k [(size_t)B_ * S_ * QKDIM];    // [4096, 2048]
__device__ float g_v [(size_t)B_ * S_ * H_ * DH_]; // [4096, 1024]
__device__ float g_o1[(size_t)B_ * S_ * H_ * DH_]; // comp-1 attention out
__device__ float g_o2[(size_t)B_ * S_ * H_ * DH_]; // comp-2 attention out
__device__ float g_o [(size_t)B_ * S_ * H_ * DH_]; // combined
__device__ float g_n [(size_t)B_ * S_ * H_ * DH_]; // normed
__device__ float g_lambda;
__device__ float g_stats[B_ * H_ * 2];             // mean, inv_std per (b,h)

// ---------------- lambda = exp(q1.k1) - exp(q2.k2) + 0.8 -------------------
__global__ void lam_kernel(const float* __restrict__ lq1, const float* __restrict__ lq2,
                           const float* __restrict__ lk1, const float* __restrict__ lk2) {
    float d1 = 0.f, d2 = 0.f;
    for (int i = 0; i < DH_; i++) { d1 += lq1[i] * lk1[i]; d2 += lq2[i] * lk2[i]; }
    g_lambda = expf(d1) - expf(d2) + LAMBDA_INIT;
}

// ---------------- SGEMM: C[M,N] = A[M,K] * B[N,K]^T (all row-major) --------
__global__ void __launch_bounds__(256) sgemm_nt(const float* __restrict__ A,
                                                const float* __restrict__ Bm,
                                                float* __restrict__ C,
                                                int M, int N, int K) {
    __shared__ float As[16][128];
    __shared__ float Bs[16][128];
    const int tid = threadIdx.x;
    const int bm = blockIdx.y * 128, bn = blockIdx.x * 128;
    const int tx = tid & 15, ty = tid >> 4;
    const int lrow = tid >> 2;
    const int lcol4 = (tid & 3) * 4;

    float acc[8][8];
#pragma unroll
    for (int i = 0; i < 8; i++)
#pragma unroll
        for (int j = 0; j < 8; j++) acc[i][j] = 0.f;

    for (int k0 = 0; k0 < K; k0 += 16) {
#pragma unroll
        for (int p = 0; p < 2; p++) {
            int r = lrow + p * 64;
            float4 va = *(const float4*)&A[(size_t)(bm + r) * K + k0 + lcol4];
            As[lcol4 + 0][r] = va.x; As[lcol4 + 1][r] = va.y;
            As[lcol4 + 2][r] = va.z; As[lcol4 + 3][r] = va.w;
            float4 vb = *(const float4*)&Bm[(size_t)(bn + r) * K + k0 + lcol4];
            Bs[lcol4 + 0][r] = vb.x; Bs[lcol4 + 1][r] = vb.y;
            Bs[lcol4 + 2][r] = vb.z; Bs[lcol4 + 3][r] = vb.w;
        }
        __syncthreads();
#pragma unroll
        for (int kk = 0; kk < 16; kk++) {
            float ra[8], rb[8];
            ((float4*)ra)[0] = *(const float4*)&As[kk][ty * 8];
            ((float4*)ra)[1] = *(const float4*)&As[kk][ty * 8 + 4];
            ((float4*)rb)[0] = *(const float4*)&Bs[kk][tx * 8];
            ((float4*)rb)[1] = *(const float4*)&Bs[kk][tx * 8 + 4];
#pragma unroll
            for (int i = 0; i < 8; i++)
#pragma unroll
                for (int j = 0; j < 8; j++) acc[i][j] += ra[i] * rb[j];
        }
        __syncthreads();
    }
#pragma unroll
    for (int i = 0; i < 8; i++) {
        float* crow = &C[(size_t)(bm + ty * 8 + i) * N + bn + tx * 8];
        *(float4*)&crow[0] = make_float4(acc[i][0], acc[i][1], acc[i][2], acc[i][3]);
        *(float4*)&crow[4] = make_float4(acc[i][4], acc[i][5], acc[i][6], acc[i][7]);
    }
}

// ---------------- flash attention, one component per CTA -------------------
// grid (S/128, B*H*2). 256 threads. Q tile 128x64, K tile 64x64.
// Register-tiled QK and PV gemms (8x4 micro-tile), xor-swizzled smem.
#define BQ 128
#define BK 64

// smem float offsets
#define OFF_Q 0                    // Qs[d][q]   64 x 128 (swizzled)
#define OFF_K (OFF_Q + 64 * 128)   // Ks[d][k]   64 x 64  (swizzled)
#define OFF_V (OFF_K + 64 * 64)    // Vs[k][d]   64 x 64  (plain)
#define OFF_P (OFF_V + 64 * 64)    // Ps[k][q]   64 x 128 (swizzled)
#define FL_SMEM ((OFF_P + 64 * 128) * 4)

__device__ __forceinline__ int swzQ(int d, int q) {
    return d * 128 + ((((q >> 2) ^ (d >> 2)) & 31) * 4 + (q & 3));
}
__device__ __forceinline__ int swzK(int d, int k) {
    return d * 64 + ((((k >> 2) ^ (d >> 2)) & 15) * 4 + (k & 3));
}
__device__ __forceinline__ int swzP(int k, int q) {
    return k * 128 + ((((q >> 2) ^ (k >> 2)) & 31) * 4 + (q & 3));
}

__global__ void __launch_bounds__(256) flash2_kernel(const float* __restrict__ amask) {
    extern __shared__ float sm[];
    float* Qs = sm + OFF_Q;
    float* Ks = sm + OFF_K;
    float* Vs = sm + OFF_V;
    float* Ps = sm + OFF_P;

    const int tid = threadIdx.x;
    const int qg = tid >> 4;     // 0..15 : 8 q rows
    const int kg = tid & 15;     // 0..15 : 4 k cols (QK) / 4 d cols (PV)
    const int qt = (gridDim.x - 1) - blockIdx.x;   // heavy tiles first
    const int z = blockIdx.y;
    const int comp = z & 1;
    const int bh = z >> 1;
    const int b = bh / H_, h = bh % H_;
    const float slope = exp2f(-8.0f * (float)(h + 1) / (float)H_);
    const float scale = 0.125f;

    // ---- load Q tile (transposed + swizzled) ----
    {
        const float* Qg = g_q + ((size_t)(b * S_) + qt * BQ) * QKDIM + h * 128 + comp * 64;
#pragma unroll
        for (int i = 0; i < 8; i++) {
            int f = tid + i * 256;            // 0..2047 float4 ids
            int q = f >> 4, d4 = (f & 15) * 4;
            float4 v = *(const float4*)&Qg[(size_t)q * QKDIM + d4];
            Qs[swzQ(d4 + 0, q)] = v.x; Qs[swzQ(d4 + 1, q)] = v.y;
            Qs[swzQ(d4 + 2, q)] = v.z; Qs[swzQ(d4 + 3, q)] = v.w;
        }
    }

    float m[8], l[8], alpha[8], o[8][4];
#pragma unroll
    for (int i = 0; i < 8; i++) {
        m[i] = -INFINITY; l[i] = 0.f;
#pragma unroll
        for (int j = 0; j < 4; j++) o[i][j] = 0.f;
    }

    const int ktmax = 2 * qt + 1;
    for (int kt = 0; kt <= ktmax; kt++) {
        __syncthreads();   // previous iter done with Ks/Vs/Ps
        // ---- load K tile (transposed + swizzled) and V tile (plain) ----
        {
            const float* Kg = g_k + ((size_t)(b * S_) + kt * 64) * QKDIM + h * 128 + comp * 64;
            const float* Vg = g_v + ((size_t)(b * S_) + kt * 64) * (H_ * DH_) + h * 64;
#pragma unroll
            for (int i = 0; i < 4; i++) {
                int f = tid + i * 256;        // 0..1023
                int k = f >> 4, d4 = (f & 15) * 4;
                float4 v = *(const float4*)&Kg[(size_t)k * QKDIM + d4];
                Ks[swzK(d4 + 0, k)] = v.x; Ks[swzK(d4 + 1, k)] = v.y;
                Ks[swzK(d4 + 2, k)] = v.z; Ks[swzK(d4 + 3, k)] = v.w;
                float4 w = *(const float4*)&Vg[(size_t)k * (H_ * DH_) + d4];
                *(float4*)&Vs[k * 64 + d4] = w;
            }
        }
        __syncthreads();

        // ---- QK^T: s[8][4] ----
        float s[8][4];
#pragma unroll
        for (int i = 0; i < 8; i++)
#pragma unroll
            for (int j = 0; j < 4; j++) s[i][j] = 0.f;
#pragma unroll 8
        for (int d = 0; d < 64; d++) {
            int dw = d >> 2;
            float4 q0 = *(const float4*)&Qs[d * 128 + ((((qg * 2)     ^ dw) & 31) * 4)];
            float4 q1 = *(const float4*)&Qs[d * 128 + ((((qg * 2 + 1) ^ dw) & 31) * 4)];
            float4 kk = *(const float4*)&Ks[d * 64  + (((kg ^ dw) & 15) * 4)];
            float qa[8] = {q0.x, q0.y, q0.z, q0.w, q1.x, q1.y, q1.z, q1.w};
            float kb[4] = {kk.x, kk.y, kk.z, kk.w};
#pragma unroll
            for (int i = 0; i < 8; i++)
#pragma unroll
                for (int j = 0; j < 4; j++) s[i][j] += qa[i] * kb[j];
        }

        // ---- bias + masks ----
        const int q0g = qt * BQ + qg * 8;
        const int k0g = kt * 64 + kg * 4;
        float am[4];
#pragma unroll
        for (int j = 0; j < 4; j++)
            am[j] = (1.0f - amask[b * S_ + k0g + j]) * NEGV;
#pragma unroll
        for (int i = 0; i < 8; i++) {
            int qa = q0g + i;
#pragma unroll
            for (int j = 0; j < 4; j++) {
                int ka = k0g + j;
                float v = s[i][j] * scale - slope * (float)(qa - ka) + am[j];
                if (ka > qa) v += NEGV;
                s[i][j] = v;
            }
        }

        // ---- online softmax (reduce across the 16 kg lanes) ----
#pragma unroll
        for (int i = 0; i < 8; i++) {
            float mx = fmaxf(fmaxf(s[i][0], s[i][1]), fmaxf(s[i][2], s[i][3]));
#pragma unroll
            for (int off = 1; off < 16; off <<= 1)
                mx = fmaxf(mx, __shfl_xor_sync(0xffffffffu, mx, off));
            float mn = fmaxf(m[i], mx);
            float al = __expf(m[i] - mn);
            m[i] = mn;
            float ls = 0.f;
#pragma unroll
            for (int j = 0; j < 4; j++) {
                float p = __expf(s[i][j] - mn);
                s[i][j] = p;
                ls += p;
            }
#pragma unroll
            for (int off = 1; off < 16; off <<= 1)
                ls += __shfl_xor_sync(0xffffffffu, ls, off);
            l[i] = l[i] * al + ls;
            alpha[i] = al;
        }

        // ---- store P (swizzled, q-vectorized) ----
#pragma unroll
        for (int j = 0; j < 4; j++) {
            int k = kg * 4 + j;
            int kw = k >> 2;
            *(float4*)&Ps[k * 128 + ((((qg * 2)     ^ kw) & 31) * 4)] =
                make_float4(s[0][j], s[1][j], s[2][j], s[3][j]);
            *(float4*)&Ps[k * 128 + ((((qg * 2 + 1) ^ kw) & 31) * 4)] =
                make_float4(s[4][j], s[5][j], s[6][j], s[7][j]);
        }
        __syncthreads();

        // ---- PV: o[8][4] over d-cols kg*4..+3 ----
#pragma unroll
        for (int i = 0; i < 8; i++)
#pragma unroll
            for (int j = 0; j < 4; j++) o[i][j] *= alpha[i];
#pragma unroll 8
        for (int k = 0; k < 64; k++) {
            int kw = k >> 2;
            float4 p0 = *(const float4*)&Ps[k * 128 + ((((qg * 2)     ^ kw) & 31) * 4)];
            float4 p1 = *(const float4*)&Ps[k * 128 + ((((qg * 2 + 1) ^ kw) & 31) * 4)];
            float4 vv = *(const float4*)&Vs[k * 64 + kg * 4];
            float pa[8] = {p0.x, p0.y, p0.z, p0.w, p1.x, p1.y, p1.z, p1.w};
            float vb[4] = {vv.x, vv.y, vv.z, vv.w};
#pragma unroll
            for (int i = 0; i < 8; i++)
#pragma unroll
                for (int j = 0; j < 4; j++) o[i][j] += pa[i] * vb[j];
        }
    }

    // ---- epilogue: divide by l, write per-component output ----
    float* Og = (comp ? g_o2 : g_o1) + ((size_t)(b * S_) + qt * BQ) * (H_ * DH_) + h * 64 + kg * 4;
#pragma unroll
    for (int i = 0; i < 8; i++) {
        float inv = 1.0f / l[i];
        *(float4*)&Og[(size_t)(qg * 8 + i) * (H_ * DH_)] =
            make_float4(o[i][0] * inv, o[i][1] * inv, o[i][2] * inv, o[i][3] * inv);
    }
}

// ---------------- combine: g_o = o1 - lambda*o2 -----------------------------
__global__ void __launch_bounds__(256) combine_kernel() {
    int f = blockIdx.x * blockDim.x + threadIdx.x;
    if (f >= (B_ * S_ * H_ * DH_) / 4) return;
    int e = f * 4;
    float lam = g_lambda;
    float4 a = *(const float4*)&g_o1[e];
    float4 c = *(const float4*)&g_o2[e];
    float4 y;
    y.x = a.x - lam * c.x; y.y = a.y - lam * c.y;
    y.z = a.z - lam * c.z; y.w = a.w - lam * c.w;
    *(float4*)&g_o[e] = y;
}

// ---------------- group norm stats: per (b,h) over (S, Dh) ------------------
__global__ void __launch_bounds__(256) gn_stats_kernel() {
    const int bh = blockIdx.x;
    const int b = bh / H_, h = bh % H_;
    double s = 0.0, ss = 0.0;
    for (int f = threadIdx.x; f < S_ * (DH_ / 4); f += blockDim.x) {
        int row = f >> 4, c = (f & 15) * 4;
        float4 v = *(const float4*)&g_o[(size_t)(b * S_ + row) * (H_ * DH_) + h * DH_ + c];
        s += (double)v.x + v.y + v.z + v.w;
        ss += (double)v.x * v.x + (double)v.y * v.y + (double)v.z * v.z + (double)v.w * v.w;
    }
    __shared__ double sh_s[256], sh_ss[256];
    sh_s[threadIdx.x] = s; sh_ss[threadIdx.x] = ss;
    __syncthreads();
    for (int st = 128; st > 0; st >>= 1) {
        if (threadIdx.x < st) {
            sh_s[threadIdx.x] += sh_s[threadIdx.x + st];
            sh_ss[threadIdx.x] += sh_ss[threadIdx.x + st];
        }
        __syncthreads();
    }
    if (threadIdx.x == 0) {
        double n = (double)S_ * DH_;
        double mean = sh_s[0] / n;
        double var = sh_ss[0] / n - mean * mean;
        g_stats[bh * 2 + 0] = (float)mean;
        g_stats[bh * 2 + 1] = rsqrtf((float)var + EPS_);
    }
}

// ---------------- normalize: g_n = ((o-mean)*inv*gamma+beta) * 0.2 ----------
__global__ void __launch_bounds__(256) gn_apply_kernel(const float* __restrict__ gamma,
                                                       const float* __restrict__ beta) {
    int f = blockIdx.x * blockDim.x + threadIdx.x;
    if (f >= (B_ * S_ * H_ * DH_) / 4) return;
    int e = f * 4;
    int row = e / (H_ * DH_);
    int c = e % (H_ * DH_);
    int b = row / S_;
    int h = c / DH_;
    float mean = g_stats[(b * H_ + h) * 2 + 0];
    float inv  = g_stats[(b * H_ + h) * 2 + 1];
    float4 x = *(const float4*)&g_o[e];
    float4 gm = *(const float4*)&gamma[c];
    float4 bt = *(const float4*)&beta[c];
    const float post = 1.0f - LAMBDA_INIT;
    float4 y;
    y.x = ((x.x - mean) * inv * gm.x + bt.x) * post;
    y.y = ((x.y - mean) * inv * gm.y + bt.y) * post;
    y.z = ((x.z - mean) * inv * gm.z + bt.z) * post;
    y.w = ((x.w - mean) * inv * gm.w + bt.w) * post;
    *(float4*)&g_n[e] = y;
}

// ---------------- launch ----------------------------------------------------
extern "C" void kernel_launch(void* const* d_in, const int* in_sizes, int n_in,
                              void* d_out, int out_size) {
    const float* x     = (const float*)d_in[0];
    const float* amask = (const float*)d_in[1];
    // d_in[2] = token_indices (== arange; positions derived from indices, not read)
    const float* Wq = (const float*)d_in[3];
    const float* Wk = (const float*)d_in[4];
    const float* Wv = (const float*)d_in[5];
    const float* Wo = (const float*)d_in[6];
    const float* lq1 = (const float*)d_in[7];
    const float* lq2 = (const float*)d_in[8];
    const float* lk1 = (const float*)d_in[9];
    const float* lk2 = (const float*)d_in[10];
    const float* gam = (const float*)d_in[11];
    const float* bet = (const float*)d_in[12];
    float* out = (float*)d_out;

    float *qb, *kb, *vb, *nb;
    cudaGetSymbolAddress((void**)&qb, g_q);
    cudaGetSymbolAddress((void**)&kb, g_k);
    cudaGetSymbolAddress((void**)&vb, g_v);
    cudaGetSymbolAddress((void**)&nb, g_n);

    const int M = B_ * S_;   // 4096

    lam_kernel<<<1, 1>>>(lq1, lq2, lk1, lk2);

    // projections
    sgemm_nt<<<dim3(QKDIM / 128, M / 128), 256>>>(x, Wq, qb, M, QKDIM, D_);
    sgemm_nt<<<dim3(QKDIM / 128, M / 128), 256>>>(x, Wk, kb, M, QKDIM, D_);
    sgemm_nt<<<dim3((H_ * DH_) / 128, M / 128), 256>>>(x, Wv, vb, M, H_ * DH_, D_);

    // attention (per-component flash)
    cudaFuncSetAttribute(flash2_kernel, cudaFuncAttributeMaxDynamicSharedMemorySize, FL_SMEM);
    flash2_kernel<<<dim3(S_ / BQ, B_ * H_ * 2), 256, FL_SMEM>>>(amask);

    // combine + group norm + scale
    combine_kernel<<<(B_ * S_ * H_ * DH_ / 4 + 255) / 256, 256>>>();
    gn_stats_kernel<<<B_ * H_, 256>>>();
    gn_apply_kernel<<<(B_ * S_ * H_ * DH_ / 4 + 255) / 256, 256>>>(gam, bet);

    // output projection -> d_out
    sgemm_nt<<<dim3(D_ / 128, M / 128), 256>>>(nb, Wo, out, M, D_, H_ * DH_);
}

// round 4
// speedup vs baseline: 3.6008x; 1.4751x over previous
#include <cuda_runtime.h>
#include <cuda_bf16.h>
#include <math.h>
#include <cstdint>

#define B_  2
#define S_  2048
#define D_  1024
#define H_  16
#define DH_ 64
#define QKDIM 2048
#define NEGV (-1000000000.0f)
#define LAMBDA_INIT 0.8f
#define EPS_ 1e-5f

// ---------------- scratch (device globals) ---------------------------------
__device__ float g_q [(size_t)B_ * S_ * QKDIM];
__device__ float g_k [(size_t)B_ * S_ * QKDIM];
__device__ float g_v [(size_t)B_ * S_ * H_ * DH_];
__device__ float g_o1[(size_t)B_ * S_ * H_ * DH_];
__device__ float g_o2[(size_t)B_ * S_ * H_ * DH_];
__device__ float g_o [(size_t)B_ * S_ * H_ * DH_];
__device__ float g_lambda;
__device__ float g_stats[B_ * H_ * 2];

// bf16 split buffers
__device__ __nv_bfloat16 g_xh[(size_t)B_ * S_ * D_], g_xl[(size_t)B_ * S_ * D_];
__device__ __nv_bfloat16 g_wqh[QKDIM * D_], g_wql[QKDIM * D_];
__device__ __nv_bfloat16 g_wkh[QKDIM * D_], g_wkl[QKDIM * D_];
__device__ __nv_bfloat16 g_wvh[(H_ * DH_) * D_], g_wvl[(H_ * DH_) * D_];
__device__ __nv_bfloat16 g_woh[D_ * (H_ * DH_)], g_wol[D_ * (H_ * DH_)];
__device__ __nv_bfloat16 g_nh[(size_t)B_ * S_ * H_ * DH_], g_nl[(size_t)B_ * S_ * H_ * DH_];

// ---------------- helpers ---------------------------------------------------
__device__ __forceinline__ uint32_t smem_u32(const void* p) {
    uint32_t a;
    asm("{ .reg .u64 t; cvta.to.shared.u64 t, %1; cvt.u32.u64 %0, t; }" : "=r"(a) : "l"(p));
    return a;
}
#define CP16(dst, src) \
    asm volatile("cp.async.cg.shared.global [%0], [%1], 16;" :: "r"(dst), "l"(src) : "memory")
#define CP_COMMIT() asm volatile("cp.async.commit_group;" ::: "memory")
#define CP_WAIT1()  asm volatile("cp.async.wait_group 1;" ::: "memory")
#define CP_WAIT0()  asm volatile("cp.async.wait_group 0;" ::: "memory")

__device__ __forceinline__ void ldsm_x4(uint32_t& r0, uint32_t& r1, uint32_t& r2, uint32_t& r3,
                                        uint32_t addr) {
    asm volatile("ldmatrix.sync.aligned.m8n8.x4.shared.b16 {%0,%1,%2,%3}, [%4];"
                 : "=r"(r0), "=r"(r1), "=r"(r2), "=r"(r3) : "r"(addr));
}
#define MMA16816(d, a, b) \
    asm volatile("mma.sync.aligned.m16n8k16.row.col.f32.bf16.bf16.f32 " \
                 "{%0,%1,%2,%3}, {%4,%5,%6,%7}, {%8,%9}, {%0,%1,%2,%3};" \
                 : "+f"((d)[0]), "+f"((d)[1]), "+f"((d)[2]), "+f"((d)[3]) \
                 : "r"((a)[0]), "r"((a)[1]), "r"((a)[2]), "r"((a)[3]), \
                   "r"((b)[0]), "r"((b)[1]))

// ---------------- lambda ----------------------------------------------------
__global__ void lam_kernel(const float* __restrict__ lq1, const float* __restrict__ lq2,
                           const float* __restrict__ lk1, const float* __restrict__ lk2) {
    float d1 = 0.f, d2 = 0.f;
    for (int i = 0; i < DH_; i++) { d1 += lq1[i] * lk1[i]; d2 += lq2[i] * lk2[i]; }
    g_lambda = expf(d1) - expf(d2) + LAMBDA_INIT;
}

// ---------------- fp32 -> bf16 hi/lo split ----------------------------------
__global__ void __launch_bounds__(256) cvt_kernel(const float* __restrict__ src,
                                                  __nv_bfloat16* __restrict__ h,
                                                  __nv_bfloat16* __restrict__ l, int n4) {
    int i = blockIdx.x * 256 + threadIdx.x;
    if (i >= n4) return;
    float4 v = ((const float4*)src)[i];
    float vv[4] = {v.x, v.y, v.z, v.w};
    __nv_bfloat16 hh[4], ll[4];
#pragma unroll
    for (int j = 0; j < 4; j++) {
        hh[j] = __float2bfloat16(vv[j]);
        ll[j] = __float2bfloat16(vv[j] - __bfloat162float(hh[j]));
    }
    *(uint2*)&h[(size_t)i * 4] = *(uint2*)hh;
    *(uint2*)&l[(size_t)i * 4] = *(uint2*)ll;
}

// ---------------- bf16x3 GEMM via mma.sync ----------------------------------
// C[M,N] = A[M,K] * B[N,K]^T, fp32 out. grid (N/128, M/128), 256 threads.
// SMEM stage: Ah, Al, Bh, Bl each 128 rows x 32 bf16, packed 2 rows per
// 128B physical row, SW128 xor swizzle. Stage 32KB, double buffered.
#define GSTAGE 32768
#define G_SMEM (2 * GSTAGE)

__device__ __forceinline__ void g_issue(
    const __nv_bfloat16* __restrict__ Ah, const __nv_bfloat16* __restrict__ Al,
    const __nv_bfloat16* __restrict__ Bh, const __nv_bfloat16* __restrict__ Bl,
    uint32_t sbuf, int tid, int bm, int bn, int K, int c) {
#pragma unroll
    for (int i = 0; i < 2; i++) {
        int ch = tid + i * 256;                 // 0..511 16B-chunk id
        int p = ch >> 3, c16 = ch & 7;
        int r = (p << 1) + (c16 >> 2);          // logical row 0..127
        int kb = (c16 & 3) * 8;                 // bf16 col offset in 32-wide row
        int off = p * 128 + c16 * 16;
        uint32_t dst = sbuf + (off ^ ((off >> 3) & 0x70));
        size_t ga = (size_t)(bm + r) * K + c * 32 + kb;
        size_t gb = (size_t)(bn + r) * K + c * 32 + kb;
        CP16(dst,         Ah + ga);
        CP16(dst + 8192,  Al + ga);
        CP16(dst + 16384, Bh + gb);
        CP16(dst + 24576, Bl + gb);
    }
    CP_COMMIT();
}

__global__ void __launch_bounds__(256) gemm_mma3(
    const __nv_bfloat16* __restrict__ Ah, const __nv_bfloat16* __restrict__ Al,
    const __nv_bfloat16* __restrict__ Bh, const __nv_bfloat16* __restrict__ Bl,
    float* __restrict__ C, int M, int N, int K) {
    extern __shared__ char smem[];
    const uint32_t sbase = smem_u32(smem);
    const int tid = threadIdx.x, wid = tid >> 5, lane = tid & 31;
    const int bm = blockIdx.y * 128, bn = blockIdx.x * 128;
    const int wm = (wid & 3) * 32;          // warp M offset
    const int wn = (wid >> 2) * 64;         // warp N offset
    const int g = lane >> 3, rl = lane & 7;

    float acc[2][8][4];
#pragma unroll
    for (int a = 0; a < 2; a++)
#pragma unroll
        for (int b = 0; b < 8; b++)
#pragma unroll
            for (int d = 0; d < 4; d++) acc[a][b][d] = 0.f;

    const int nch = K >> 5;
    g_issue(Ah, Al, Bh, Bl, sbase, tid, bm, bn, K, 0);

    for (int c = 0; c < nch; c++) {
        uint32_t sbuf = sbase + (c & 1) * GSTAGE;
        if (c + 1 < nch) {
            g_issue(Ah, Al, Bh, Bl, sbase + ((c + 1) & 1) * GSTAGE, tid, bm, bn, K, c + 1);
            CP_WAIT1();
        } else {
            CP_WAIT0();
        }
        __syncthreads();

#pragma unroll
        for (int ks = 0; ks < 2; ks++) {
            // ---- load A fragments (hi, lo) ----
            uint32_t ah[2][4], al[2][4];
#pragma unroll
            for (int mb = 0; mb < 2; mb++) {
                int r = wm + mb * 16 + ((g & 1) << 3) + rl;
                int c16 = ((r & 1) << 2) + ks * 2 + (g >> 1);
                int off = (r >> 1) * 128 + c16 * 16;
                uint32_t sw = (uint32_t)(off ^ ((off >> 3) & 0x70));
                ldsm_x4(ah[mb][0], ah[mb][1], ah[mb][2], ah[mb][3], sbuf + sw);
                ldsm_x4(al[mb][0], al[mb][1], al[mb][2], al[mb][3], sbuf + 8192 + sw);
            }
            // ---- load B fragments (hi, lo): 4 x4 each, 2 n-blocks per x4 ----
            uint32_t bh[4][4], bl[4][4];
#pragma unroll
            for (int np = 0; np < 4; np++) {
                int r = wn + np * 16 + ((g >> 1) << 3) + rl;
                int c16 = ((r & 1) << 2) + ks * 2 + (g & 1);
                int off = (r >> 1) * 128 + c16 * 16;
                uint32_t sw = (uint32_t)(off ^ ((off >> 3) & 0x70));
                ldsm_x4(bh[np][0], bh[np][1], bh[np][2], bh[np][3], sbuf + 16384 + sw);
                ldsm_x4(bl[np][0], bl[np][1], bl[np][2], bl[np][3], sbuf + 24576 + sw);
            }
            // ---- 48 MMAs: hh + hl + lh ----
#pragma unroll
            for (int mb = 0; mb < 2; mb++)
#pragma unroll
                for (int j = 0; j < 8; j++) {
                    MMA16816(acc[mb][j], ah[mb], &bh[j >> 1][(j & 1) * 2]);
                    MMA16816(acc[mb][j], ah[mb], &bl[j >> 1][(j & 1) * 2]);
                    MMA16816(acc[mb][j], al[mb], &bh[j >> 1][(j & 1) * 2]);
                }
        }
        __syncthreads();
    }

    // ---- epilogue ----
#pragma unroll
    for (int mb = 0; mb < 2; mb++) {
        int row0 = bm + wm + mb * 16 + (lane >> 2);
#pragma unroll
        for (int j = 0; j < 8; j++) {
            int col = bn + wn + j * 8 + (lane & 3) * 2;
            *(float2*)&C[(size_t)row0 * N + col]       = make_float2(acc[mb][j][0], acc[mb][j][1]);
            *(float2*)&C[(size_t)(row0 + 8) * N + col] = make_float2(acc[mb][j][2], acc[mb][j][3]);
        }
    }
}

// ---------------- flash attention (unchanged) -------------------------------
#define BQ 128
#define OFF_Q 0
#define OFF_K (OFF_Q + 64 * 128)
#define OFF_V (OFF_K + 64 * 64)
#define OFF_P (OFF_V + 64 * 64)
#define FL_SMEM ((OFF_P + 64 * 128) * 4)

__device__ __forceinline__ int swzQ(int d, int q) {
    return d * 128 + ((((q >> 2) ^ (d >> 2)) & 31) * 4 + (q & 3));
}
__device__ __forceinline__ int swzK(int d, int k) {
    return d * 64 + ((((k >> 2) ^ (d >> 2)) & 15) * 4 + (k & 3));
}

__global__ void __launch_bounds__(256) flash2_kernel(const float* __restrict__ amask) {
    extern __shared__ float sm[];
    float* Qs = sm + OFF_Q;
    float* Ks = sm + OFF_K;
    float* Vs = sm + OFF_V;
    float* Ps = sm + OFF_P;

    const int tid = threadIdx.x;
    const int qg = tid >> 4;
    const int kg = tid & 15;
    const int qt = (gridDim.x - 1) - blockIdx.x;
    const int z = blockIdx.y;
    const int comp = z & 1;
    const int bh = z >> 1;
    const int b = bh / H_, h = bh % H_;
    const float slope = exp2f(-8.0f * (float)(h + 1) / (float)H_);
    const float scale = 0.125f;

    {
        const float* Qg = g_q + ((size_t)(b * S_) + qt * BQ) * QKDIM + h * 128 + comp * 64;
#pragma unroll
        for (int i = 0; i < 8; i++) {
            int f = tid + i * 256;
            int q = f >> 4, d4 = (f & 15) * 4;
            float4 v = *(const float4*)&Qg[(size_t)q * QKDIM + d4];
            Qs[swzQ(d4 + 0, q)] = v.x; Qs[swzQ(d4 + 1, q)] = v.y;
            Qs[swzQ(d4 + 2, q)] = v.z; Qs[swzQ(d4 + 3, q)] = v.w;
        }
    }

    float m[8], l[8], alpha[8], o[8][4];
#pragma unroll
    for (int i = 0; i < 8; i++) {
        m[i] = -INFINITY; l[i] = 0.f;
#pragma unroll
        for (int j = 0; j < 4; j++) o[i][j] = 0.f;
    }

    const int ktmax = 2 * qt + 1;
    for (int kt = 0; kt <= ktmax; kt++) {
        __syncthreads();
        {
            const float* Kg = g_k + ((size_t)(b * S_) + kt * 64) * QKDIM + h * 128 + comp * 64;
            const float* Vg = g_v + ((size_t)(b * S_) + kt * 64) * (H_ * DH_) + h * 64;
#pragma unroll
            for (int i = 0; i < 4; i++) {
                int f = tid + i * 256;
                int k = f >> 4, d4 = (f & 15) * 4;
                float4 v = *(const float4*)&Kg[(size_t)k * QKDIM + d4];
                Ks[swzK(d4 + 0, k)] = v.x; Ks[swzK(d4 + 1, k)] = v.y;
                Ks[swzK(d4 + 2, k)] = v.z; Ks[swzK(d4 + 3, k)] = v.w;
                float4 w = *(const float4*)&Vg[(size_t)k * (H_ * DH_) + d4];
                *(float4*)&Vs[k * 64 + d4] = w;
            }
        }
        __syncthreads();

        float s[8][4];
#pragma unroll
        for (int i = 0; i < 8; i++)
#pragma unroll
            for (int j = 0; j < 4; j++) s[i][j] = 0.f;
#pragma unroll 8
        for (int d = 0; d < 64; d++) {
            int dw = d >> 2;
            float4 q0 = *(const float4*)&Qs[d * 128 + ((((qg * 2)     ^ dw) & 31) * 4)];
            float4 q1 = *(const float4*)&Qs[d * 128 + ((((qg * 2 + 1) ^ dw) & 31) * 4)];
            float4 kk = *(const float4*)&Ks[d * 64  + (((kg ^ dw) & 15) * 4)];
            float qa[8] = {q0.x, q0.y, q0.z, q0.w, q1.x, q1.y, q1.z, q1.w};
            float kb[4] = {kk.x, kk.y, kk.z, kk.w};
#pragma unroll
            for (int i = 0; i < 8; i++)
#pragma unroll
                for (int j = 0; j < 4; j++) s[i][j] += qa[i] * kb[j];
        }

        const int q0g = qt * BQ + qg * 8;
        const int k0g = kt * 64 + kg * 4;
        float am[4];
#pragma unroll
        for (int j = 0; j < 4; j++)
            am[j] = (1.0f - amask[b * S_ + k0g + j]) * NEGV;
#pragma unroll
        for (int i = 0; i < 8; i++) {
            int qa = q0g + i;
#pragma unroll
            for (int j = 0; j < 4; j++) {
                int ka = k0g + j;
                float v = s[i][j] * scale - slope * (float)(qa - ka) + am[j];
                if (ka > qa) v += NEGV;
                s[i][j] = v;
            }
        }

#pragma unroll
        for (int i = 0; i < 8; i++) {
            float mx = fmaxf(fmaxf(s[i][0], s[i][1]), fmaxf(s[i][2], s[i][3]));
#pragma unroll
            for (int off = 1; off < 16; off <<= 1)
                mx = fmaxf(mx, __shfl_xor_sync(0xffffffffu, mx, off));
            float mn = fmaxf(m[i], mx);
            float al = __expf(m[i] - mn);
            m[i] = mn;
            float ls = 0.f;
#pragma unroll
            for (int j = 0; j < 4; j++) {
                float p = __expf(s[i][j] - mn);
                s[i][j] = p;
                ls += p;
            }
#pragma unroll
            for (int off = 1; off < 16; off <<= 1)
                ls += __shfl_xor_sync(0xffffffffu, ls, off);
            l[i] = l[i] * al + ls;
            alpha[i] = al;
        }

#pragma unroll
        for (int j = 0; j < 4; j++) {
            int k = kg * 4 + j;
            int kw = k >> 2;
            *(float4*)&Ps[k * 128 + ((((qg * 2)     ^ kw) & 31) * 4)] =
                make_float4(s[0][j], s[1][j], s[2][j], s[3][j]);
            *(float4*)&Ps[k * 128 + ((((qg * 2 + 1) ^ kw) & 31) * 4)] =
                make_float4(s[4][j], s[5][j], s[6][j], s[7][j]);
        }
        __syncthreads();

#pragma unroll
        for (int i = 0; i < 8; i++)
#pragma unroll
            for (int j = 0; j < 4; j++) o[i][j] *= alpha[i];
#pragma unroll 8
        for (int k = 0; k < 64; k++) {
            int kw = k >> 2;
            float4 p0 = *(const float4*)&Ps[k * 128 + ((((qg * 2)     ^ kw) & 31) * 4)];
            float4 p1 = *(const float4*)&Ps[k * 128 + ((((qg * 2 + 1) ^ kw) & 31) * 4)];
            float4 vv = *(const float4*)&Vs[k * 64 + kg * 4];
            float pa[8] = {p0.x, p0.y, p0.z, p0.w, p1.x, p1.y, p1.z, p1.w};
            float vb[4] = {vv.x, vv.y, vv.z, vv.w};
#pragma unroll
            for (int i = 0; i < 8; i++)
#pragma unroll
                for (int j = 0; j < 4; j++) o[i][j] += pa[i] * vb[j];
        }
    }

    float* Og = (comp ? g_o2 : g_o1) + ((size_t)(b * S_) + qt * BQ) * (H_ * DH_) + h * 64 + kg * 4;
#pragma unroll
    for (int i = 0; i < 8; i++) {
        float inv = 1.0f / l[i];
        *(float4*)&Og[(size_t)(qg * 8 + i) * (H_ * DH_)] =
            make_float4(o[i][0] * inv, o[i][1] * inv, o[i][2] * inv, o[i][3] * inv);
    }
}

// ---------------- combine ---------------------------------------------------
__global__ void __launch_bounds__(256) combine_kernel() {
    int f = blockIdx.x * blockDim.x + threadIdx.x;
    if (f >= (B_ * S_ * H_ * DH_) / 4) return;
    int e = f * 4;
    float lam = g_lambda;
    float4 a = *(const float4*)&g_o1[e];
    float4 c = *(const float4*)&g_o2[e];
    float4 y;
    y.x = a.x - lam * c.x; y.y = a.y - lam * c.y;
    y.z = a.z - lam * c.z; y.w = a.w - lam * c.w;
    *(float4*)&g_o[e] = y;
}

// ---------------- group norm stats ------------------------------------------
__global__ void __launch_bounds__(256) gn_stats_kernel() {
    const int bh = blockIdx.x;
    const int b = bh / H_, h = bh % H_;
    double s = 0.0, ss = 0.0;
    for (int f = threadIdx.x; f < S_ * (DH_ / 4); f += blockDim.x) {
        int row = f >> 4, c = (f & 15) * 4;
        float4 v = *(const float4*)&g_o[(size_t)(b * S_ + row) * (H_ * DH_) + h * DH_ + c];
        s += (double)v.x + v.y + v.z + v.w;
        ss += (double)v.x * v.x + (double)v.y * v.y + (double)v.z * v.z + (double)v.w * v.w;
    }
    __shared__ double sh_s[256], sh_ss[256];
    sh_s[threadIdx.x] = s; sh_ss[threadIdx.x] = ss;
    __syncthreads();
    for (int st = 128; st > 0; st >>= 1) {
        if (threadIdx.x < st) {
            sh_s[threadIdx.x] += sh_s[threadIdx.x + st];
            sh_ss[threadIdx.x] += sh_ss[threadIdx.x + st];
        }
        __syncthreads();
    }
    if (threadIdx.x == 0) {
        double n = (double)S_ * DH_;
        double mean = sh_s[0] / n;
        double var = sh_ss[0] / n - mean * mean;
        g_stats[bh * 2 + 0] = (float)mean;
        g_stats[bh * 2 + 1] = rsqrtf((float)var + EPS_);
    }
}

// ---------------- normalize + emit bf16 hi/lo -------------------------------
__global__ void __launch_bounds__(256) gn_apply_kernel(const float* __restrict__ gamma,
                                                       const float* __restrict__ beta) {
    int f = blockIdx.x * blockDim.x + threadIdx.x;
    if (f >= (B_ * S_ * H_ * DH_) / 4) return;
    int e = f * 4;
    int c = e % (H_ * DH_);
    int row = e / (H_ * DH_);
    int b = row / S_;
    int h = c / DH_;
    float mean = g_stats[(b * H_ + h) * 2 + 0];
    float inv  = g_stats[(b * H_ + h) * 2 + 1];
    float4 x = *(const float4*)&g_o[e];
    float4 gm = *(const float4*)&gamma[c];
    float4 bt = *(const float4*)&beta[c];
    const float post = 1.0f - LAMBDA_INIT;
    float y[4];
    y[0] = ((x.x - mean) * inv * gm.x + bt.x) * post;
    y[1] = ((x.y - mean) * inv * gm.y + bt.y) * post;
    y[2] = ((x.z - mean) * inv * gm.z + bt.z) * post;
    y[3] = ((x.w - mean) * inv * gm.w + bt.w) * post;
    __nv_bfloat16 hh[4], ll[4];
#pragma unroll
    for (int j = 0; j < 4; j++) {
        hh[j] = __float2bfloat16(y[j]);
        ll[j] = __float2bfloat16(y[j] - __bfloat162float(hh[j]));
    }
    *(uint2*)&g_nh[e] = *(uint2*)hh;
    *(uint2*)&g_nl[e] = *(uint2*)ll;
}

// ---------------- launch ----------------------------------------------------
extern "C" void kernel_launch(void* const* d_in, const int* in_sizes, int n_in,
                              void* d_out, int out_size) {
    const float* x     = (const float*)d_in[0];
    const float* amask = (const float*)d_in[1];
    const float* Wq = (const float*)d_in[3];
    const float* Wk = (const float*)d_in[4];
    const float* Wv = (const float*)d_in[5];
    const float* Wo = (const float*)d_in[6];
    const float* lq1 = (const float*)d_in[7];
    const float* lq2 = (const float*)d_in[8];
    const float* lk1 = (const float*)d_in[9];
    const float* lk2 = (const float*)d_in[10];
    const float* gam = (const float*)d_in[11];
    const float* bet = (const float*)d_in[12];
    float* out = (float*)d_out;

    float *qb, *kb, *vb;
    cudaGetSymbolAddress((void**)&qb, g_q);
    cudaGetSymbolAddress((void**)&kb, g_k);
    cudaGetSymbolAddress((void**)&vb, g_v);
    __nv_bfloat16 *xh, *xl, *wqh, *wql, *wkh, *wkl, *wvh, *wvl, *woh, *wol, *nh, *nl;
    cudaGetSymbolAddress((void**)&xh, g_xh);   cudaGetSymbolAddress((void**)&xl, g_xl);
    cudaGetSymbolAddress((void**)&wqh, g_wqh); cudaGetSymbolAddress((void**)&wql, g_wql);
    cudaGetSymbolAddress((void**)&wkh, g_wkh); cudaGetSymbolAddress((void**)&wkl, g_wkl);
    cudaGetSymbolAddress((void**)&wvh, g_wvh); cudaGetSymbolAddress((void**)&wvl, g_wvl);
    cudaGetSymbolAddress((void**)&woh, g_woh); cudaGetSymbolAddress((void**)&wol, g_wol);
    cudaGetSymbolAddress((void**)&nh, g_nh);   cudaGetSymbolAddress((void**)&nl, g_nl);

    const int M = B_ * S_;  // 4096

    lam_kernel<<<1, 1>>>(lq1, lq2, lk1, lk2);

    // splits
    cvt_kernel<<<(M * D_ / 4 + 255) / 256, 256>>>(x, xh, xl, M * D_ / 4);
    cvt_kernel<<<(QKDIM * D_ / 4 + 255) / 256, 256>>>(Wq, wqh, wql, QKDIM * D_ / 4);
    cvt_kernel<<<(QKDIM * D_ / 4 + 255) / 256, 256>>>(Wk, wkh, wkl, QKDIM * D_ / 4);
    cvt_kernel<<<(H_ * DH_ * D_ / 4 + 255) / 256, 256>>>(Wv, wvh, wvl, H_ * DH_ * D_ / 4);
    cvt_kernel<<<(D_ * H_ * DH_ / 4 + 255) / 256, 256>>>(Wo, woh, wol, D_ * H_ * DH_ / 4);

    cudaFuncSetAttribute(gemm_mma3, cudaFuncAttributeMaxDynamicSharedMemorySize, G_SMEM);

    // projections (tensor cores via mma.sync)
    gemm_mma3<<<dim3(QKDIM / 128, M / 128), 256, G_SMEM>>>(xh, xl, wqh, wql, qb, M, QKDIM, D_);
    gemm_mma3<<<dim3(QKDIM / 128, M / 128), 256, G_SMEM>>>(xh, xl, wkh, wkl, kb, M, QKDIM, D_);
    gemm_mma3<<<dim3((H_ * DH_) / 128, M / 128), 256, G_SMEM>>>(xh, xl, wvh, wvl, vb, M, H_ * DH_, D_);

    // attention
    cudaFuncSetAttribute(flash2_kernel, cudaFuncAttributeMaxDynamicSharedMemorySize, FL_SMEM);
    flash2_kernel<<<dim3(S_ / BQ, B_ * H_ * 2), 256, FL_SMEM>>>(amask);

    // combine + group norm (+bf16 split of normed)
    combine_kernel<<<(B_ * S_ * H_ * DH_ / 4 + 255) / 256, 256>>>();
    gn_stats_kernel<<<B_ * H_, 256>>>();
    gn_apply_kernel<<<(B_ * S_ * H_ * DH_ / 4 + 255) / 256, 256>>>(gam, bet);

    // output projection -> d_out
    gemm_mma3<<<dim3(D_ / 128, M / 128), 256, G_SMEM>>>(nh, nl, woh, wol, out, M, D_, H_ * DH_);
}

// round 5
// speedup vs baseline: 6.0762x; 1.6874x over previous
#include <cuda_runtime.h>
#include <cuda_bf16.h>
#include <math.h>
#include <cstdint>

#define B_  2
#define S_  2048
#define D_  1024
#define H_  16
#define DH_ 64
#define QKDIM 2048
#define NEGV (-1000000000.0f)
#define LAMBDA_INIT 0.8f
#define EPS_ 1e-5f

// ---------------- scratch (device globals) ---------------------------------
__device__ float g_o1[(size_t)B_ * S_ * H_ * DH_];
__device__ float g_o2[(size_t)B_ * S_ * H_ * DH_];
__device__ float g_o [(size_t)B_ * S_ * H_ * DH_];
__device__ float g_lambda;
__device__ float g_stats[B_ * H_ * 2];

// bf16 split buffers
__device__ __nv_bfloat16 g_xh[(size_t)B_ * S_ * D_], g_xl[(size_t)B_ * S_ * D_];
__device__ __nv_bfloat16 g_wqh[QKDIM * D_], g_wql[QKDIM * D_];
__device__ __nv_bfloat16 g_wkh[QKDIM * D_], g_wkl[QKDIM * D_];
__device__ __nv_bfloat16 g_wvh[(H_ * DH_) * D_], g_wvl[(H_ * DH_) * D_];
__device__ __nv_bfloat16 g_woh[D_ * (H_ * DH_)], g_wol[D_ * (H_ * DH_)];
__device__ __nv_bfloat16 g_nh[(size_t)B_ * S_ * H_ * DH_], g_nl[(size_t)B_ * S_ * H_ * DH_];
// qkv as bf16 hi/lo (written by gemm epilogue)
__device__ __nv_bfloat16 g_qh[(size_t)B_ * S_ * QKDIM], g_ql[(size_t)B_ * S_ * QKDIM];
__device__ __nv_bfloat16 g_kh[(size_t)B_ * S_ * QKDIM], g_kl[(size_t)B_ * S_ * QKDIM];
__device__ __nv_bfloat16 g_vh[(size_t)B_ * S_ * H_ * DH_], g_vl[(size_t)B_ * S_ * H_ * DH_];

// ---------------- helpers ---------------------------------------------------
__device__ __forceinline__ uint32_t smem_u32(const void* p) {
    uint32_t a;
    asm("{ .reg .u64 t; cvta.to.shared.u64 t, %1; cvt.u32.u64 %0, t; }" : "=r"(a) : "l"(p));
    return a;
}
#define CP16(dst, src) \
    asm volatile("cp.async.cg.shared.global [%0], [%1], 16;" :: "r"(dst), "l"(src) : "memory")
#define CP_COMMIT() asm volatile("cp.async.commit_group;" ::: "memory")
#define CP_WAIT1()  asm volatile("cp.async.wait_group 1;" ::: "memory")
#define CP_WAIT0()  asm volatile("cp.async.wait_group 0;" ::: "memory")

__device__ __forceinline__ void ldsm_x4(uint32_t& r0, uint32_t& r1, uint32_t& r2, uint32_t& r3,
                                        uint32_t addr) {
    asm volatile("ldmatrix.sync.aligned.m8n8.x4.shared.b16 {%0,%1,%2,%3}, [%4];"
                 : "=r"(r0), "=r"(r1), "=r"(r2), "=r"(r3) : "r"(addr));
}
__device__ __forceinline__ void ldsm_x4t(uint32_t& r0, uint32_t& r1, uint32_t& r2, uint32_t& r3,
                                         uint32_t addr) {
    asm volatile("ldmatrix.sync.aligned.m8n8.x4.trans.shared.b16 {%0,%1,%2,%3}, [%4];"
                 : "=r"(r0), "=r"(r1), "=r"(r2), "=r"(r3) : "r"(addr));
}
#define MMA16816(d, a, b) \
    asm volatile("mma.sync.aligned.m16n8k16.row.col.f32.bf16.bf16.f32 " \
                 "{%0,%1,%2,%3}, {%4,%5,%6,%7}, {%8,%9}, {%0,%1,%2,%3};" \
                 : "+f"((d)[0]), "+f"((d)[1]), "+f"((d)[2]), "+f"((d)[3]) \
                 : "r"((a)[0]), "r"((a)[1]), "r"((a)[2]), "r"((a)[3]), \
                   "r"((b)[0]), "r"((b)[1]))

__device__ __forceinline__ uint32_t pack_bf2(float lo, float hi) {
    __nv_bfloat162 t = __floats2bfloat162_rn(lo, hi);
    return *(uint32_t*)&t;
}

// ---------------- lambda ----------------------------------------------------
__global__ void lam_kernel(const float* __restrict__ lq1, const float* __restrict__ lq2,
                           const float* __restrict__ lk1, const float* __restrict__ lk2) {
    float d1 = 0.f, d2 = 0.f;
    for (int i = 0; i < DH_; i++) { d1 += lq1[i] * lk1[i]; d2 += lq2[i] * lk2[i]; }
    g_lambda = expf(d1) - expf(d2) + LAMBDA_INIT;
}

// ---------------- fp32 -> bf16 hi/lo split ----------------------------------
__global__ void __launch_bounds__(256) cvt_kernel(const float* __restrict__ src,
                                                  __nv_bfloat16* __restrict__ h,
                                                  __nv_bfloat16* __restrict__ l, int n4) {
    int i = blockIdx.x * 256 + threadIdx.x;
    if (i >= n4) return;
    float4 v = ((const float4*)src)[i];
    float vv[4] = {v.x, v.y, v.z, v.w};
    __nv_bfloat16 hh[4], ll[4];
#pragma unroll
    for (int j = 0; j < 4; j++) {
        hh[j] = __float2bfloat16(vv[j]);
        ll[j] = __float2bfloat16(vv[j] - __bfloat162float(hh[j]));
    }
    *(uint2*)&h[(size_t)i * 4] = *(uint2*)hh;
    *(uint2*)&l[(size_t)i * 4] = *(uint2*)ll;
}

// ---------------- bf16x3 GEMM via mma.sync ----------------------------------
// C[M,N] = A[M,K]*B[N,K]^T. If Cf != 0: fp32 out; else bf16 hi/lo out.
#define GSTAGE 32768
#define G_SMEM (2 * GSTAGE)

__device__ __forceinline__ void g_issue(
    const __nv_bfloat16* __restrict__ Ah, const __nv_bfloat16* __restrict__ Al,
    const __nv_bfloat16* __restrict__ Bh, const __nv_bfloat16* __restrict__ Bl,
    uint32_t sbuf, int tid, int bm, int bn, int K, int c) {
#pragma unroll
    for (int i = 0; i < 2; i++) {
        int ch = tid + i * 256;
        int p = ch >> 3, c16 = ch & 7;
        int r = (p << 1) + (c16 >> 2);
        int kb = (c16 & 3) * 8;
        int off = p * 128 + c16 * 16;
        uint32_t dst = sbuf + (off ^ ((off >> 3) & 0x70));
        size_t ga = (size_t)(bm + r) * K + c * 32 + kb;
        size_t gb = (size_t)(bn + r) * K + c * 32 + kb;
        CP16(dst,         Ah + ga);
        CP16(dst + 8192,  Al + ga);
        CP16(dst + 16384, Bh + gb);
        CP16(dst + 24576, Bl + gb);
    }
    CP_COMMIT();
}

__global__ void __launch_bounds__(256) gemm_mma3(
    const __nv_bfloat16* __restrict__ Ah, const __nv_bfloat16* __restrict__ Al,
    const __nv_bfloat16* __restrict__ Bh, const __nv_bfloat16* __restrict__ Bl,
    float* __restrict__ Cf, __nv_bfloat16* __restrict__ Chi, __nv_bfloat16* __restrict__ Clo,
    int M, int N, int K) {
    extern __shared__ char smem[];
    const uint32_t sbase = smem_u32(smem);
    const int tid = threadIdx.x, wid = tid >> 5, lane = tid & 31;
    const int bm = blockIdx.y * 128, bn = blockIdx.x * 128;
    const int wm = (wid & 3) * 32;
    const int wn = (wid >> 2) * 64;
    const int g = lane >> 3, rl = lane & 7;

    float acc[2][8][4];
#pragma unroll
    for (int a = 0; a < 2; a++)
#pragma unroll
        for (int b = 0; b < 8; b++)
#pragma unroll
            for (int d = 0; d < 4; d++) acc[a][b][d] = 0.f;

    const int nch = K >> 5;
    g_issue(Ah, Al, Bh, Bl, sbase, tid, bm, bn, K, 0);

    for (int c = 0; c < nch; c++) {
        uint32_t sbuf = sbase + (c & 1) * GSTAGE;
        if (c + 1 < nch) {
            g_issue(Ah, Al, Bh, Bl, sbase + ((c + 1) & 1) * GSTAGE, tid, bm, bn, K, c + 1);
            CP_WAIT1();
        } else {
            CP_WAIT0();
        }
        __syncthreads();

#pragma unroll
        for (int ks = 0; ks < 2; ks++) {
            uint32_t ah[2][4], al[2][4];
#pragma unroll
            for (int mb = 0; mb < 2; mb++) {
                int r = wm + mb * 16 + ((g & 1) << 3) + rl;
                int c16 = ((r & 1) << 2) + ks * 2 + (g >> 1);
                int off = (r >> 1) * 128 + c16 * 16;
                uint32_t sw = (uint32_t)(off ^ ((off >> 3) & 0x70));
                ldsm_x4(ah[mb][0], ah[mb][1], ah[mb][2], ah[mb][3], sbuf + sw);
                ldsm_x4(al[mb][0], al[mb][1], al[mb][2], al[mb][3], sbuf + 8192 + sw);
            }
            uint32_t bh[4][4], bl[4][4];
#pragma unroll
            for (int np = 0; np < 4; np++) {
                int r = wn + np * 16 + ((g >> 1) << 3) + rl;
                int c16 = ((r & 1) << 2) + ks * 2 + (g & 1);
                int off = (r >> 1) * 128 + c16 * 16;
                uint32_t sw = (uint32_t)(off ^ ((off >> 3) & 0x70));
                ldsm_x4(bh[np][0], bh[np][1], bh[np][2], bh[np][3], sbuf + 16384 + sw);
                ldsm_x4(bl[np][0], bl[np][1], bl[np][2], bl[np][3], sbuf + 24576 + sw);
            }
#pragma unroll
            for (int mb = 0; mb < 2; mb++)
#pragma unroll
                for (int j = 0; j < 8; j++) {
                    MMA16816(acc[mb][j], ah[mb], &bh[j >> 1][(j & 1) * 2]);
                    MMA16816(acc[mb][j], ah[mb], &bl[j >> 1][(j & 1) * 2]);
                    MMA16816(acc[mb][j], al[mb], &bh[j >> 1][(j & 1) * 2]);
                }
        }
        __syncthreads();
    }

    if (Cf) {
#pragma unroll
        for (int mb = 0; mb < 2; mb++) {
            int row0 = bm + wm + mb * 16 + (lane >> 2);
#pragma unroll
            for (int j = 0; j < 8; j++) {
                int col = bn + wn + j * 8 + (lane & 3) * 2;
                *(float2*)&Cf[(size_t)row0 * N + col]       = make_float2(acc[mb][j][0], acc[mb][j][1]);
                *(float2*)&Cf[(size_t)(row0 + 8) * N + col] = make_float2(acc[mb][j][2], acc[mb][j][3]);
            }
        }
    } else {
#pragma unroll
        for (int mb = 0; mb < 2; mb++) {
            int row0 = bm + wm + mb * 16 + (lane >> 2);
#pragma unroll
            for (int j = 0; j < 8; j++) {
                int col = bn + wn + j * 8 + (lane & 3) * 2;
#pragma unroll
                for (int rr = 0; rr < 2; rr++) {
                    float v0 = acc[mb][j][rr * 2], v1 = acc[mb][j][rr * 2 + 1];
                    __nv_bfloat16 h0 = __float2bfloat16(v0), h1 = __float2bfloat16(v1);
                    __nv_bfloat16 l0 = __float2bfloat16(v0 - __bfloat162float(h0));
                    __nv_bfloat16 l1 = __float2bfloat16(v1 - __bfloat162float(h1));
                    size_t idx = (size_t)(row0 + rr * 8) * N + col;
                    __nv_bfloat162 hp; hp.x = h0; hp.y = h1;
                    __nv_bfloat162 lp; lp.x = l0; lp.y = l1;
                    *(__nv_bfloat162*)&Chi[idx] = hp;
                    *(__nv_bfloat162*)&Clo[idx] = lp;
                }
            }
        }
    }
}

// ---------------- flash attention via mma.sync ------------------------------
// grid (16, B*H*2). 256 threads / 8 warps, each warp 16 q rows.
// smem: Qh/Ql [128x64], 2 stages of {Kh,Kl,Vh,Vl [64x64], amask[64]}.
#define FQ_H 0
#define FQ_L 16384
#define FSTG0 32768
#define FK_H 0
#define FK_L 8192
#define FV_H 16384
#define FV_L 24576
#define FAM  32768
#define FSTG_SZ 33024
#define FL_SMEM (FSTG0 + 2 * FSTG_SZ)

__device__ __forceinline__ void f_issue_stage(uint32_t stg, const char* fsm_unused,
                                              int tid, int b, int h, int comp, int kt,
                                              const float* __restrict__ amask) {
    const char* Khg = (const char*)(g_kh + ((size_t)(b * S_) + kt * 64) * QKDIM + h * 128 + comp * 64);
    const char* Klg = (const char*)(g_kl + ((size_t)(b * S_) + kt * 64) * QKDIM + h * 128 + comp * 64);
    const char* Vhg = (const char*)(g_vh + ((size_t)(b * S_) + kt * 64) * (H_ * DH_) + h * 64);
    const char* Vlg = (const char*)(g_vl + ((size_t)(b * S_) + kt * 64) * (H_ * DH_) + h * 64);
#pragma unroll
    for (int i = 0; i < 2; i++) {
        int t = tid + i * 256;             // 0..511 : row(0..63) x gran(0..7)
        int row = t >> 3, gr = t & 7;
        int off = row * 128 + gr * 16;
        uint32_t sw = (uint32_t)(off ^ ((off >> 3) & 0x70));
        CP16(stg + FK_H + sw, Khg + (size_t)row * (QKDIM * 2) + gr * 16);
        CP16(stg + FK_L + sw, Klg + (size_t)row * (QKDIM * 2) + gr * 16);
        CP16(stg + FV_H + sw, Vhg + (size_t)row * (H_ * DH_ * 2) + gr * 16);
        CP16(stg + FV_L + sw, Vlg + (size_t)row * (H_ * DH_ * 2) + gr * 16);
    }
    if (tid < 16)
        CP16(stg + FAM + tid * 16, amask + b * S_ + kt * 64 + tid * 4);
}

__global__ void __launch_bounds__(256) flashmma_kernel(const float* __restrict__ amask) {
    extern __shared__ char fsm[];
    const uint32_t sb = smem_u32(fsm);
    const int tid = threadIdx.x, wid = tid >> 5, lane = tid & 31;
    const int g = lane >> 3, rl = lane & 7;
    const int qt = (gridDim.x - 1) - blockIdx.x;
    const int z = blockIdx.y;
    const int comp = z & 1;
    const int bh = z >> 1;
    const int b = bh / H_, h = bh % H_;
    const float slope = exp2f(-8.0f * (float)(h + 1) / (float)H_);
    const float scale = 0.125f;

    // ---- load Q tiles (hi/lo) ----
    {
        const char* Qhg = (const char*)(g_qh + ((size_t)(b * S_) + qt * 128) * QKDIM + h * 128 + comp * 64);
        const char* Qlg = (const char*)(g_ql + ((size_t)(b * S_) + qt * 128) * QKDIM + h * 128 + comp * 64);
#pragma unroll
        for (int i = 0; i < 4; i++) {
            int t = tid + i * 256;         // 0..1023 : row(0..127) x gran(0..7)
            int row = t >> 3, gr = t & 7;
            int off = row * 128 + gr * 16;
            uint32_t sw = (uint32_t)(off ^ ((off >> 3) & 0x70));
            CP16(sb + FQ_H + sw, Qhg + (size_t)row * (QKDIM * 2) + gr * 16);
            CP16(sb + FQ_L + sw, Qlg + (size_t)row * (QKDIM * 2) + gr * 16);
        }
    }
    f_issue_stage(sb + FSTG0, fsm, tid, b, h, comp, 0, amask);
    CP_COMMIT();

    float oa[8][4];
#pragma unroll
    for (int j = 0; j < 8; j++)
#pragma unroll
        for (int d = 0; d < 4; d++) oa[j][d] = 0.f;
    float m0 = -1e30f, m1 = -1e30f, l0 = 0.f, l1 = 0.f;

    const int qr0 = qt * 128 + wid * 16 + (lane >> 2);
    const int nkt = 2 * qt + 2;

    for (int kt = 0; kt < nkt; kt++) {
        uint32_t stg = sb + FSTG0 + (uint32_t)(kt & 1) * FSTG_SZ;
        if (kt + 1 < nkt) {
            f_issue_stage(sb + FSTG0 + (uint32_t)((kt + 1) & 1) * FSTG_SZ, fsm, tid, b, h, comp, kt + 1, amask);
            CP_COMMIT();
            CP_WAIT1();
        } else {
            CP_WAIT0();
        }
        __syncthreads();

        // ---- S = Q K^T (x3 split) ----
        float sa[8][4];
#pragma unroll
        for (int j = 0; j < 8; j++)
#pragma unroll
            for (int d = 0; d < 4; d++) sa[j][d] = 0.f;
#pragma unroll
        for (int kb = 0; kb < 4; kb++) {
            uint32_t ah[4], al[4];
            {
                int row = wid * 16 + ((g & 1) << 3) + rl;
                int gr = kb * 2 + (g >> 1);
                int off = row * 128 + gr * 16;
                uint32_t sw = (uint32_t)(off ^ ((off >> 3) & 0x70));
                ldsm_x4(ah[0], ah[1], ah[2], ah[3], sb + FQ_H + sw);
                ldsm_x4(al[0], al[1], al[2], al[3], sb + FQ_L + sw);
            }
#pragma unroll
            for (int nb2 = 0; nb2 < 4; nb2++) {
                uint32_t kh4[4], kl4[4];
                int row = nb2 * 16 + ((g >> 1) << 3) + rl;
                int gr = kb * 2 + (g & 1);
                int off = row * 128 + gr * 16;
                uint32_t sw = (uint32_t)(off ^ ((off >> 3) & 0x70));
                ldsm_x4(kh4[0], kh4[1], kh4[2], kh4[3], stg + FK_H + sw);
                ldsm_x4(kl4[0], kl4[1], kl4[2], kl4[3], stg + FK_L + sw);
                MMA16816(sa[nb2 * 2], ah, &kh4[0]);
                MMA16816(sa[nb2 * 2], ah, &kl4[0]);
                MMA16816(sa[nb2 * 2], al, &kh4[0]);
                MMA16816(sa[nb2 * 2 + 1], ah, &kh4[2]);
                MMA16816(sa[nb2 * 2 + 1], ah, &kl4[2]);
                MMA16816(sa[nb2 * 2 + 1], al, &kh4[2]);
            }
        }

        // ---- bias + masks ----
        const float* ams = (const float*)(fsm + (stg - sb) + FAM);
        const int kcb = kt * 64;
#pragma unroll
        for (int nb = 0; nb < 8; nb++) {
            int kc = nb * 8 + (lane & 3) * 2;
            float a0 = (1.0f - ams[kc]) * NEGV;
            float a1 = (1.0f - ams[kc + 1]) * NEGV;
            int k0 = kcb + kc, k1 = k0 + 1;
            float b00 = a0 - slope * (float)(qr0 - k0) + ((k0 > qr0) ? NEGV : 0.f);
            float b01 = a1 - slope * (float)(qr0 - k1) + ((k1 > qr0) ? NEGV : 0.f);
            float b10 = a0 - slope * (float)(qr0 + 8 - k0) + ((k0 > qr0 + 8) ? NEGV : 0.f);
            float b11 = a1 - slope * (float)(qr0 + 8 - k1) + ((k1 > qr0 + 8) ? NEGV : 0.f);
            sa[nb][0] = sa[nb][0] * scale + b00;
            sa[nb][1] = sa[nb][1] * scale + b01;
            sa[nb][2] = sa[nb][2] * scale + b10;
            sa[nb][3] = sa[nb][3] * scale + b11;
        }

        // ---- online softmax (rows qr0 and qr0+8) ----
        float mx0 = -1e30f, mx1 = -1e30f;
#pragma unroll
        for (int nb = 0; nb < 8; nb++) {
            mx0 = fmaxf(mx0, fmaxf(sa[nb][0], sa[nb][1]));
            mx1 = fmaxf(mx1, fmaxf(sa[nb][2], sa[nb][3]));
        }
        mx0 = fmaxf(mx0, __shfl_xor_sync(0xffffffffu, mx0, 1));
        mx0 = fmaxf(mx0, __shfl_xor_sync(0xffffffffu, mx0, 2));
        mx1 = fmaxf(mx1, __shfl_xor_sync(0xffffffffu, mx1, 1));
        mx1 = fmaxf(mx1, __shfl_xor_sync(0xffffffffu, mx1, 2));
        float mn0 = fmaxf(m0, mx0), mn1 = fmaxf(m1, mx1);
        float al0 = __expf(m0 - mn0), al1 = __expf(m1 - mn1);
        m0 = mn0; m1 = mn1;
        float ls0 = 0.f, ls1 = 0.f;
#pragma unroll
        for (int nb = 0; nb < 8; nb++) {
            sa[nb][0] = __expf(sa[nb][0] - mn0);
            sa[nb][1] = __expf(sa[nb][1] - mn0);
            sa[nb][2] = __expf(sa[nb][2] - mn1);
            sa[nb][3] = __expf(sa[nb][3] - mn1);
            ls0 += sa[nb][0] + sa[nb][1];
            ls1 += sa[nb][2] + sa[nb][3];
        }
        ls0 += __shfl_xor_sync(0xffffffffu, ls0, 1);
        ls0 += __shfl_xor_sync(0xffffffffu, ls0, 2);
        ls1 += __shfl_xor_sync(0xffffffffu, ls1, 1);
        ls1 += __shfl_xor_sync(0xffffffffu, ls1, 2);
        l0 = l0 * al0 + ls0;
        l1 = l1 * al1 + ls1;

        // ---- rescale O ----
#pragma unroll
        for (int j = 0; j < 8; j++) {
            oa[j][0] *= al0; oa[j][1] *= al0;
            oa[j][2] *= al1; oa[j][3] *= al1;
        }

        // ---- pack P (hi/lo A fragments per 16-key block) ----
        uint32_t pAh[4][4], pAl[4][4];
#pragma unroll
        for (int kb2 = 0; kb2 < 4; kb2++) {
#pragma unroll
            for (int half = 0; half < 2; half++) {     // half0: c0/c1(row r), half1: c2/c3(row r+8)
                float v0a = sa[kb2 * 2][half * 2], v1a = sa[kb2 * 2][half * 2 + 1];
                float v0b = sa[kb2 * 2 + 1][half * 2], v1b = sa[kb2 * 2 + 1][half * 2 + 1];
                __nv_bfloat16 h0a = __float2bfloat16(v0a), h1a = __float2bfloat16(v1a);
                __nv_bfloat16 h0b = __float2bfloat16(v0b), h1b = __float2bfloat16(v1b);
                pAh[kb2][half]     = pack_bf2(__bfloat162float(h0a), __bfloat162float(h1a));
                pAh[kb2][2 + half] = pack_bf2(__bfloat162float(h0b), __bfloat162float(h1b));
                pAl[kb2][half]     = pack_bf2(v0a - __bfloat162float(h0a), v1a - __bfloat162float(h1a));
                pAl[kb2][2 + half] = pack_bf2(v0b - __bfloat162float(h0b), v1b - __bfloat162float(h1b));
            }
        }
        // fix A-frag ordering: a0=(r,k0-7), a1=(r+8,k0-7), a2=(r,k8-15), a3=(r+8,k8-15)
        // pAh[kb2] currently: [0]=(r, first 8 keys), [1]=(r+8, first 8), [2]=(r, next 8), [3]=(r+8, next 8)  ✓

        // ---- O += P V (x3 split) ----
#pragma unroll
        for (int kb2 = 0; kb2 < 4; kb2++) {
#pragma unroll
            for (int db = 0; db < 4; db++) {
                uint32_t vh4[4], vl4[4];
                int row = kb2 * 16 + ((g & 1) << 3) + rl;
                int gr = db * 2 + (g >> 1);
                int off = row * 128 + gr * 16;
                uint32_t sw = (uint32_t)(off ^ ((off >> 3) & 0x70));
                ldsm_x4t(vh4[0], vh4[1], vh4[2], vh4[3], stg + FV_H + sw);
                ldsm_x4t(vl4[0], vl4[1], vl4[2], vl4[3], stg + FV_L + sw);
                MMA16816(oa[db * 2], pAh[kb2], &vh4[0]);
                MMA16816(oa[db * 2], pAh[kb2], &vl4[0]);
                MMA16816(oa[db * 2], pAl[kb2], &vh4[0]);
                MMA16816(oa[db * 2 + 1], pAh[kb2], &vh4[2]);
                MMA16816(oa[db * 2 + 1], pAh[kb2], &vl4[2]);
                MMA16816(oa[db * 2 + 1], pAl[kb2], &vh4[2]);
            }
        }
        __syncthreads();
    }

    // ---- epilogue ----
    float inv0 = 1.0f / l0, inv1 = 1.0f / l1;
    float* Og = (comp ? g_o2 : g_o1) + ((size_t)(b * S_) + qr0) * (H_ * DH_) + h * 64;
#pragma unroll
    for (int j = 0; j < 8; j++) {
        int col = j * 8 + (lane & 3) * 2;
        *(float2*)&Og[col] = make_float2(oa[j][0] * inv0, oa[j][1] * inv0);
        *(float2*)&Og[(size_t)8 * (H_ * DH_) + col] = make_float2(oa[j][2] * inv1, oa[j][3] * inv1);
    }
}

// ---------------- combine ---------------------------------------------------
__global__ void __launch_bounds__(256) combine_kernel() {
    int f = blockIdx.x * blockDim.x + threadIdx.x;
    if (f >= (B_ * S_ * H_ * DH_) / 4) return;
    int e = f * 4;
    float lam = g_lambda;
    float4 a = *(const float4*)&g_o1[e];
    float4 c = *(const float4*)&g_o2[e];
    float4 y;
    y.x = a.x - lam * c.x; y.y = a.y - lam * c.y;
    y.z = a.z - lam * c.z; y.w = a.w - lam * c.w;
    *(float4*)&g_o[e] = y;
}

// ---------------- group norm stats ------------------------------------------
__global__ void __launch_bounds__(256) gn_stats_kernel() {
    const int bh = blockIdx.x;
    const int b = bh / H_, h = bh % H_;
    double s = 0.0, ss = 0.0;
    for (int f = threadIdx.x; f < S_ * (DH_ / 4); f += blockDim.x) {
        int row = f >> 4, c = (f & 15) * 4;
        float4 v = *(const float4*)&g_o[(size_t)(b * S_ + row) * (H_ * DH_) + h * DH_ + c];
        s += (double)v.x + v.y + v.z + v.w;
        ss += (double)v.x * v.x + (double)v.y * v.y + (double)v.z * v.z + (double)v.w * v.w;
    }
    __shared__ double sh_s[256], sh_ss[256];
    sh_s[threadIdx.x] = s; sh_ss[threadIdx.x] = ss;
    __syncthreads();
    for (int st = 128; st > 0; st >>= 1) {
        if (threadIdx.x < st) {
            sh_s[threadIdx.x] += sh_s[threadIdx.x + st];
            sh_ss[threadIdx.x] += sh_ss[threadIdx.x + st];
        }
        __syncthreads();
    }
    if (threadIdx.x == 0) {
        double n = (double)S_ * DH_;
        double mean = sh_s[0] / n;
        double var = sh_ss[0] / n - mean * mean;
        g_stats[bh * 2 + 0] = (float)mean;
        g_stats[bh * 2 + 1] = rsqrtf((float)var + EPS_);
    }
}

// ---------------- normalize + emit bf16 hi/lo -------------------------------
__global__ void __launch_bounds__(256) gn_apply_kernel(const float* __restrict__ gamma,
                                                       const float* __restrict__ beta) {
    int f = blockIdx.x * blockDim.x + threadIdx.x;
    if (f >= (B_ * S_ * H_ * DH_) / 4) return;
    int e = f * 4;
    int c = e % (H_ * DH_);
    int row = e / (H_ * DH_);
    int b = row / S_;
    int h = c / DH_;
    float mean = g_stats[(b * H_ + h) * 2 + 0];
    float inv  = g_stats[(b * H_ + h) * 2 + 1];
    float4 x = *(const float4*)&g_o[e];
    float4 gm = *(const float4*)&gamma[c];
    float4 bt = *(const float4*)&beta[c];
    const float post = 1.0f - LAMBDA_INIT;
    float y[4];
    y[0] = ((x.x - mean) * inv * gm.x + bt.x) * post;
    y[1] = ((x.y - mean) * inv * gm.y + bt.y) * post;
    y[2] = ((x.z - mean) * inv * gm.z + bt.z) * post;
    y[3] = ((x.w - mean) * inv * gm.w + bt.w) * post;
    __nv_bfloat16 hh[4], ll[4];
#pragma unroll
    for (int j = 0; j < 4; j++) {
        hh[j] = __float2bfloat16(y[j]);
        ll[j] = __float2bfloat16(y[j] - __bfloat162float(hh[j]));
    }
    *(uint2*)&g_nh[e] = *(uint2*)hh;
    *(uint2*)&g_nl[e] = *(uint2*)ll;
}

// ---------------- launch ----------------------------------------------------
extern "C" void kernel_launch(void* const* d_in, const int* in_sizes, int n_in,
                              void* d_out, int out_size) {
    const float* x     = (const float*)d_in[0];
    const float* amask = (const float*)d_in[1];
    const float* Wq = (const float*)d_in[3];
    const float* Wk = (const float*)d_in[4];
    const float* Wv = (const float*)d_in[5];
    const float* Wo = (const float*)d_in[6];
    const float* lq1 = (const float*)d_in[7];
    const float* lq2 = (const float*)d_in[8];
    const float* lk1 = (const float*)d_in[9];
    const float* lk2 = (const float*)d_in[10];
    const float* gam = (const float*)d_in[11];
    const float* bet = (const float*)d_in[12];
    float* out = (float*)d_out;

    __nv_bfloat16 *xh, *xl, *wqh, *wql, *wkh, *wkl, *wvh, *wvl, *woh, *wol, *nh, *nl;
    __nv_bfloat16 *qh, *ql, *kh, *kl, *vh, *vl;
    cudaGetSymbolAddress((void**)&xh, g_xh);   cudaGetSymbolAddress((void**)&xl, g_xl);
    cudaGetSymbolAddress((void**)&wqh, g_wqh); cudaGetSymbolAddress((void**)&wql, g_wql);
    cudaGetSymbolAddress((void**)&wkh, g_wkh); cudaGetSymbolAddress((void**)&wkl, g_wkl);
    cudaGetSymbolAddress((void**)&wvh, g_wvh); cudaGetSymbolAddress((void**)&wvl, g_wvl);
    cudaGetSymbolAddress((void**)&woh, g_woh); cudaGetSymbolAddress((void**)&wol, g_wol);
    cudaGetSymbolAddress((void**)&nh, g_nh);   cudaGetSymbolAddress((void**)&nl, g_nl);
    cudaGetSymbolAddress((void**)&qh, g_qh);   cudaGetSymbolAddress((void**)&ql, g_ql);
    cudaGetSymbolAddress((void**)&kh, g_kh);   cudaGetSymbolAddress((void**)&kl, g_kl);
    cudaGetSymbolAddress((void**)&vh, g_vh);   cudaGetSymbolAddress((void**)&vl, g_vl);

    const int M = B_ * S_;  // 4096

    lam_kernel<<<1, 1>>>(lq1, lq2, lk1, lk2);

    // splits
    cvt_kernel<<<(M * D_ / 4 + 255) / 256, 256>>>(x, xh, xl, M * D_ / 4);
    cvt_kernel<<<(QKDIM * D_ / 4 + 255) / 256, 256>>>(Wq, wqh, wql, QKDIM * D_ / 4);
    cvt_kernel<<<(QKDIM * D_ / 4 + 255) / 256, 256>>>(Wk, wkh, wkl, QKDIM * D_ / 4);
    cvt_kernel<<<(H_ * DH_ * D_ / 4 + 255) / 256, 256>>>(Wv, wvh, wvl, H_ * DH_ * D_ / 4);
    cvt_kernel<<<(D_ * H_ * DH_ / 4 + 255) / 256, 256>>>(Wo, woh, wol, D_ * H_ * DH_ / 4);

    cudaFuncSetAttribute(gemm_mma3, cudaFuncAttributeMaxDynamicSharedMemorySize, G_SMEM);

    // projections -> bf16 hi/lo outputs
    gemm_mma3<<<dim3(QKDIM / 128, M / 128), 256, G_SMEM>>>(xh, xl, wqh, wql, (float*)0, qh, ql, M, QKDIM, D_);
    gemm_mma3<<<dim3(QKDIM / 128, M / 128), 256, G_SMEM>>>(xh, xl, wkh, wkl, (float*)0, kh, kl, M, QKDIM, D_);
    gemm_mma3<<<dim3((H_ * DH_) / 128, M / 128), 256, G_SMEM>>>(xh, xl, wvh, wvl, (float*)0, vh, vl, M, H_ * DH_, D_);

    // attention (tensor-core flash)
    cudaFuncSetAttribute(flashmma_kernel, cudaFuncAttributeMaxDynamicSharedMemorySize, FL_SMEM);
    flashmma_kernel<<<dim3(S_ / 128, B_ * H_ * 2), 256, FL_SMEM>>>(amask);

    // combine + group norm (+bf16 split of normed)
    combine_kernel<<<(B_ * S_ * H_ * DH_ / 4 + 255) / 256, 256>>>();
    gn_stats_kernel<<<B_ * H_, 256>>>();
    gn_apply_kernel<<<(B_ * S_ * H_ * DH_ / 4 + 255) / 256, 256>>>(gam, bet);

    // output projection -> d_out (fp32)
    gemm_mma3<<<dim3(D_ / 128, M / 128), 256, G_SMEM>>>(nh, nl, woh, wol, out, (__nv_bfloat16*)0, (__nv_bfloat16*)0, M, D_, H_ * DH_);
}

// round 6
// speedup vs baseline: 6.3380x; 1.0431x over previous
#include <cuda_runtime.h>
#include <cuda_bf16.h>
#include <math.h>
#include <cstdint>

#define B_  2
#define S_  2048
#define D_  1024
#define H_  16
#define DH_ 64
#define QKDIM 2048
#define NEGV (-1000000000.0f)
#define LAMBDA_INIT 0.8f
#define EPS_ 1e-5f

// ---------------- scratch (device globals) ---------------------------------
__device__ float g_o1[(size_t)B_ * S_ * H_ * DH_];
__device__ float g_o2[(size_t)B_ * S_ * H_ * DH_];
__device__ float g_o [(size_t)B_ * S_ * H_ * DH_];
__device__ float g_lambda;
__device__ float g_stats[B_ * H_ * 2];

// bf16 split buffers
__device__ __nv_bfloat16 g_xh[(size_t)B_ * S_ * D_], g_xl[(size_t)B_ * S_ * D_];
__device__ __nv_bfloat16 g_wqh[QKDIM * D_], g_wql[QKDIM * D_];
__device__ __nv_bfloat16 g_wkh[QKDIM * D_], g_wkl[QKDIM * D_];
__device__ __nv_bfloat16 g_wvh[(H_ * DH_) * D_], g_wvl[(H_ * DH_) * D_];
__device__ __nv_bfloat16 g_woh[D_ * (H_ * DH_)], g_wol[D_ * (H_ * DH_)];
__device__ __nv_bfloat16 g_nh[(size_t)B_ * S_ * H_ * DH_], g_nl[(size_t)B_ * S_ * H_ * DH_];
__device__ __nv_bfloat16 g_qh[(size_t)B_ * S_ * QKDIM], g_ql[(size_t)B_ * S_ * QKDIM];
__device__ __nv_bfloat16 g_kh[(size_t)B_ * S_ * QKDIM], g_kl[(size_t)B_ * S_ * QKDIM];
__device__ __nv_bfloat16 g_vh[(size_t)B_ * S_ * H_ * DH_], g_vl[(size_t)B_ * S_ * H_ * DH_];

// ---------------- helpers ---------------------------------------------------
__device__ __forceinline__ uint32_t smem_u32(const void* p) {
    uint32_t a;
    asm("{ .reg .u64 t; cvta.to.shared.u64 t, %1; cvt.u32.u64 %0, t; }" : "=r"(a) : "l"(p));
    return a;
}
#define CP16(dst, src) \
    asm volatile("cp.async.cg.shared.global [%0], [%1], 16;" :: "r"(dst), "l"(src) : "memory")
#define CP_COMMIT() asm volatile("cp.async.commit_group;" ::: "memory")
#define CP_WAIT2()  asm volatile("cp.async.wait_group 2;" ::: "memory")
#define CP_WAIT1()  asm volatile("cp.async.wait_group 1;" ::: "memory")
#define CP_WAIT0()  asm volatile("cp.async.wait_group 0;" ::: "memory")

__device__ __forceinline__ void ldsm_x4(uint32_t& r0, uint32_t& r1, uint32_t& r2, uint32_t& r3,
                                        uint32_t addr) {
    asm volatile("ldmatrix.sync.aligned.m8n8.x4.shared.b16 {%0,%1,%2,%3}, [%4];"
                 : "=r"(r0), "=r"(r1), "=r"(r2), "=r"(r3) : "r"(addr));
}
__device__ __forceinline__ void ldsm_x4t(uint32_t& r0, uint32_t& r1, uint32_t& r2, uint32_t& r3,
                                         uint32_t addr) {
    asm volatile("ldmatrix.sync.aligned.m8n8.x4.trans.shared.b16 {%0,%1,%2,%3}, [%4];"
                 : "=r"(r0), "=r"(r1), "=r"(r2), "=r"(r3) : "r"(addr));
}
#define MMA16816(d, a, b) \
    asm volatile("mma.sync.aligned.m16n8k16.row.col.f32.bf16.bf16.f32 " \
                 "{%0,%1,%2,%3}, {%4,%5,%6,%7}, {%8,%9}, {%0,%1,%2,%3};" \
                 : "+f"((d)[0]), "+f"((d)[1]), "+f"((d)[2]), "+f"((d)[3]) \
                 : "r"((a)[0]), "r"((a)[1]), "r"((a)[2]), "r"((a)[3]), \
                   "r"((b)[0]), "r"((b)[1]))

__device__ __forceinline__ uint32_t pack_bf2(float lo, float hi) {
    __nv_bfloat162 t = __floats2bfloat162_rn(lo, hi);
    return *(uint32_t*)&t;
}

// ---------------- lambda ----------------------------------------------------
__global__ void lam_kernel(const float* __restrict__ lq1, const float* __restrict__ lq2,
                           const float* __restrict__ lk1, const float* __restrict__ lk2) {
    float d1 = 0.f, d2 = 0.f;
    for (int i = 0; i < DH_; i++) { d1 += lq1[i] * lk1[i]; d2 += lq2[i] * lk2[i]; }
    g_lambda = expf(d1) - expf(d2) + LAMBDA_INIT;
}

// ---------------- fp32 -> bf16 hi/lo split ----------------------------------
__device__ __forceinline__ void split4(const float* src, __nv_bfloat16* h, __nv_bfloat16* l,
                                       size_t i) {
    float4 v = ((const float4*)src)[i];
    float vv[4] = {v.x, v.y, v.z, v.w};
    __nv_bfloat16 hh[4], ll[4];
#pragma unroll
    for (int j = 0; j < 4; j++) {
        hh[j] = __float2bfloat16(vv[j]);
        ll[j] = __float2bfloat16(vv[j] - __bfloat162float(hh[j]));
    }
    *(uint2*)&h[i * 4] = *(uint2*)hh;
    *(uint2*)&l[i * 4] = *(uint2*)ll;
}

__global__ void __launch_bounds__(256) cvt_kernel(const float* __restrict__ src,
                                                  __nv_bfloat16* __restrict__ h,
                                                  __nv_bfloat16* __restrict__ l, int n4) {
    int i = blockIdx.x * 256 + threadIdx.x;
    if (i < n4) split4(src, h, l, i);
}

__global__ void __launch_bounds__(256) cvt2_kernel(
    const float* __restrict__ a, __nv_bfloat16* __restrict__ ah, __nv_bfloat16* __restrict__ al, int na4,
    const float* __restrict__ b, __nv_bfloat16* __restrict__ bh, __nv_bfloat16* __restrict__ bl, int nb4) {
    int i = blockIdx.x * 256 + threadIdx.x;
    if (i < na4) split4(a, ah, al, i);
    else if (i - na4 < nb4) split4(b, bh, bl, i - na4);
}

// ---------------- GEMM stage loader -----------------------------------------
#define GSTAGE 32768
#define G_SMEM (3 * GSTAGE)

__device__ __forceinline__ void g_issue(
    const __nv_bfloat16* __restrict__ Ah, const __nv_bfloat16* __restrict__ Al,
    const __nv_bfloat16* __restrict__ Bh, const __nv_bfloat16* __restrict__ Bl,
    uint32_t sbuf, int tid, int bm, int bn, int K, int c) {
#pragma unroll
    for (int i = 0; i < 2; i++) {
        int ch = tid + i * 256;
        int p = ch >> 3, c16 = ch & 7;
        int r = (p << 1) + (c16 >> 2);
        int kb = (c16 & 3) * 8;
        int off = p * 128 + c16 * 16;
        uint32_t dst = sbuf + (off ^ ((off >> 3) & 0x70));
        size_t ga = (size_t)(bm + r) * K + c * 32 + kb;
        size_t gb = (size_t)(bn + r) * K + c * 32 + kb;
        CP16(dst,         Ah + ga);
        CP16(dst + 8192,  Al + ga);
        CP16(dst + 16384, Bh + gb);
        CP16(dst + 24576, Bl + gb);
    }
    CP_COMMIT();
}

// core compute for one 32-k chunk (shared by both gemm kernels)
__device__ __forceinline__ void g_chunk(uint32_t sbuf, int wm, int wn, int g, int rl,
                                        float acc[2][8][4]) {
#pragma unroll
    for (int ks = 0; ks < 2; ks++) {
        uint32_t ah[2][4], al[2][4];
#pragma unroll
        for (int mb = 0; mb < 2; mb++) {
            int r = wm + mb * 16 + ((g & 1) << 3) + rl;
            int c16 = ((r & 1) << 2) + ks * 2 + (g >> 1);
            int off = (r >> 1) * 128 + c16 * 16;
            uint32_t sw = (uint32_t)(off ^ ((off >> 3) & 0x70));
            ldsm_x4(ah[mb][0], ah[mb][1], ah[mb][2], ah[mb][3], sbuf + sw);
            ldsm_x4(al[mb][0], al[mb][1], al[mb][2], al[mb][3], sbuf + 8192 + sw);
        }
        uint32_t bh[4][4], bl[4][4];
#pragma unroll
        for (int np = 0; np < 4; np++) {
            int r = wn + np * 16 + ((g >> 1) << 3) + rl;
            int c16 = ((r & 1) << 2) + ks * 2 + (g & 1);
            int off = (r >> 1) * 128 + c16 * 16;
            uint32_t sw = (uint32_t)(off ^ ((off >> 3) & 0x70));
            ldsm_x4(bh[np][0], bh[np][1], bh[np][2], bh[np][3], sbuf + 16384 + sw);
            ldsm_x4(bl[np][0], bl[np][1], bl[np][2], bl[np][3], sbuf + 24576 + sw);
        }
#pragma unroll
        for (int mb = 0; mb < 2; mb++)
#pragma unroll
            for (int j = 0; j < 8; j++) {
                MMA16816(acc[mb][j], ah[mb], &bh[j >> 1][(j & 1) * 2]);
                MMA16816(acc[mb][j], ah[mb], &bl[j >> 1][(j & 1) * 2]);
                MMA16816(acc[mb][j], al[mb], &bh[j >> 1][(j & 1) * 2]);
            }
    }
}

// ---------------- fused QKV projection (bf16 hi/lo out) ---------------------
// grid (40, 32): nt<16 -> Q, nt<32 -> K, else -> V.
__global__ void __launch_bounds__(256) gemm_qkv() {
    extern __shared__ char smem[];
    const uint32_t sbase = smem_u32(smem);
    const int tid = threadIdx.x, wid = tid >> 5, lane = tid & 31;
    const int nt = blockIdx.x;
    const int bm = blockIdx.y * 128;
    const int wm = (wid & 3) * 32;
    const int wn = (wid >> 2) * 64;
    const int g = lane >> 3, rl = lane & 7;
    const int K = D_;

    const __nv_bfloat16 *Ah = g_xh, *Al = g_xl, *Bh, *Bl;
    __nv_bfloat16 *Oh, *Ol;
    int N, bn;
    if (nt < 16)      { Bh = g_wqh; Bl = g_wql; Oh = g_qh; Ol = g_ql; N = QKDIM; bn = nt * 128; }
    else if (nt < 32) { Bh = g_wkh; Bl = g_wkl; Oh = g_kh; Ol = g_kl; N = QKDIM; bn = (nt - 16) * 128; }
    else              { Bh = g_wvh; Bl = g_wvl; Oh = g_vh; Ol = g_vl; N = H_ * DH_; bn = (nt - 32) * 128; }

    float acc[2][8][4];
#pragma unroll
    for (int a = 0; a < 2; a++)
#pragma unroll
        for (int b = 0; b < 8; b++)
#pragma unroll
            for (int d = 0; d < 4; d++) acc[a][b][d] = 0.f;

    const int nch = K >> 5;   // 32
    g_issue(Ah, Al, Bh, Bl, sbase, tid, bm, bn, K, 0);
    g_issue(Ah, Al, Bh, Bl, sbase + GSTAGE, tid, bm, bn, K, 1);

    for (int c = 0; c < nch; c++) {
        uint32_t sbuf = sbase + (uint32_t)(c % 3) * GSTAGE;
        if (c + 2 < nch) {
            g_issue(Ah, Al, Bh, Bl, sbase + (uint32_t)((c + 2) % 3) * GSTAGE, tid, bm, bn, K, c + 2);
            CP_WAIT2();
        } else if (c + 1 < nch) {
            CP_WAIT1();
        } else {
            CP_WAIT0();
        }
        __syncthreads();
        g_chunk(sbuf, wm, wn, g, rl, acc);
        __syncthreads();
    }

#pragma unroll
    for (int mb = 0; mb < 2; mb++) {
        int row0 = bm + wm + mb * 16 + (lane >> 2);
#pragma unroll
        for (int j = 0; j < 8; j++) {
            int col = bn + wn + j * 8 + (lane & 3) * 2;
#pragma unroll
            for (int rr = 0; rr < 2; rr++) {
                float v0 = acc[mb][j][rr * 2], v1 = acc[mb][j][rr * 2 + 1];
                __nv_bfloat16 h0 = __float2bfloat16(v0), h1 = __float2bfloat16(v1);
                __nv_bfloat16 l0 = __float2bfloat16(v0 - __bfloat162float(h0));
                __nv_bfloat16 l1 = __float2bfloat16(v1 - __bfloat162float(h1));
                size_t idx = (size_t)(row0 + rr * 8) * N + col;
                __nv_bfloat162 hp; hp.x = h0; hp.y = h1;
                __nv_bfloat162 lp; lp.x = l0; lp.y = l1;
                *(__nv_bfloat162*)&Oh[idx] = hp;
                *(__nv_bfloat162*)&Ol[idx] = lp;
            }
        }
    }
}

// ---------------- output projection (fp32 out) ------------------------------
__global__ void __launch_bounds__(256) gemm_o(
    const __nv_bfloat16* __restrict__ Ah, const __nv_bfloat16* __restrict__ Al,
    const __nv_bfloat16* __restrict__ Bh, const __nv_bfloat16* __restrict__ Bl,
    float* __restrict__ Cf, int M, int N, int K) {
    extern __shared__ char smem[];
    const uint32_t sbase = smem_u32(smem);
    const int tid = threadIdx.x, wid = tid >> 5, lane = tid & 31;
    const int bm = blockIdx.y * 128, bn = blockIdx.x * 128;
    const int wm = (wid & 3) * 32;
    const int wn = (wid >> 2) * 64;
    const int g = lane >> 3, rl = lane & 7;

    float acc[2][8][4];
#pragma unroll
    for (int a = 0; a < 2; a++)
#pragma unroll
        for (int b = 0; b < 8; b++)
#pragma unroll
            for (int d = 0; d < 4; d++) acc[a][b][d] = 0.f;

    const int nch = K >> 5;
    g_issue(Ah, Al, Bh, Bl, sbase, tid, bm, bn, K, 0);
    g_issue(Ah, Al, Bh, Bl, sbase + GSTAGE, tid, bm, bn, K, 1);

    for (int c = 0; c < nch; c++) {
        uint32_t sbuf = sbase + (uint32_t)(c % 3) * GSTAGE;
        if (c + 2 < nch) {
            g_issue(Ah, Al, Bh, Bl, sbase + (uint32_t)((c + 2) % 3) * GSTAGE, tid, bm, bn, K, c + 2);
            CP_WAIT2();
        } else if (c + 1 < nch) {
            CP_WAIT1();
        } else {
            CP_WAIT0();
        }
        __syncthreads();
        g_chunk(sbuf, wm, wn, g, rl, acc);
        __syncthreads();
    }

#pragma unroll
    for (int mb = 0; mb < 2; mb++) {
        int row0 = bm + wm + mb * 16 + (lane >> 2);
#pragma unroll
        for (int j = 0; j < 8; j++) {
            int col = bn + wn + j * 8 + (lane & 3) * 2;
            *(float2*)&Cf[(size_t)row0 * N + col]       = make_float2(acc[mb][j][0], acc[mb][j][1]);
            *(float2*)&Cf[(size_t)(row0 + 8) * N + col] = make_float2(acc[mb][j][2], acc[mb][j][3]);
        }
    }
}

// ---------------- flash attention via mma.sync ------------------------------
// grid (16, B*H*2). 8 warps x 16 q rows. 3-stage K/V pipeline.
#define FQ_H 0
#define FQ_L 16384
#define FSTG0 32768
#define FK_H 0
#define FK_L 8192
#define FV_H 16384
#define FV_L 24576
#define FAM  32768
#define FSTG_SZ 33024
#define FL_SMEM (FSTG0 + 3 * FSTG_SZ)

__device__ __forceinline__ void f_issue_stage(uint32_t stg, int tid, int b, int h, int comp,
                                              int kt, const float* __restrict__ amask) {
    const char* Khg = (const char*)(g_kh + ((size_t)(b * S_) + kt * 64) * QKDIM + h * 128 + comp * 64);
    const char* Klg = (const char*)(g_kl + ((size_t)(b * S_) + kt * 64) * QKDIM + h * 128 + comp * 64);
    const char* Vhg = (const char*)(g_vh + ((size_t)(b * S_) + kt * 64) * (H_ * DH_) + h * 64);
    const char* Vlg = (const char*)(g_vl + ((size_t)(b * S_) + kt * 64) * (H_ * DH_) + h * 64);
#pragma unroll
    for (int i = 0; i < 2; i++) {
        int t = tid + i * 256;
        int row = t >> 3, gr = t & 7;
        int off = row * 128 + gr * 16;
        uint32_t sw = (uint32_t)(off ^ ((off >> 3) & 0x70));
        CP16(stg + FK_H + sw, Khg + (size_t)row * (QKDIM * 2) + gr * 16);
        CP16(stg + FK_L + sw, Klg + (size_t)row * (QKDIM * 2) + gr * 16);
        CP16(stg + FV_H + sw, Vhg + (size_t)row * (H_ * DH_ * 2) + gr * 16);
        CP16(stg + FV_L + sw, Vlg + (size_t)row * (H_ * DH_ * 2) + gr * 16);
    }
    if (tid < 16)
        CP16(stg + FAM + tid * 16, amask + b * S_ + kt * 64 + tid * 4);
}

__global__ void __launch_bounds__(256) flashmma_kernel(const float* __restrict__ amask) {
    extern __shared__ char fsm[];
    const uint32_t sb = smem_u32(fsm);
    const int tid = threadIdx.x, wid = tid >> 5, lane = tid & 31;
    const int g = lane >> 3, rl = lane & 7;
    const int qt = (gridDim.x - 1) - blockIdx.x;
    const int z = blockIdx.y;
    const int comp = z & 1;
    const int bh = z >> 1;
    const int b = bh / H_, h = bh % H_;
    const float slope = exp2f(-8.0f * (float)(h + 1) / (float)H_);
    const float scale = 0.125f;
    const int nkt = 2 * qt + 2;

    // ---- load Q tiles (hi/lo), stage 0 together in group 0 ----
    {
        const char* Qhg = (const char*)(g_qh + ((size_t)(b * S_) + qt * 128) * QKDIM + h * 128 + comp * 64);
        const char* Qlg = (const char*)(g_ql + ((size_t)(b * S_) + qt * 128) * QKDIM + h * 128 + comp * 64);
#pragma unroll
        for (int i = 0; i < 4; i++) {
            int t = tid + i * 256;
            int row = t >> 3, gr = t & 7;
            int off = row * 128 + gr * 16;
            uint32_t sw = (uint32_t)(off ^ ((off >> 3) & 0x70));
            CP16(sb + FQ_H + sw, Qhg + (size_t)row * (QKDIM * 2) + gr * 16);
            CP16(sb + FQ_L + sw, Qlg + (size_t)row * (QKDIM * 2) + gr * 16);
        }
    }
    f_issue_stage(sb + FSTG0, tid, b, h, comp, 0, amask);
    CP_COMMIT();
    if (nkt > 1) {
        f_issue_stage(sb + FSTG0 + FSTG_SZ, tid, b, h, comp, 1, amask);
        CP_COMMIT();
    }

    float oa[8][4];
#pragma unroll
    for (int j = 0; j < 8; j++)
#pragma unroll
        for (int d = 0; d < 4; d++) oa[j][d] = 0.f;
    float m0 = -1e30f, m1 = -1e30f, l0 = 0.f, l1 = 0.f;

    const int qr0 = qt * 128 + wid * 16 + (lane >> 2);

    for (int kt = 0; kt < nkt; kt++) {
        uint32_t stg = sb + FSTG0 + (uint32_t)(kt % 3) * FSTG_SZ;
        if (kt + 2 < nkt) {
            f_issue_stage(sb + FSTG0 + (uint32_t)((kt + 2) % 3) * FSTG_SZ, tid, b, h, comp, kt + 2, amask);
            CP_COMMIT();
            CP_WAIT2();
        } else if (kt + 1 < nkt) {
            CP_WAIT1();
        } else {
            CP_WAIT0();
        }
        __syncthreads();

        // ---- S = Q K^T (x3 split) ----
        float sa[8][4];
#pragma unroll
        for (int j = 0; j < 8; j++)
#pragma unroll
            for (int d = 0; d < 4; d++) sa[j][d] = 0.f;
#pragma unroll
        for (int kb = 0; kb < 4; kb++) {
            uint32_t ah[4], al[4];
            {
                int row = wid * 16 + ((g & 1) << 3) + rl;
                int gr = kb * 2 + (g >> 1);
                int off = row * 128 + gr * 16;
                uint32_t sw = (uint32_t)(off ^ ((off >> 3) & 0x70));
                ldsm_x4(ah[0], ah[1], ah[2], ah[3], sb + FQ_H + sw);
                ldsm_x4(al[0], al[1], al[2], al[3], sb + FQ_L + sw);
            }
#pragma unroll
            for (int nb2 = 0; nb2 < 4; nb2++) {
                uint32_t kh4[4], kl4[4];
                int row = nb2 * 16 + ((g >> 1) << 3) + rl;
                int gr = kb * 2 + (g & 1);
                int off = row * 128 + gr * 16;
                uint32_t sw = (uint32_t)(off ^ ((off >> 3) & 0x70));
                ldsm_x4(kh4[0], kh4[1], kh4[2], kh4[3], stg + FK_H + sw);
                ldsm_x4(kl4[0], kl4[1], kl4[2], kl4[3], stg + FK_L + sw);
                MMA16816(sa[nb2 * 2], ah, &kh4[0]);
                MMA16816(sa[nb2 * 2], ah, &kl4[0]);
                MMA16816(sa[nb2 * 2], al, &kh4[0]);
                MMA16816(sa[nb2 * 2 + 1], ah, &kh4[2]);
                MMA16816(sa[nb2 * 2 + 1], ah, &kl4[2]);
                MMA16816(sa[nb2 * 2 + 1], al, &kh4[2]);
            }
        }

        // ---- bias + masks ----
        const float* ams = (const float*)(fsm + (stg - sb) + FAM);
        const int kcb = kt * 64;
#pragma unroll
        for (int nb = 0; nb < 8; nb++) {
            int kc = nb * 8 + (lane & 3) * 2;
            float a0 = (1.0f - ams[kc]) * NEGV;
            float a1 = (1.0f - ams[kc + 1]) * NEGV;
            int k0 = kcb + kc, k1 = k0 + 1;
            float b00 = a0 - slope * (float)(qr0 - k0) + ((k0 > qr0) ? NEGV : 0.f);
            float b01 = a1 - slope * (float)(qr0 - k1) + ((k1 > qr0) ? NEGV : 0.f);
            float b10 = a0 - slope * (float)(qr0 + 8 - k0) + ((k0 > qr0 + 8) ? NEGV : 0.f);
            float b11 = a1 - slope * (float)(qr0 + 8 - k1) + ((k1 > qr0 + 8) ? NEGV : 0.f);
            sa[nb][0] = sa[nb][0] * scale + b00;
            sa[nb][1] = sa[nb][1] * scale + b01;
            sa[nb][2] = sa[nb][2] * scale + b10;
            sa[nb][3] = sa[nb][3] * scale + b11;
        }

        // ---- online softmax ----
        float mx0 = -1e30f, mx1 = -1e30f;
#pragma unroll
        for (int nb = 0; nb < 8; nb++) {
            mx0 = fmaxf(mx0, fmaxf(sa[nb][0], sa[nb][1]));
            mx1 = fmaxf(mx1, fmaxf(sa[nb][2], sa[nb][3]));
        }
        mx0 = fmaxf(mx0, __shfl_xor_sync(0xffffffffu, mx0, 1));
        mx0 = fmaxf(mx0, __shfl_xor_sync(0xffffffffu, mx0, 2));
        mx1 = fmaxf(mx1, __shfl_xor_sync(0xffffffffu, mx1, 1));
        mx1 = fmaxf(mx1, __shfl_xor_sync(0xffffffffu, mx1, 2));
        float mn0 = fmaxf(m0, mx0), mn1 = fmaxf(m1, mx1);
        float al0 = __expf(m0 - mn0), al1 = __expf(m1 - mn1);
        m0 = mn0; m1 = mn1;
        float ls0 = 0.f, ls1 = 0.f;
#pragma unroll
        for (int nb = 0; nb < 8; nb++) {
            sa[nb][0] = __expf(sa[nb][0] - mn0);
            sa[nb][1] = __expf(sa[nb][1] - mn0);
            sa[nb][2] = __expf(sa[nb][2] - mn1);
            sa[nb][3] = __expf(sa[nb][3] - mn1);
            ls0 += sa[nb][0] + sa[nb][1];
            ls1 += sa[nb][2] + sa[nb][3];
        }
        ls0 += __shfl_xor_sync(0xffffffffu, ls0, 1);
        ls0 += __shfl_xor_sync(0xffffffffu, ls0, 2);
        ls1 += __shfl_xor_sync(0xffffffffu, ls1, 1);
        ls1 += __shfl_xor_sync(0xffffffffu, ls1, 2);
        l0 = l0 * al0 + ls0;
        l1 = l1 * al1 + ls1;

#pragma unroll
        for (int j = 0; j < 8; j++) {
            oa[j][0] *= al0; oa[j][1] *= al0;
            oa[j][2] *= al1; oa[j][3] *= al1;
        }

        // ---- pack P (hi/lo A fragments) ----
        uint32_t pAh[4][4], pAl[4][4];
#pragma unroll
        for (int kb2 = 0; kb2 < 4; kb2++) {
#pragma unroll
            for (int half = 0; half < 2; half++) {
                float v0a = sa[kb2 * 2][half * 2], v1a = sa[kb2 * 2][half * 2 + 1];
                float v0b = sa[kb2 * 2 + 1][half * 2], v1b = sa[kb2 * 2 + 1][half * 2 + 1];
                __nv_bfloat16 h0a = __float2bfloat16(v0a), h1a = __float2bfloat16(v1a);
                __nv_bfloat16 h0b = __float2bfloat16(v0b), h1b = __float2bfloat16(v1b);
                pAh[kb2][half]     = pack_bf2(__bfloat162float(h0a), __bfloat162float(h1a));
                pAh[kb2][2 + half] = pack_bf2(__bfloat162float(h0b), __bfloat162float(h1b));
                pAl[kb2][half]     = pack_bf2(v0a - __bfloat162float(h0a), v1a - __bfloat162float(h1a));
                pAl[kb2][2 + half] = pack_bf2(v0b - __bfloat162float(h0b), v1b - __bfloat162float(h1b));
            }
        }

        // ---- O += P V (x3 split) ----
#pragma unroll
        for (int kb2 = 0; kb2 < 4; kb2++) {
#pragma unroll
            for (int db = 0; db < 4; db++) {
                uint32_t vh4[4], vl4[4];
                int row = kb2 * 16 + ((g & 1) << 3) + rl;
                int gr = db * 2 + (g >> 1);
                int off = row * 128 + gr * 16;
                uint32_t sw = (uint32_t)(off ^ ((off >> 3) & 0x70));
                ldsm_x4t(vh4[0], vh4[1], vh4[2], vh4[3], stg + FV_H + sw);
                ldsm_x4t(vl4[0], vl4[1], vl4[2], vl4[3], stg + FV_L + sw);
                MMA16816(oa[db * 2], pAh[kb2], &vh4[0]);
                MMA16816(oa[db * 2], pAh[kb2], &vl4[0]);
                MMA16816(oa[db * 2], pAl[kb2], &vh4[0]);
                MMA16816(oa[db * 2 + 1], pAh[kb2], &vh4[2]);
                MMA16816(oa[db * 2 + 1], pAh[kb2], &vl4[2]);
                MMA16816(oa[db * 2 + 1], pAl[kb2], &vh4[2]);
            }
        }
        __syncthreads();
    }

    // ---- epilogue ----
    float inv0 = 1.0f / l0, inv1 = 1.0f / l1;
    float* Og = (comp ? g_o2 : g_o1) + ((size_t)(b * S_) + qr0) * (H_ * DH_) + h * 64;
#pragma unroll
    for (int j = 0; j < 8; j++) {
        int col = j * 8 + (lane & 3) * 2;
        *(float2*)&Og[col] = make_float2(oa[j][0] * inv0, oa[j][1] * inv0);
        *(float2*)&Og[(size_t)8 * (H_ * DH_) + col] = make_float2(oa[j][2] * inv1, oa[j][3] * inv1);
    }
}

// ---------------- combine ---------------------------------------------------
__global__ void __launch_bounds__(256) combine_kernel() {
    int f = blockIdx.x * blockDim.x + threadIdx.x;
    if (f >= (B_ * S_ * H_ * DH_) / 4) return;
    int e = f * 4;
    float lam = g_lambda;
    float4 a = *(const float4*)&g_o1[e];
    float4 c = *(const float4*)&g_o2[e];
    float4 y;
    y.x = a.x - lam * c.x; y.y = a.y - lam * c.y;
    y.z = a.z - lam * c.z; y.w = a.w - lam * c.w;
    *(float4*)&g_o[e] = y;
}

// ---------------- group norm stats ------------------------------------------
__global__ void __launch_bounds__(256) gn_stats_kernel() {
    const int bh = blockIdx.x;
    const int b = bh / H_, h = bh % H_;
    double s = 0.0, ss = 0.0;
    for (int f = threadIdx.x; f < S_ * (DH_ / 4); f += blockDim.x) {
        int row = f >> 4, c = (f & 15) * 4;
        float4 v = *(const float4*)&g_o[(size_t)(b * S_ + row) * (H_ * DH_) + h * DH_ + c];
        s += (double)v.x + v.y + v.z + v.w;
        ss += (double)v.x * v.x + (double)v.y * v.y + (double)v.z * v.z + (double)v.w * v.w;
    }
    __shared__ double sh_s[256], sh_ss[256];
    sh_s[threadIdx.x] = s; sh_ss[threadIdx.x] = ss;
    __syncthreads();
    for (int st = 128; st > 0; st >>= 1) {
        if (threadIdx.x < st) {
            sh_s[threadIdx.x] += sh_s[threadIdx.x + st];
            sh_ss[threadIdx.x] += sh_ss[threadIdx.x + st];
        }
        __syncthreads();
    }
    if (threadIdx.x == 0) {
        double n = (double)S_ * DH_;
        double mean = sh_s[0] / n;
        double var = sh_ss[0] / n - mean * mean;
        g_stats[bh * 2 + 0] = (float)mean;
        g_stats[bh * 2 + 1] = rsqrtf((float)var + EPS_);
    }
}

// ---------------- normalize + emit bf16 hi/lo -------------------------------
__global__ void __launch_bounds__(256) gn_apply_kernel(const float* __restrict__ gamma,
                                                       const float* __restrict__ beta) {
    int f = blockIdx.x * blockDim.x + threadIdx.x;
    if (f >= (B_ * S_ * H_ * DH_) / 4) return;
    int e = f * 4;
    int c = e % (H_ * DH_);
    int row = e / (H_ * DH_);
    int b = row / S_;
    int h = c / DH_;
    float mean = g_stats[(b * H_ + h) * 2 + 0];
    float inv  = g_stats[(b * H_ + h) * 2 + 1];
    float4 x = *(const float4*)&g_o[e];
    float4 gm = *(const float4*)&gamma[c];
    float4 bt = *(const float4*)&beta[c];
    const float post = 1.0f - LAMBDA_INIT;
    float y[4];
    y[0] = ((x.x - mean) * inv * gm.x + bt.x) * post;
    y[1] = ((x.y - mean) * inv * gm.y + bt.y) * post;
    y[2] = ((x.z - mean) * inv * gm.z + bt.z) * post;
    y[3] = ((x.w - mean) * inv * gm.w + bt.w) * post;
    __nv_bfloat16 hh[4], ll[4];
#pragma unroll
    for (int j = 0; j < 4; j++) {
        hh[j] = __float2bfloat16(y[j]);
        ll[j] = __float2bfloat16(y[j] - __bfloat162float(hh[j]));
    }
    *(uint2*)&g_nh[e] = *(uint2*)hh;
    *(uint2*)&g_nl[e] = *(uint2*)ll;
}

// ---------------- launch ----------------------------------------------------
extern "C" void kernel_launch(void* const* d_in, const int* in_sizes, int n_in,
                              void* d_out, int out_size) {
    const float* x     = (const float*)d_in[0];
    const float* amask = (const float*)d_in[1];
    const float* Wq = (const float*)d_in[3];
    const float* Wk = (const float*)d_in[4];
    const float* Wv = (const float*)d_in[5];
    const float* Wo = (const float*)d_in[6];
    const float* lq1 = (const float*)d_in[7];
    const float* lq2 = (const float*)d_in[8];
    const float* lk1 = (const float*)d_in[9];
    const float* lk2 = (const float*)d_in[10];
    const float* gam = (const float*)d_in[11];
    const float* bet = (const float*)d_in[12];
    float* out = (float*)d_out;

    __nv_bfloat16 *xh, *xl, *wqh, *wql, *wkh, *wkl, *wvh, *wvl, *woh, *wol, *nh, *nl;
    cudaGetSymbolAddress((void**)&xh, g_xh);   cudaGetSymbolAddress((void**)&xl, g_xl);
    cudaGetSymbolAddress((void**)&wqh, g_wqh); cudaGetSymbolAddress((void**)&wql, g_wql);
    cudaGetSymbolAddress((void**)&wkh, g_wkh); cudaGetSymbolAddress((void**)&wkl, g_wkl);
    cudaGetSymbolAddress((void**)&wvh, g_wvh); cudaGetSymbolAddress((void**)&wvl, g_wvl);
    cudaGetSymbolAddress((void**)&woh, g_woh); cudaGetSymbolAddress((void**)&wol, g_wol);
    cudaGetSymbolAddress((void**)&nh, g_nh);   cudaGetSymbolAddress((void**)&nl, g_nl);

    const int M = B_ * S_;  // 4096

    // launches 0-3: conversions (order chosen so launch #5 = flashmma for ncu)
    cvt_kernel<<<(M * D_ / 4 + 255) / 256, 256>>>(x, xh, xl, M * D_ / 4);
    cvt_kernel<<<(QKDIM * D_ / 4 + 255) / 256, 256>>>(Wq, wqh, wql, QKDIM * D_ / 4);
    cvt_kernel<<<(QKDIM * D_ / 4 + 255) / 256, 256>>>(Wk, wkh, wkl, QKDIM * D_ / 4);
    cvt2_kernel<<<(2 * H_ * DH_ * D_ / 4 + 255) / 256, 256>>>(
        Wv, wvh, wvl, H_ * DH_ * D_ / 4, Wo, woh, wol, D_ * H_ * DH_ / 4);

    // launch 4: fused QKV projection
    cudaFuncSetAttribute(gemm_qkv, cudaFuncAttributeMaxDynamicSharedMemorySize, G_SMEM);
    gemm_qkv<<<dim3(40, M / 128), 256, G_SMEM>>>();

    // launch 5: flash attention (profiled by ncu -s 5 -c 1)
    cudaFuncSetAttribute(flashmma_kernel, cudaFuncAttributeMaxDynamicSharedMemorySize, FL_SMEM);
    flashmma_kernel<<<dim3(S_ / 128, B_ * H_ * 2), 256, FL_SMEM>>>(amask);

    // lambda + combine + group norm
    lam_kernel<<<1, 1>>>(lq1, lq2, lk1, lk2);
    combine_kernel<<<(B_ * S_ * H_ * DH_ / 4 + 255) / 256, 256>>>();
    gn_stats_kernel<<<B_ * H_, 256>>>();
    gn_apply_kernel<<<(B_ * S_ * H_ * DH_ / 4 + 255) / 256, 256>>>(gam, bet);

    // output projection -> d_out (fp32)
    cudaFuncSetAttribute(gemm_o, cudaFuncAttributeMaxDynamicSharedMemorySize, G_SMEM);
    gemm_o<<<dim3(D_ / 128, M / 128), 256, G_SMEM>>>(nh, nl, woh, wol, out, M, D_, H_ * DH_);
}

// round 7
// speedup vs baseline: 7.1422x; 1.1269x over previous
#include <cuda_runtime.h>
#include <cuda_bf16.h>
#include <math.h>
#include <cstdint>

#define B_  2
#define S_  2048
#define D_  1024
#define H_  16
#define DH_ 64
#define QKDIM 2048
#define NEGV (-1000000000.0f)
#define LAMBDA_INIT 0.8f
#define EPS_ 1e-5f

// ---------------- scratch (device globals) ---------------------------------
__device__ float g_o1[(size_t)B_ * S_ * H_ * DH_];
__device__ float g_o2[(size_t)B_ * S_ * H_ * DH_];
__device__ float g_o [(size_t)B_ * S_ * H_ * DH_];
__device__ float g_lambda;
__device__ double g_sum[B_ * H_], g_sumsq[B_ * H_];

// bf16 split buffers
__device__ __nv_bfloat16 g_xh[(size_t)B_ * S_ * D_], g_xl[(size_t)B_ * S_ * D_];
__device__ __nv_bfloat16 g_wqh[QKDIM * D_], g_wql[QKDIM * D_];
__device__ __nv_bfloat16 g_wkh[QKDIM * D_], g_wkl[QKDIM * D_];
__device__ __nv_bfloat16 g_wvh[(H_ * DH_) * D_], g_wvl[(H_ * DH_) * D_];
__device__ __nv_bfloat16 g_woh[D_ * (H_ * DH_)], g_wol[D_ * (H_ * DH_)];
__device__ __nv_bfloat16 g_nh[(size_t)B_ * S_ * H_ * DH_], g_nl[(size_t)B_ * S_ * H_ * DH_];
__device__ __nv_bfloat16 g_qh[(size_t)B_ * S_ * QKDIM], g_ql[(size_t)B_ * S_ * QKDIM];
__device__ __nv_bfloat16 g_kh[(size_t)B_ * S_ * QKDIM], g_kl[(size_t)B_ * S_ * QKDIM];
__device__ __nv_bfloat16 g_vh[(size_t)B_ * S_ * H_ * DH_], g_vl[(size_t)B_ * S_ * H_ * DH_];

// ---------------- helpers ---------------------------------------------------
__device__ __forceinline__ uint32_t smem_u32(const void* p) {
    uint32_t a;
    asm("{ .reg .u64 t; cvta.to.shared.u64 t, %1; cvt.u32.u64 %0, t; }" : "=r"(a) : "l"(p));
    return a;
}
#define CP16(dst, src) \
    asm volatile("cp.async.cg.shared.global [%0], [%1], 16;" :: "r"(dst), "l"(src) : "memory")
#define CP_COMMIT() asm volatile("cp.async.commit_group;" ::: "memory")
#define CP_WAIT1()  asm volatile("cp.async.wait_group 1;" ::: "memory")
#define CP_WAIT0()  asm volatile("cp.async.wait_group 0;" ::: "memory")

__device__ __forceinline__ void ldsm_x4(uint32_t& r0, uint32_t& r1, uint32_t& r2, uint32_t& r3,
                                        uint32_t addr) {
    asm volatile("ldmatrix.sync.aligned.m8n8.x4.shared.b16 {%0,%1,%2,%3}, [%4];"
                 : "=r"(r0), "=r"(r1), "=r"(r2), "=r"(r3) : "r"(addr));
}
__device__ __forceinline__ void ldsm_x4t(uint32_t& r0, uint32_t& r1, uint32_t& r2, uint32_t& r3,
                                         uint32_t addr) {
    asm volatile("ldmatrix.sync.aligned.m8n8.x4.trans.shared.b16 {%0,%1,%2,%3}, [%4];"
                 : "=r"(r0), "=r"(r1), "=r"(r2), "=r"(r3) : "r"(addr));
}
#define MMA16816(d, a, b) \
    asm volatile("mma.sync.aligned.m16n8k16.row.col.f32.bf16.bf16.f32 " \
                 "{%0,%1,%2,%3}, {%4,%5,%6,%7}, {%8,%9}, {%0,%1,%2,%3};" \
                 : "+f"((d)[0]), "+f"((d)[1]), "+f"((d)[2]), "+f"((d)[3]) \
                 : "r"((a)[0]), "r"((a)[1]), "r"((a)[2]), "r"((a)[3]), \
                   "r"((b)[0]), "r"((b)[1]))

__device__ __forceinline__ uint32_t pack_bf2(float lo, float hi) {
    __nv_bfloat162 t = __floats2bfloat162_rn(lo, hi);
    return *(uint32_t*)&t;
}

// ---------------- lambda + zero stats ---------------------------------------
__global__ void lam_kernel(const float* __restrict__ lq1, const float* __restrict__ lq2,
                           const float* __restrict__ lk1, const float* __restrict__ lk2) {
    float d1 = 0.f, d2 = 0.f;
    for (int i = 0; i < DH_; i++) { d1 += lq1[i] * lk1[i]; d2 += lq2[i] * lk2[i]; }
    g_lambda = expf(d1) - expf(d2) + LAMBDA_INIT;
    for (int i = 0; i < B_ * H_; i++) { g_sum[i] = 0.0; g_sumsq[i] = 0.0; }
}

// ---------------- fused fp32 -> bf16 hi/lo split of all operands ------------
#define N4_X  (B_ * S_ * D_ / 4)        // 1048576
#define N4_WQ (QKDIM * D_ / 4)          // 524288
#define N4_WV (H_ * DH_ * D_ / 4)       // 262144
#define N4_TOT (N4_X + 2 * N4_WQ + 2 * N4_WV)

__device__ __forceinline__ void split4(const float* src, __nv_bfloat16* h, __nv_bfloat16* l,
                                       size_t i) {
    float4 v = ((const float4*)src)[i];
    float vv[4] = {v.x, v.y, v.z, v.w};
    __nv_bfloat16 hh[4], ll[4];
#pragma unroll
    for (int j = 0; j < 4; j++) {
        hh[j] = __float2bfloat16(vv[j]);
        ll[j] = __float2bfloat16(vv[j] - __bfloat162float(hh[j]));
    }
    *(uint2*)&h[i * 4] = *(uint2*)hh;
    *(uint2*)&l[i * 4] = *(uint2*)ll;
}

__global__ void __launch_bounds__(256) cvt_all(
    const float* __restrict__ x,  const float* __restrict__ Wq,
    const float* __restrict__ Wk, const float* __restrict__ Wv,
    const float* __restrict__ Wo) {
    int i = blockIdx.x * 256 + threadIdx.x;
    if (i < N4_X) { split4(x, g_xh, g_xl, i); return; }
    i -= N4_X;
    if (i < N4_WQ) { split4(Wq, g_wqh, g_wql, i); return; }
    i -= N4_WQ;
    if (i < N4_WQ) { split4(Wk, g_wkh, g_wkl, i); return; }
    i -= N4_WQ;
    if (i < N4_WV) { split4(Wv, g_wvh, g_wvl, i); return; }
    i -= N4_WV;
    if (i < N4_WV) { split4(Wo, g_woh, g_wol, i); return; }
}

// ---------------- GEMM stage loader -----------------------------------------
#define GSTAGE 32768
#define G_SMEM (3 * GSTAGE)

__device__ __forceinline__ void g_issue(
    const __nv_bfloat16* __restrict__ Ah, const __nv_bfloat16* __restrict__ Al,
    const __nv_bfloat16* __restrict__ Bh, const __nv_bfloat16* __restrict__ Bl,
    uint32_t sbuf, int tid, int bm, int bn, int K, int c) {
#pragma unroll
    for (int i = 0; i < 2; i++) {
        int ch = tid + i * 256;
        int p = ch >> 3, c16 = ch & 7;
        int r = (p << 1) + (c16 >> 2);
        int kb = (c16 & 3) * 8;
        int off = p * 128 + c16 * 16;
        uint32_t dst = sbuf + (off ^ ((off >> 3) & 0x70));
        size_t ga = (size_t)(bm + r) * K + c * 32 + kb;
        size_t gb = (size_t)(bn + r) * K + c * 32 + kb;
        CP16(dst,         Ah + ga);
        CP16(dst + 8192,  Al + ga);
        CP16(dst + 16384, Bh + gb);
        CP16(dst + 24576, Bl + gb);
    }
    CP_COMMIT();
}

__device__ __forceinline__ void g_chunk(uint32_t sbuf, int wm, int wn, int g, int rl,
                                        float acc[2][8][4]) {
#pragma unroll
    for (int ks = 0; ks < 2; ks++) {
        uint32_t ah[2][4], al[2][4];
#pragma unroll
        for (int mb = 0; mb < 2; mb++) {
            int r = wm + mb * 16 + ((g & 1) << 3) + rl;
            int c16 = ((r & 1) << 2) + ks * 2 + (g >> 1);
            int off = (r >> 1) * 128 + c16 * 16;
            uint32_t sw = (uint32_t)(off ^ ((off >> 3) & 0x70));
            ldsm_x4(ah[mb][0], ah[mb][1], ah[mb][2], ah[mb][3], sbuf + sw);
            ldsm_x4(al[mb][0], al[mb][1], al[mb][2], al[mb][3], sbuf + 8192 + sw);
        }
        uint32_t bh[4][4], bl[4][4];
#pragma unroll
        for (int np = 0; np < 4; np++) {
            int r = wn + np * 16 + ((g >> 1) << 3) + rl;
            int c16 = ((r & 1) << 2) + ks * 2 + (g & 1);
            int off = (r >> 1) * 128 + c16 * 16;
            uint32_t sw = (uint32_t)(off ^ ((off >> 3) & 0x70));
            ldsm_x4(bh[np][0], bh[np][1], bh[np][2], bh[np][3], sbuf + 16384 + sw);
            ldsm_x4(bl[np][0], bl[np][1], bl[np][2], bl[np][3], sbuf + 24576 + sw);
        }
#pragma unroll
        for (int mb = 0; mb < 2; mb++)
#pragma unroll
            for (int j = 0; j < 8; j++) {
                MMA16816(acc[mb][j], ah[mb], &bh[j >> 1][(j & 1) * 2]);
                MMA16816(acc[mb][j], ah[mb], &bl[j >> 1][(j & 1) * 2]);
                MMA16816(acc[mb][j], al[mb], &bh[j >> 1][(j & 1) * 2]);
            }
    }
}

// ---------------- fused QKV projection (bf16 hi/lo out) ---------------------
__global__ void __launch_bounds__(256) gemm_qkv() {
    extern __shared__ char smem[];
    const uint32_t sbase = smem_u32(smem);
    const int tid = threadIdx.x, wid = tid >> 5, lane = tid & 31;
    const int nt = blockIdx.x;
    const int bm = blockIdx.y * 128;
    const int wm = (wid & 3) * 32;
    const int wn = (wid >> 2) * 64;
    const int g = lane >> 3, rl = lane & 7;
    const int K = D_;

    const __nv_bfloat16 *Ah = g_xh, *Al = g_xl, *Bh, *Bl;
    __nv_bfloat16 *Oh, *Ol;
    int N, bn;
    if (nt < 16)      { Bh = g_wqh; Bl = g_wql; Oh = g_qh; Ol = g_ql; N = QKDIM; bn = nt * 128; }
    else if (nt < 32) { Bh = g_wkh; Bl = g_wkl; Oh = g_kh; Ol = g_kl; N = QKDIM; bn = (nt - 16) * 128; }
    else              { Bh = g_wvh; Bl = g_wvl; Oh = g_vh; Ol = g_vl; N = H_ * DH_; bn = (nt - 32) * 128; }

    float acc[2][8][4];
#pragma unroll
    for (int a = 0; a < 2; a++)
#pragma unroll
        for (int b = 0; b < 8; b++)
#pragma unroll
            for (int d = 0; d < 4; d++) acc[a][b][d] = 0.f;

    const int nch = K >> 5;   // 32
    g_issue(Ah, Al, Bh, Bl, sbase, tid, bm, bn, K, 0);
    g_issue(Ah, Al, Bh, Bl, sbase + GSTAGE, tid, bm, bn, K, 1);

    for (int c = 0; c < nch; c++) {
        if (c + 1 < nch) { CP_WAIT1(); } else { CP_WAIT0(); }
        __syncthreads();
        if (c + 2 < nch)
            g_issue(Ah, Al, Bh, Bl, sbase + (uint32_t)((c + 2) % 3) * GSTAGE, tid, bm, bn, K, c + 2);
        g_chunk(sbase + (uint32_t)(c % 3) * GSTAGE, wm, wn, g, rl, acc);
    }

#pragma unroll
    for (int mb = 0; mb < 2; mb++) {
        int row0 = bm + wm + mb * 16 + (lane >> 2);
#pragma unroll
        for (int j = 0; j < 8; j++) {
            int col = bn + wn + j * 8 + (lane & 3) * 2;
#pragma unroll
            for (int rr = 0; rr < 2; rr++) {
                float v0 = acc[mb][j][rr * 2], v1 = acc[mb][j][rr * 2 + 1];
                __nv_bfloat16 h0 = __float2bfloat16(v0), h1 = __float2bfloat16(v1);
                __nv_bfloat16 l0 = __float2bfloat16(v0 - __bfloat162float(h0));
                __nv_bfloat16 l1 = __float2bfloat16(v1 - __bfloat162float(h1));
                size_t idx = (size_t)(row0 + rr * 8) * N + col;
                __nv_bfloat162 hp; hp.x = h0; hp.y = h1;
                __nv_bfloat162 lp; lp.x = l0; lp.y = l1;
                *(__nv_bfloat162*)&Oh[idx] = hp;
                *(__nv_bfloat162*)&Ol[idx] = lp;
            }
        }
    }
}

// ---------------- output projection (fp32 out) ------------------------------
__global__ void __launch_bounds__(256) gemm_o(
    const __nv_bfloat16* __restrict__ Ah, const __nv_bfloat16* __restrict__ Al,
    const __nv_bfloat16* __restrict__ Bh, const __nv_bfloat16* __restrict__ Bl,
    float* __restrict__ Cf, int M, int N, int K) {
    extern __shared__ char smem[];
    const uint32_t sbase = smem_u32(smem);
    const int tid = threadIdx.x, wid = tid >> 5, lane = tid & 31;
    const int bm = blockIdx.y * 128, bn = blockIdx.x * 128;
    const int wm = (wid & 3) * 32;
    const int wn = (wid >> 2) * 64;
    const int g = lane >> 3, rl = lane & 7;

    float acc[2][8][4];
#pragma unroll
    for (int a = 0; a < 2; a++)
#pragma unroll
        for (int b = 0; b < 8; b++)
#pragma unroll
            for (int d = 0; d < 4; d++) acc[a][b][d] = 0.f;

    const int nch = K >> 5;
    g_issue(Ah, Al, Bh, Bl, sbase, tid, bm, bn, K, 0);
    g_issue(Ah, Al, Bh, Bl, sbase + GSTAGE, tid, bm, bn, K, 1);

    for (int c = 0; c < nch; c++) {
        if (c + 1 < nch) { CP_WAIT1(); } else { CP_WAIT0(); }
        __syncthreads();
        if (c + 2 < nch)
            g_issue(Ah, Al, Bh, Bl, sbase + (uint32_t)((c + 2) % 3) * GSTAGE, tid, bm, bn, K, c + 2);
        g_chunk(sbase + (uint32_t)(c % 3) * GSTAGE, wm, wn, g, rl, acc);
    }

#pragma unroll
    for (int mb = 0; mb < 2; mb++) {
        int row0 = bm + wm + mb * 16 + (lane >> 2);
#pragma unroll
        for (int j = 0; j < 8; j++) {
            int col = bn + wn + j * 8 + (lane & 3) * 2;
            *(float2*)&Cf[(size_t)row0 * N + col]       = make_float2(acc[mb][j][0], acc[mb][j][1]);
            *(float2*)&Cf[(size_t)(row0 + 8) * N + col] = make_float2(acc[mb][j][2], acc[mb][j][3]);
        }
    }
}

// ---------------- flash attention via mma.sync ------------------------------
#define FQ_H 0
#define FQ_L 16384
#define FSTG0 32768
#define FK_H 0
#define FK_L 8192
#define FV_H 16384
#define FV_L 24576
#define FAM  32768
#define FSTG_SZ 33024
#define FL_SMEM (FSTG0 + 3 * FSTG_SZ)

__device__ __forceinline__ void f_issue_stage(uint32_t stg, int tid, int b, int h, int comp,
                                              int kt, const float* __restrict__ amask) {
    const char* Khg = (const char*)(g_kh + ((size_t)(b * S_) + kt * 64) * QKDIM + h * 128 + comp * 64);
    const char* Klg = (const char*)(g_kl + ((size_t)(b * S_) + kt * 64) * QKDIM + h * 128 + comp * 64);
    const char* Vhg = (const char*)(g_vh + ((size_t)(b * S_) + kt * 64) * (H_ * DH_) + h * 64);
    const char* Vlg = (const char*)(g_vl + ((size_t)(b * S_) + kt * 64) * (H_ * DH_) + h * 64);
#pragma unroll
    for (int i = 0; i < 2; i++) {
        int t = tid + i * 256;
        int row = t >> 3, gr = t & 7;
        int off = row * 128 + gr * 16;
        uint32_t sw = (uint32_t)(off ^ ((off >> 3) & 0x70));
        CP16(stg + FK_H + sw, Khg + (size_t)row * (QKDIM * 2) + gr * 16);
        CP16(stg + FK_L + sw, Klg + (size_t)row * (QKDIM * 2) + gr * 16);
        CP16(stg + FV_H + sw, Vhg + (size_t)row * (H_ * DH_ * 2) + gr * 16);
        CP16(stg + FV_L + sw, Vlg + (size_t)row * (H_ * DH_ * 2) + gr * 16);
    }
    if (tid < 16)
        CP16(stg + FAM + tid * 16, amask + b * S_ + kt * 64 + tid * 4);
    CP_COMMIT();
}

__global__ void __launch_bounds__(256) flashmma_kernel(const float* __restrict__ amask) {
    extern __shared__ char fsm[];
    const uint32_t sb = smem_u32(fsm);
    const int tid = threadIdx.x, wid = tid >> 5, lane = tid & 31;
    const int g = lane >> 3, rl = lane & 7;
    const int qt = (gridDim.x - 1) - blockIdx.x;
    const int z = blockIdx.y;
    const int comp = z & 1;
    const int bh = z >> 1;
    const int b = bh / H_, h = bh % H_;
    const float slope = exp2f(-8.0f * (float)(h + 1) / (float)H_);
    const float scale = 0.125f;
    const int nkt = 2 * qt + 2;

    // ---- prologue: Q tiles + stage 0 in group 0, stage 1 in group 1 ----
    {
        const char* Qhg = (const char*)(g_qh + ((size_t)(b * S_) + qt * 128) * QKDIM + h * 128 + comp * 64);
        const char* Qlg = (const char*)(g_ql + ((size_t)(b * S_) + qt * 128) * QKDIM + h * 128 + comp * 64);
#pragma unroll
        for (int i = 0; i < 4; i++) {
            int t = tid + i * 256;
            int row = t >> 3, gr = t & 7;
            int off = row * 128 + gr * 16;
            uint32_t sw = (uint32_t)(off ^ ((off >> 3) & 0x70));
            CP16(sb + FQ_H + sw, Qhg + (size_t)row * (QKDIM * 2) + gr * 16);
            CP16(sb + FQ_L + sw, Qlg + (size_t)row * (QKDIM * 2) + gr * 16);
        }
    }
    {
        const char* Khg0 = (const char*)(g_kh + (size_t)(b * S_) * QKDIM + h * 128 + comp * 64);
        (void)Khg0;
    }
    // stage 0 shares group 0 with Q
    {
        uint32_t stg = sb + FSTG0;
        const char* Khg = (const char*)(g_kh + (size_t)(b * S_) * QKDIM + h * 128 + comp * 64);
        const char* Klg = (const char*)(g_kl + (size_t)(b * S_) * QKDIM + h * 128 + comp * 64);
        const char* Vhg = (const char*)(g_vh + (size_t)(b * S_) * (H_ * DH_) + h * 64);
        const char* Vlg = (const char*)(g_vl + (size_t)(b * S_) * (H_ * DH_) + h * 64);
#pragma unroll
        for (int i = 0; i < 2; i++) {
            int t = tid + i * 256;
            int row = t >> 3, gr = t & 7;
            int off = row * 128 + gr * 16;
            uint32_t sw = (uint32_t)(off ^ ((off >> 3) & 0x70));
            CP16(stg + FK_H + sw, Khg + (size_t)row * (QKDIM * 2) + gr * 16);
            CP16(stg + FK_L + sw, Klg + (size_t)row * (QKDIM * 2) + gr * 16);
            CP16(stg + FV_H + sw, Vhg + (size_t)row * (H_ * DH_ * 2) + gr * 16);
            CP16(stg + FV_L + sw, Vlg + (size_t)row * (H_ * DH_ * 2) + gr * 16);
        }
        if (tid < 16)
            CP16(stg + FAM + tid * 16, amask + b * S_ + tid * 4);
        CP_COMMIT();
    }
    if (nkt > 1)
        f_issue_stage(sb + FSTG0 + FSTG_SZ, tid, b, h, comp, 1, amask);

    float oa[8][4];
#pragma unroll
    for (int j = 0; j < 8; j++)
#pragma unroll
        for (int d = 0; d < 4; d++) oa[j][d] = 0.f;
    float m0 = -1e30f, m1 = -1e30f, l0 = 0.f, l1 = 0.f;
    uint32_t qAh[4][4], qAl[4][4];

    const int qr0 = qt * 128 + wid * 16 + (lane >> 2);

    for (int kt = 0; kt < nkt; kt++) {
        if (kt + 1 < nkt) { CP_WAIT1(); } else { CP_WAIT0(); }
        __syncthreads();
        if (kt + 2 < nkt)
            f_issue_stage(sb + FSTG0 + (uint32_t)((kt + 2) % 3) * FSTG_SZ, tid, b, h, comp, kt + 2, amask);
        uint32_t stg = sb + FSTG0 + (uint32_t)(kt % 3) * FSTG_SZ;

        if (kt == 0) {
            // hoist Q fragments to registers (once)
#pragma unroll
            for (int kb = 0; kb < 4; kb++) {
                int row = wid * 16 + ((g & 1) << 3) + rl;
                int gr = kb * 2 + (g >> 1);
                int off = row * 128 + gr * 16;
                uint32_t sw = (uint32_t)(off ^ ((off >> 3) & 0x70));
                ldsm_x4(qAh[kb][0], qAh[kb][1], qAh[kb][2], qAh[kb][3], sb + FQ_H + sw);
                ldsm_x4(qAl[kb][0], qAl[kb][1], qAl[kb][2], qAl[kb][3], sb + FQ_L + sw);
            }
        }

        // ---- S = Q K^T (x3 split) ----
        float sa[8][4];
#pragma unroll
        for (int j = 0; j < 8; j++)
#pragma unroll
            for (int d = 0; d < 4; d++) sa[j][d] = 0.f;
#pragma unroll
        for (int kb = 0; kb < 4; kb++) {
#pragma unroll
            for (int nb2 = 0; nb2 < 4; nb2++) {
                uint32_t kh4[4], kl4[4];
                int row = nb2 * 16 + ((g >> 1) << 3) + rl;
                int gr = kb * 2 + (g & 1);
                int off = row * 128 + gr * 16;
                uint32_t sw = (uint32_t)(off ^ ((off >> 3) & 0x70));
                ldsm_x4(kh4[0], kh4[1], kh4[2], kh4[3], stg + FK_H + sw);
                ldsm_x4(kl4[0], kl4[1], kl4[2], kl4[3], stg + FK_L + sw);
                MMA16816(sa[nb2 * 2], qAh[kb], &kh4[0]);
                MMA16816(sa[nb2 * 2], qAh[kb], &kl4[0]);
                MMA16816(sa[nb2 * 2], qAl[kb], &kh4[0]);
                MMA16816(sa[nb2 * 2 + 1], qAh[kb], &kh4[2]);
                MMA16816(sa[nb2 * 2 + 1], qAh[kb], &kl4[2]);
                MMA16816(sa[nb2 * 2 + 1], qAl[kb], &kh4[2]);
            }
        }

        // ---- bias + masks ----
        const float* ams = (const float*)(fsm + (stg - sb) + FAM);
        const int kcb = kt * 64;
#pragma unroll
        for (int nb = 0; nb < 8; nb++) {
            int kc = nb * 8 + (lane & 3) * 2;
            float a0 = (1.0f - ams[kc]) * NEGV;
            float a1 = (1.0f - ams[kc + 1]) * NEGV;
            int k0 = kcb + kc, k1 = k0 + 1;
            float b00 = a0 - slope * (float)(qr0 - k0) + ((k0 > qr0) ? NEGV : 0.f);
            float b01 = a1 - slope * (float)(qr0 - k1) + ((k1 > qr0) ? NEGV : 0.f);
            float b10 = a0 - slope * (float)(qr0 + 8 - k0) + ((k0 > qr0 + 8) ? NEGV : 0.f);
            float b11 = a1 - slope * (float)(qr0 + 8 - k1) + ((k1 > qr0 + 8) ? NEGV : 0.f);
            sa[nb][0] = sa[nb][0] * scale + b00;
            sa[nb][1] = sa[nb][1] * scale + b01;
            sa[nb][2] = sa[nb][2] * scale + b10;
            sa[nb][3] = sa[nb][3] * scale + b11;
        }

        // ---- online softmax ----
        float mx0 = -1e30f, mx1 = -1e30f;
#pragma unroll
        for (int nb = 0; nb < 8; nb++) {
            mx0 = fmaxf(mx0, fmaxf(sa[nb][0], sa[nb][1]));
            mx1 = fmaxf(mx1, fmaxf(sa[nb][2], sa[nb][3]));
        }
        mx0 = fmaxf(mx0, __shfl_xor_sync(0xffffffffu, mx0, 1));
        mx0 = fmaxf(mx0, __shfl_xor_sync(0xffffffffu, mx0, 2));
        mx1 = fmaxf(mx1, __shfl_xor_sync(0xffffffffu, mx1, 1));
        mx1 = fmaxf(mx1, __shfl_xor_sync(0xffffffffu, mx1, 2));
        float mn0 = fmaxf(m0, mx0), mn1 = fmaxf(m1, mx1);
        float al0 = __expf(m0 - mn0), al1 = __expf(m1 - mn1);
        m0 = mn0; m1 = mn1;
        float ls0 = 0.f, ls1 = 0.f;
#pragma unroll
        for (int nb = 0; nb < 8; nb++) {
            sa[nb][0] = __expf(sa[nb][0] - mn0);
            sa[nb][1] = __expf(sa[nb][1] - mn0);
            sa[nb][2] = __expf(sa[nb][2] - mn1);
            sa[nb][3] = __expf(sa[nb][3] - mn1);
            ls0 += sa[nb][0] + sa[nb][1];
            ls1 += sa[nb][2] + sa[nb][3];
        }
        ls0 += __shfl_xor_sync(0xffffffffu, ls0, 1);
        ls0 += __shfl_xor_sync(0xffffffffu, ls0, 2);
        ls1 += __shfl_xor_sync(0xffffffffu, ls1, 1);
        ls1 += __shfl_xor_sync(0xffffffffu, ls1, 2);
        l0 = l0 * al0 + ls0;
        l1 = l1 * al1 + ls1;

#pragma unroll
        for (int j = 0; j < 8; j++) {
            oa[j][0] *= al0; oa[j][1] *= al0;
            oa[j][2] *= al1; oa[j][3] *= al1;
        }

        // ---- pack P (hi/lo A fragments) ----
        uint32_t pAh[4][4], pAl[4][4];
#pragma unroll
        for (int kb2 = 0; kb2 < 4; kb2++) {
#pragma unroll
            for (int half = 0; half < 2; half++) {
                float v0a = sa[kb2 * 2][half * 2], v1a = sa[kb2 * 2][half * 2 + 1];
                float v0b = sa[kb2 * 2 + 1][half * 2], v1b = sa[kb2 * 2 + 1][half * 2 + 1];
                __nv_bfloat16 h0a = __float2bfloat16(v0a), h1a = __float2bfloat16(v1a);
                __nv_bfloat16 h0b = __float2bfloat16(v0b), h1b = __float2bfloat16(v1b);
                pAh[kb2][half]     = pack_bf2(__bfloat162float(h0a), __bfloat162float(h1a));
                pAh[kb2][2 + half] = pack_bf2(__bfloat162float(h0b), __bfloat162float(h1b));
                pAl[kb2][half]     = pack_bf2(v0a - __bfloat162float(h0a), v1a - __bfloat162float(h1a));
                pAl[kb2][2 + half] = pack_bf2(v0b - __bfloat162float(h0b), v1b - __bfloat162float(h1b));
            }
        }

        // ---- O += P V (x3 split) ----
#pragma unroll
        for (int kb2 = 0; kb2 < 4; kb2++) {
#pragma unroll
            for (int db = 0; db < 4; db++) {
                uint32_t vh4[4], vl4[4];
                int row = kb2 * 16 + ((g & 1) << 3) + rl;
                int gr = db * 2 + (g >> 1);
                int off = row * 128 + gr * 16;
                uint32_t sw = (uint32_t)(off ^ ((off >> 3) & 0x70));
                ldsm_x4t(vh4[0], vh4[1], vh4[2], vh4[3], stg + FV_H + sw);
                ldsm_x4t(vl4[0], vl4[1], vl4[2], vl4[3], stg + FV_L + sw);
                MMA16816(oa[db * 2], pAh[kb2], &vh4[0]);
                MMA16816(oa[db * 2], pAh[kb2], &vl4[0]);
                MMA16816(oa[db * 2], pAl[kb2], &vh4[0]);
                MMA16816(oa[db * 2 + 1], pAh[kb2], &vh4[2]);
                MMA16816(oa[db * 2 + 1], pAh[kb2], &vl4[2]);
                MMA16816(oa[db * 2 + 1], pAl[kb2], &vh4[2]);
            }
        }
    }

    // ---- epilogue ----
    float inv0 = 1.0f / l0, inv1 = 1.0f / l1;
    float* Og = (comp ? g_o2 : g_o1) + ((size_t)(b * S_) + qr0) * (H_ * DH_) + h * 64;
#pragma unroll
    for (int j = 0; j < 8; j++) {
        int col = j * 8 + (lane & 3) * 2;
        *(float2*)&Og[col] = make_float2(oa[j][0] * inv0, oa[j][1] * inv0);
        *(float2*)&Og[(size_t)8 * (H_ * DH_) + col] = make_float2(oa[j][2] * inv1, oa[j][3] * inv1);
    }
}

// ---------------- combine + groupnorm stats ---------------------------------
// grid 256: bh = blockIdx>>3, slice = blockIdx&7 (256 rows each).
__global__ void __launch_bounds__(256) combine_stats_kernel() {
    const int bh = blockIdx.x >> 3;
    const int slice = blockIdx.x & 7;
    const int b = bh / H_, h = bh % H_;
    const float lam = g_lambda;
    double s = 0.0, ss = 0.0;
    const int base_row = b * S_ + slice * 256;
    for (int f = threadIdx.x; f < 256 * (DH_ / 4); f += 256) {
        int row = f >> 4, c = (f & 15) * 4;
        size_t e = (size_t)(base_row + row) * (H_ * DH_) + h * DH_ + c;
        float4 a = *(const float4*)&g_o1[e];
        float4 cc = *(const float4*)&g_o2[e];
        float4 y;
        y.x = a.x - lam * cc.x; y.y = a.y - lam * cc.y;
        y.z = a.z - lam * cc.z; y.w = a.w - lam * cc.w;
        *(float4*)&g_o[e] = y;
        s += (double)y.x + y.y + y.z + y.w;
        ss += (double)y.x * y.x + (double)y.y * y.y + (double)y.z * y.z + (double)y.w * y.w;
    }
    __shared__ double sh_s[256], sh_ss[256];
    sh_s[threadIdx.x] = s; sh_ss[threadIdx.x] = ss;
    __syncthreads();
    for (int st = 128; st > 0; st >>= 1) {
        if (threadIdx.x < st) {
            sh_s[threadIdx.x] += sh_s[threadIdx.x + st];
            sh_ss[threadIdx.x] += sh_ss[threadIdx.x + st];
        }
        __syncthreads();
    }
    if (threadIdx.x == 0) {
        atomicAdd(&g_sum[bh], sh_s[0]);
        atomicAdd(&g_sumsq[bh], sh_ss[0]);
    }
}

// ---------------- normalize + emit bf16 hi/lo -------------------------------
__global__ void __launch_bounds__(256) gn_apply_kernel(const float* __restrict__ gamma,
                                                       const float* __restrict__ beta) {
    int f = blockIdx.x * blockDim.x + threadIdx.x;
    if (f >= (B_ * S_ * H_ * DH_) / 4) return;
    int e = f * 4;
    int c = e % (H_ * DH_);
    int row = e / (H_ * DH_);
    int b = row / S_;
    int h = c / DH_;
    const double n = (double)S_ * DH_;
    double sm = g_sum[b * H_ + h], sq = g_sumsq[b * H_ + h];
    double meand = sm / n;
    float mean = (float)meand;
    float inv = rsqrtf((float)(sq / n - meand * meand) + EPS_);
    float4 x = *(const float4*)&g_o[e];
    float4 gm = *(const float4*)&gamma[c];
    float4 bt = *(const float4*)&beta[c];
    const float post = 1.0f - LAMBDA_INIT;
    float y[4];
    y[0] = ((x.x - mean) * inv * gm.x + bt.x) * post;
    y[1] = ((x.y - mean) * inv * gm.y + bt.y) * post;
    y[2] = ((x.z - mean) * inv * gm.z + bt.z) * post;
    y[3] = ((x.w - mean) * inv * gm.w + bt.w) * post;
    __nv_bfloat16 hh[4], ll[4];
#pragma unroll
    for (int j = 0; j < 4; j++) {
        hh[j] = __float2bfloat16(y[j]);
        ll[j] = __float2bfloat16(y[j] - __bfloat162float(hh[j]));
    }
    *(uint2*)&g_nh[e] = *(uint2*)hh;
    *(uint2*)&g_nl[e] = *(uint2*)ll;
}

// ---------------- launch ----------------------------------------------------
extern "C" void kernel_launch(void* const* d_in, const int* in_sizes, int n_in,
                              void* d_out, int out_size) {
    const float* x     = (const float*)d_in[0];
    const float* amask = (const float*)d_in[1];
    const float* Wq = (const float*)d_in[3];
    const float* Wk = (const float*)d_in[4];
    const float* Wv = (const float*)d_in[5];
    const float* Wo = (const float*)d_in[6];
    const float* lq1 = (const float*)d_in[7];
    const float* lq2 = (const float*)d_in[8];
    const float* lk1 = (const float*)d_in[9];
    const float* lk2 = (const float*)d_in[10];
    const float* gam = (const float*)d_in[11];
    const float* bet = (const float*)d_in[12];
    float* out = (float*)d_out;

    __nv_bfloat16 *woh, *wol, *nh, *nl;
    cudaGetSymbolAddress((void**)&woh, g_woh); cudaGetSymbolAddress((void**)&wol, g_wol);
    cudaGetSymbolAddress((void**)&nh, g_nh);   cudaGetSymbolAddress((void**)&nl, g_nl);

    const int M = B_ * S_;  // 4096

    // 0: lambda + zero stats
    lam_kernel<<<1, 1>>>(lq1, lq2, lk1, lk2);
    // 1: all fp32->bf16 hi/lo splits
    cvt_all<<<N4_TOT / 256, 256>>>(x, Wq, Wk, Wv, Wo);
    // 2: fused QKV projection
    cudaFuncSetAttribute(gemm_qkv, cudaFuncAttributeMaxDynamicSharedMemorySize, G_SMEM);
    gemm_qkv<<<dim3(40, M / 128), 256, G_SMEM>>>();
    // 3: flash attention
    cudaFuncSetAttribute(flashmma_kernel, cudaFuncAttributeMaxDynamicSharedMemorySize, FL_SMEM);
    flashmma_kernel<<<dim3(S_ / 128, B_ * H_ * 2), 256, FL_SMEM>>>(amask);
    // 4: combine + stats
    combine_stats_kernel<<<B_ * H_ * 8, 256>>>();
    // 5: normalize + split
    gn_apply_kernel<<<(B_ * S_ * H_ * DH_ / 4 + 255) / 256, 256>>>(gam, bet);
    // 6: output projection
    cudaFuncSetAttribute(gemm_o, cudaFuncAttributeMaxDynamicSharedMemorySize, G_SMEM);
    gemm_o<<<dim3(D_ / 128, M / 128), 256, G_SMEM>>>(nh, nl, woh, wol, out, M, D_, H_ * DH_);
}

// round 8
// speedup vs baseline: 7.8013x; 1.0923x over previous
#include <cuda_runtime.h>
#include <cuda_bf16.h>
#include <math.h>
#include <cstdint>

#define B_  2
#define S_  2048
#define D_  1024
#define H_  16
#define DH_ 64
#define QKDIM 2048
#define NEGV (-1000000000.0f)
#define LAMBDA_INIT 0.8f
#define EPS_ 1e-5f

// ---------------- scratch (device globals) ---------------------------------
__device__ float g_o1[(size_t)B_ * S_ * H_ * DH_];
__device__ float g_o2[(size_t)B_ * S_ * H_ * DH_];
__device__ float g_o [(size_t)B_ * S_ * H_ * DH_];
__device__ float g_lambda;
__device__ double g_sum[B_ * H_], g_sumsq[B_ * H_];

// bf16 split buffers
__device__ __nv_bfloat16 g_xh[(size_t)B_ * S_ * D_], g_xl[(size_t)B_ * S_ * D_];
__device__ __nv_bfloat16 g_wqh[QKDIM * D_], g_wql[QKDIM * D_];
__device__ __nv_bfloat16 g_wkh[QKDIM * D_], g_wkl[QKDIM * D_];
__device__ __nv_bfloat16 g_wvh[(H_ * DH_) * D_], g_wvl[(H_ * DH_) * D_];
__device__ __nv_bfloat16 g_woh[D_ * (H_ * DH_)], g_wol[D_ * (H_ * DH_)];
__device__ __nv_bfloat16 g_nh[(size_t)B_ * S_ * H_ * DH_], g_nl[(size_t)B_ * S_ * H_ * DH_];
__device__ __nv_bfloat16 g_qh[(size_t)B_ * S_ * QKDIM], g_ql[(size_t)B_ * S_ * QKDIM];
__device__ __nv_bfloat16 g_kh[(size_t)B_ * S_ * QKDIM], g_kl[(size_t)B_ * S_ * QKDIM];
__device__ __nv_bfloat16 g_vh[(size_t)B_ * S_ * H_ * DH_], g_vl[(size_t)B_ * S_ * H_ * DH_];

// ---------------- helpers ---------------------------------------------------
__device__ __forceinline__ uint32_t smem_u32(const void* p) {
    uint32_t a;
    asm("{ .reg .u64 t; cvta.to.shared.u64 t, %1; cvt.u32.u64 %0, t; }" : "=r"(a) : "l"(p));
    return a;
}
#define CP16(dst, src) \
    asm volatile("cp.async.cg.shared.global [%0], [%1], 16;" :: "r"(dst), "l"(src) : "memory")
#define CP_COMMIT() asm volatile("cp.async.commit_group;" ::: "memory")
#define CP_WAIT1()  asm volatile("cp.async.wait_group 1;" ::: "memory")
#define CP_WAIT0()  asm volatile("cp.async.wait_group 0;" ::: "memory")

__device__ __forceinline__ void ldsm_x4(uint32_t& r0, uint32_t& r1, uint32_t& r2, uint32_t& r3,
                                        uint32_t addr) {
    asm volatile("ldmatrix.sync.aligned.m8n8.x4.shared.b16 {%0,%1,%2,%3}, [%4];"
                 : "=r"(r0), "=r"(r1), "=r"(r2), "=r"(r3) : "r"(addr));
}
__device__ __forceinline__ void ldsm_x4t(uint32_t& r0, uint32_t& r1, uint32_t& r2, uint32_t& r3,
                                         uint32_t addr) {
    asm volatile("ldmatrix.sync.aligned.m8n8.x4.trans.shared.b16 {%0,%1,%2,%3}, [%4];"
                 : "=r"(r0), "=r"(r1), "=r"(r2), "=r"(r3) : "r"(addr));
}
#define MMA16816(d, a, b) \
    asm volatile("mma.sync.aligned.m16n8k16.row.col.f32.bf16.bf16.f32 " \
                 "{%0,%1,%2,%3}, {%4,%5,%6,%7}, {%8,%9}, {%0,%1,%2,%3};" \
                 : "+f"((d)[0]), "+f"((d)[1]), "+f"((d)[2]), "+f"((d)[3]) \
                 : "r"((a)[0]), "r"((a)[1]), "r"((a)[2]), "r"((a)[3]), \
                   "r"((b)[0]), "r"((b)[1]))

__device__ __forceinline__ uint32_t pack_bf2(float lo, float hi) {
    __nv_bfloat162 t = __floats2bfloat162_rn(lo, hi);
    return *(uint32_t*)&t;
}

// ---------------- lambda + zero stats ---------------------------------------
__global__ void lam_kernel(const float* __restrict__ lq1, const float* __restrict__ lq2,
                           const float* __restrict__ lk1, const float* __restrict__ lk2) {
    float d1 = 0.f, d2 = 0.f;
    for (int i = 0; i < DH_; i++) { d1 += lq1[i] * lk1[i]; d2 += lq2[i] * lk2[i]; }
    g_lambda = expf(d1) - expf(d2) + LAMBDA_INIT;
    for (int i = 0; i < B_ * H_; i++) { g_sum[i] = 0.0; g_sumsq[i] = 0.0; }
}

// ---------------- fused fp32 -> bf16 hi/lo split of all operands ------------
#define N4_X  (B_ * S_ * D_ / 4)
#define N4_WQ (QKDIM * D_ / 4)
#define N4_WV (H_ * DH_ * D_ / 4)
#define N4_TOT (N4_X + 2 * N4_WQ + 2 * N4_WV)

__device__ __forceinline__ void split4(const float* src, __nv_bfloat16* h, __nv_bfloat16* l,
                                       size_t i) {
    float4 v = ((const float4*)src)[i];
    float vv[4] = {v.x, v.y, v.z, v.w};
    __nv_bfloat16 hh[4], ll[4];
#pragma unroll
    for (int j = 0; j < 4; j++) {
        hh[j] = __float2bfloat16(vv[j]);
        ll[j] = __float2bfloat16(vv[j] - __bfloat162float(hh[j]));
    }
    *(uint2*)&h[i * 4] = *(uint2*)hh;
    *(uint2*)&l[i * 4] = *(uint2*)ll;
}

__global__ void __launch_bounds__(256) cvt_all(
    const float* __restrict__ x,  const float* __restrict__ Wq,
    const float* __restrict__ Wk, const float* __restrict__ Wv,
    const float* __restrict__ Wo) {
    int i = blockIdx.x * 256 + threadIdx.x;
    if (i < N4_X) { split4(x, g_xh, g_xl, i); return; }
    i -= N4_X;
    if (i < N4_WQ) { split4(Wq, g_wqh, g_wql, i); return; }
    i -= N4_WQ;
    if (i < N4_WQ) { split4(Wk, g_wkh, g_wkl, i); return; }
    i -= N4_WQ;
    if (i < N4_WV) { split4(Wv, g_wvh, g_wvl, i); return; }
    i -= N4_WV;
    if (i < N4_WV) { split4(Wo, g_woh, g_wol, i); return; }
}

// ---------------- GEMM stage loader -----------------------------------------
#define GSTAGE 32768
#define G_SMEM (3 * GSTAGE)

__device__ __forceinline__ void g_issue(
    const __nv_bfloat16* __restrict__ Ah, const __nv_bfloat16* __restrict__ Al,
    const __nv_bfloat16* __restrict__ Bh, const __nv_bfloat16* __restrict__ Bl,
    uint32_t sbuf, int tid, int bm, int bn, int K, int c) {
#pragma unroll
    for (int i = 0; i < 2; i++) {
        int ch = tid + i * 256;
        int p = ch >> 3, c16 = ch & 7;
        int r = (p << 1) + (c16 >> 2);
        int kb = (c16 & 3) * 8;
        int off = p * 128 + c16 * 16;
        uint32_t dst = sbuf + (off ^ ((off >> 3) & 0x70));
        size_t ga = (size_t)(bm + r) * K + c * 32 + kb;
        size_t gb = (size_t)(bn + r) * K + c * 32 + kb;
        CP16(dst,         Ah + ga);
        CP16(dst + 8192,  Al + ga);
        CP16(dst + 16384, Bh + gb);
        CP16(dst + 24576, Bl + gb);
    }
    CP_COMMIT();
}

__device__ __forceinline__ void g_chunk(uint32_t sbuf, int wm, int wn, int g, int rl,
                                        float acc[2][8][4]) {
#pragma unroll
    for (int ks = 0; ks < 2; ks++) {
        uint32_t ah[2][4], al[2][4];
#pragma unroll
        for (int mb = 0; mb < 2; mb++) {
            int r = wm + mb * 16 + ((g & 1) << 3) + rl;
            int c16 = ((r & 1) << 2) + ks * 2 + (g >> 1);
            int off = (r >> 1) * 128 + c16 * 16;
            uint32_t sw = (uint32_t)(off ^ ((off >> 3) & 0x70));
            ldsm_x4(ah[mb][0], ah[mb][1], ah[mb][2], ah[mb][3], sbuf + sw);
            ldsm_x4(al[mb][0], al[mb][1], al[mb][2], al[mb][3], sbuf + 8192 + sw);
        }
        uint32_t bh[4][4], bl[4][4];
#pragma unroll
        for (int np = 0; np < 4; np++) {
            int r = wn + np * 16 + ((g >> 1) << 3) + rl;
            int c16 = ((r & 1) << 2) + ks * 2 + (g & 1);
            int off = (r >> 1) * 128 + c16 * 16;
            uint32_t sw = (uint32_t)(off ^ ((off >> 3) & 0x70));
            ldsm_x4(bh[np][0], bh[np][1], bh[np][2], bh[np][3], sbuf + 16384 + sw);
            ldsm_x4(bl[np][0], bl[np][1], bl[np][2], bl[np][3], sbuf + 24576 + sw);
        }
#pragma unroll
        for (int mb = 0; mb < 2; mb++)
#pragma unroll
            for (int j = 0; j < 8; j++) {
                MMA16816(acc[mb][j], ah[mb], &bh[j >> 1][(j & 1) * 2]);
                MMA16816(acc[mb][j], ah[mb], &bl[j >> 1][(j & 1) * 2]);
                MMA16816(acc[mb][j], al[mb], &bh[j >> 1][(j & 1) * 2]);
            }
    }
}

// ---------------- fused QKV projection (bf16 hi/lo out) ---------------------
__global__ void __launch_bounds__(256, 2) gemm_qkv() {
    extern __shared__ char smem[];
    const uint32_t sbase = smem_u32(smem);
    const int tid = threadIdx.x, wid = tid >> 5, lane = tid & 31;
    const int nt = blockIdx.x;
    const int bm = blockIdx.y * 128;
    const int wm = (wid & 3) * 32;
    const int wn = (wid >> 2) * 64;
    const int g = lane >> 3, rl = lane & 7;
    const int K = D_;

    const __nv_bfloat16 *Ah = g_xh, *Al = g_xl, *Bh, *Bl;
    __nv_bfloat16 *Oh, *Ol;
    int N, bn;
    if (nt < 16)      { Bh = g_wqh; Bl = g_wql; Oh = g_qh; Ol = g_ql; N = QKDIM; bn = nt * 128; }
    else if (nt < 32) { Bh = g_wkh; Bl = g_wkl; Oh = g_kh; Ol = g_kl; N = QKDIM; bn = (nt - 16) * 128; }
    else              { Bh = g_wvh; Bl = g_wvl; Oh = g_vh; Ol = g_vl; N = H_ * DH_; bn = (nt - 32) * 128; }

    float acc[2][8][4];
#pragma unroll
    for (int a = 0; a < 2; a++)
#pragma unroll
        for (int b = 0; b < 8; b++)
#pragma unroll
            for (int d = 0; d < 4; d++) acc[a][b][d] = 0.f;

    const int nch = K >> 5;
    g_issue(Ah, Al, Bh, Bl, sbase, tid, bm, bn, K, 0);
    g_issue(Ah, Al, Bh, Bl, sbase + GSTAGE, tid, bm, bn, K, 1);

    for (int c = 0; c < nch; c++) {
        if (c + 1 < nch) { CP_WAIT1(); } else { CP_WAIT0(); }
        __syncthreads();
        if (c + 2 < nch)
            g_issue(Ah, Al, Bh, Bl, sbase + (uint32_t)((c + 2) % 3) * GSTAGE, tid, bm, bn, K, c + 2);
        g_chunk(sbase + (uint32_t)(c % 3) * GSTAGE, wm, wn, g, rl, acc);
    }

#pragma unroll
    for (int mb = 0; mb < 2; mb++) {
        int row0 = bm + wm + mb * 16 + (lane >> 2);
#pragma unroll
        for (int j = 0; j < 8; j++) {
            int col = bn + wn + j * 8 + (lane & 3) * 2;
#pragma unroll
            for (int rr = 0; rr < 2; rr++) {
                float v0 = acc[mb][j][rr * 2], v1 = acc[mb][j][rr * 2 + 1];
                __nv_bfloat16 h0 = __float2bfloat16(v0), h1 = __float2bfloat16(v1);
                __nv_bfloat16 l0 = __float2bfloat16(v0 - __bfloat162float(h0));
                __nv_bfloat16 l1 = __float2bfloat16(v1 - __bfloat162float(h1));
                size_t idx = (size_t)(row0 + rr * 8) * N + col;
                __nv_bfloat162 hp; hp.x = h0; hp.y = h1;
                __nv_bfloat162 lp; lp.x = l0; lp.y = l1;
                *(__nv_bfloat162*)&Oh[idx] = hp;
                *(__nv_bfloat162*)&Ol[idx] = lp;
            }
        }
    }
}

// ---------------- output projection (fp32 out) ------------------------------
__global__ void __launch_bounds__(256, 2) gemm_o(
    const __nv_bfloat16* __restrict__ Ah, const __nv_bfloat16* __restrict__ Al,
    const __nv_bfloat16* __restrict__ Bh, const __nv_bfloat16* __restrict__ Bl,
    float* __restrict__ Cf, int M, int N, int K) {
    extern __shared__ char smem[];
    const uint32_t sbase = smem_u32(smem);
    const int tid = threadIdx.x, wid = tid >> 5, lane = tid & 31;
    const int bm = blockIdx.y * 128, bn = blockIdx.x * 128;
    const int wm = (wid & 3) * 32;
    const int wn = (wid >> 2) * 64;
    const int g = lane >> 3, rl = lane & 7;

    float acc[2][8][4];
#pragma unroll
    for (int a = 0; a < 2; a++)
#pragma unroll
        for (int b = 0; b < 8; b++)
#pragma unroll
            for (int d = 0; d < 4; d++) acc[a][b][d] = 0.f;

    const int nch = K >> 5;
    g_issue(Ah, Al, Bh, Bl, sbase, tid, bm, bn, K, 0);
    g_issue(Ah, Al, Bh, Bl, sbase + GSTAGE, tid, bm, bn, K, 1);

    for (int c = 0; c < nch; c++) {
        if (c + 1 < nch) { CP_WAIT1(); } else { CP_WAIT0(); }
        __syncthreads();
        if (c + 2 < nch)
            g_issue(Ah, Al, Bh, Bl, sbase + (uint32_t)((c + 2) % 3) * GSTAGE, tid, bm, bn, K, c + 2);
        g_chunk(sbase + (uint32_t)(c % 3) * GSTAGE, wm, wn, g, rl, acc);
    }

#pragma unroll
    for (int mb = 0; mb < 2; mb++) {
        int row0 = bm + wm + mb * 16 + (lane >> 2);
#pragma unroll
        for (int j = 0; j < 8; j++) {
            int col = bn + wn + j * 8 + (lane & 3) * 2;
            *(float2*)&Cf[(size_t)row0 * N + col]       = make_float2(acc[mb][j][0], acc[mb][j][1]);
            *(float2*)&Cf[(size_t)(row0 + 8) * N + col] = make_float2(acc[mb][j][2], acc[mb][j][3]);
        }
    }
}

// ---------------- flash attention via mma.sync, 128-key tiles ----------------
// grid (16, B*H*2). 8 warps x 16 q rows. 3-stage pipeline; Q staging overlays
// stage 2 (consumed into registers at kt=0 before stage 2 is first written).
#define FSTG_SZ 66048
#define FK_H 0
#define FK_L 16384
#define FV_H 32768
#define FV_L 49152
#define FAM  65536
#define FQ_H (2 * FSTG_SZ)
#define FQ_L (2 * FSTG_SZ + 16384)
#define FL_SMEM (3 * FSTG_SZ)   // 198144

__device__ __forceinline__ void f_issue_stage(uint32_t stg, int tid, int b, int h, int comp,
                                              int kt, const float* __restrict__ amask) {
    const char* Khg = (const char*)(g_kh + ((size_t)(b * S_) + kt * 128) * QKDIM + h * 128 + comp * 64);
    const char* Klg = (const char*)(g_kl + ((size_t)(b * S_) + kt * 128) * QKDIM + h * 128 + comp * 64);
    const char* Vhg = (const char*)(g_vh + ((size_t)(b * S_) + kt * 128) * (H_ * DH_) + h * 64);
    const char* Vlg = (const char*)(g_vl + ((size_t)(b * S_) + kt * 128) * (H_ * DH_) + h * 64);
#pragma unroll
    for (int i = 0; i < 4; i++) {
        int t = tid + i * 256;              // 0..1023 : row(0..127) x gran(0..7)
        int row = t >> 3, gr = t & 7;
        int off = row * 128 + gr * 16;
        uint32_t sw = (uint32_t)(off ^ ((off >> 3) & 0x70));
        CP16(stg + FK_H + sw, Khg + (size_t)row * (QKDIM * 2) + gr * 16);
        CP16(stg + FK_L + sw, Klg + (size_t)row * (QKDIM * 2) + gr * 16);
        CP16(stg + FV_H + sw, Vhg + (size_t)row * (H_ * DH_ * 2) + gr * 16);
        CP16(stg + FV_L + sw, Vlg + (size_t)row * (H_ * DH_ * 2) + gr * 16);
    }
    if (tid < 32)
        CP16(stg + FAM + tid * 16, amask + b * S_ + kt * 128 + tid * 4);
    CP_COMMIT();
}

__global__ void __launch_bounds__(256) flashmma_kernel(const float* __restrict__ amask) {
    extern __shared__ char fsm[];
    const uint32_t sb = smem_u32(fsm);
    const int tid = threadIdx.x, wid = tid >> 5, lane = tid & 31;
    const int g = lane >> 3, rl = lane & 7;
    const int qt = (gridDim.x - 1) - blockIdx.x;
    const int z = blockIdx.y;
    const int comp = z & 1;
    const int bh = z >> 1;
    const int b = bh / H_, h = bh % H_;
    const float slope = exp2f(-8.0f * (float)(h + 1) / (float)H_);
    const float scale = 0.125f;
    const int nkt = qt + 1;

    // ---- prologue: Q (hi/lo) into FQ region, grouped with stage 0 ----
    {
        const char* Qhg = (const char*)(g_qh + ((size_t)(b * S_) + qt * 128) * QKDIM + h * 128 + comp * 64);
        const char* Qlg = (const char*)(g_ql + ((size_t)(b * S_) + qt * 128) * QKDIM + h * 128 + comp * 64);
#pragma unroll
        for (int i = 0; i < 4; i++) {
            int t = tid + i * 256;
            int row = t >> 3, gr = t & 7;
            int off = row * 128 + gr * 16;
            uint32_t sw = (uint32_t)(off ^ ((off >> 3) & 0x70));
            CP16(sb + FQ_H + sw, Qhg + (size_t)row * (QKDIM * 2) + gr * 16);
            CP16(sb + FQ_L + sw, Qlg + (size_t)row * (QKDIM * 2) + gr * 16);
        }
    }
    f_issue_stage(sb, tid, b, h, comp, 0, amask);            // commit: group {Q, stage0}
    if (nkt > 1) f_issue_stage(sb + FSTG_SZ, tid, b, h, comp, 1, amask);

    float oa[8][4];
#pragma unroll
    for (int j = 0; j < 8; j++)
#pragma unroll
        for (int d = 0; d < 4; d++) oa[j][d] = 0.f;
    float m0 = -1e30f, m1 = -1e30f, l0 = 0.f, l1 = 0.f;
    uint32_t qAh[4][4], qAl[4][4];

    const int qr0 = qt * 128 + wid * 16 + (lane >> 2);

    for (int kt = 0; kt < nkt; kt++) {
        if (kt + 1 < nkt) { CP_WAIT1(); } else { CP_WAIT0(); }
        __syncthreads();
        if (kt == 0) {
            // hoist Q fragments to registers (once); Q region is reused as stage 2
#pragma unroll
            for (int kb = 0; kb < 4; kb++) {
                int row = wid * 16 + ((g & 1) << 3) + rl;
                int gr = kb * 2 + (g >> 1);
                int off = row * 128 + gr * 16;
                uint32_t sw = (uint32_t)(off ^ ((off >> 3) & 0x70));
                ldsm_x4(qAh[kb][0], qAh[kb][1], qAh[kb][2], qAh[kb][3], sb + FQ_H + sw);
                ldsm_x4(qAl[kb][0], qAl[kb][1], qAl[kb][2], qAl[kb][3], sb + FQ_L + sw);
            }
            if (nkt > 2) __syncthreads();   // all warps done reading Q before stage2 write
        }
        if (kt + 2 < nkt)
            f_issue_stage(sb + (uint32_t)((kt + 2) % 3) * FSTG_SZ, tid, b, h, comp, kt + 2, amask);
        uint32_t stg = sb + (uint32_t)(kt % 3) * FSTG_SZ;

        // ---- S = Q K^T (x3 split), 128 keys ----
        float sa[16][4];
#pragma unroll
        for (int j = 0; j < 16; j++)
#pragma unroll
            for (int d = 0; d < 4; d++) sa[j][d] = 0.f;
#pragma unroll
        for (int kb = 0; kb < 4; kb++) {
#pragma unroll
            for (int nb2 = 0; nb2 < 8; nb2++) {
                uint32_t kh4[4], kl4[4];
                int row = nb2 * 16 + ((g >> 1) << 3) + rl;
                int gr = kb * 2 + (g & 1);
                int off = row * 128 + gr * 16;
                uint32_t sw = (uint32_t)(off ^ ((off >> 3) & 0x70));
                ldsm_x4(kh4[0], kh4[1], kh4[2], kh4[3], stg + FK_H + sw);
                ldsm_x4(kl4[0], kl4[1], kl4[2], kl4[3], stg + FK_L + sw);
                MMA16816(sa[nb2 * 2], qAh[kb], &kh4[0]);
                MMA16816(sa[nb2 * 2], qAh[kb], &kl4[0]);
                MMA16816(sa[nb2 * 2], qAl[kb], &kh4[0]);
                MMA16816(sa[nb2 * 2 + 1], qAh[kb], &kh4[2]);
                MMA16816(sa[nb2 * 2 + 1], qAh[kb], &kl4[2]);
                MMA16816(sa[nb2 * 2 + 1], qAl[kb], &kh4[2]);
            }
        }

        // ---- bias + masks ----
        const float* ams = (const float*)(fsm + (stg - sb) + FAM);
        const int kcb = kt * 128;
#pragma unroll
        for (int nb = 0; nb < 16; nb++) {
            int kc = nb * 8 + (lane & 3) * 2;
            float a0 = (1.0f - ams[kc]) * NEGV;
            float a1 = (1.0f - ams[kc + 1]) * NEGV;
            int k0 = kcb + kc, k1 = k0 + 1;
            float b00 = a0 - slope * (float)(qr0 - k0) + ((k0 > qr0) ? NEGV : 0.f);
            float b01 = a1 - slope * (float)(qr0 - k1) + ((k1 > qr0) ? NEGV : 0.f);
            float b10 = a0 - slope * (float)(qr0 + 8 - k0) + ((k0 > qr0 + 8) ? NEGV : 0.f);
            float b11 = a1 - slope * (float)(qr0 + 8 - k1) + ((k1 > qr0 + 8) ? NEGV : 0.f);
            sa[nb][0] = sa[nb][0] * scale + b00;
            sa[nb][1] = sa[nb][1] * scale + b01;
            sa[nb][2] = sa[nb][2] * scale + b10;
            sa[nb][3] = sa[nb][3] * scale + b11;
        }

        // ---- online softmax ----
        float mx0 = -1e30f, mx1 = -1e30f;
#pragma unroll
        for (int nb = 0; nb < 16; nb++) {
            mx0 = fmaxf(mx0, fmaxf(sa[nb][0], sa[nb][1]));
            mx1 = fmaxf(mx1, fmaxf(sa[nb][2], sa[nb][3]));
        }
        mx0 = fmaxf(mx0, __shfl_xor_sync(0xffffffffu, mx0, 1));
        mx0 = fmaxf(mx0, __shfl_xor_sync(0xffffffffu, mx0, 2));
        mx1 = fmaxf(mx1, __shfl_xor_sync(0xffffffffu, mx1, 1));
        mx1 = fmaxf(mx1, __shfl_xor_sync(0xffffffffu, mx1, 2));
        float mn0 = fmaxf(m0, mx0), mn1 = fmaxf(m1, mx1);
        float al0 = __expf(m0 - mn0), al1 = __expf(m1 - mn1);
        m0 = mn0; m1 = mn1;
        float ls0 = 0.f, ls1 = 0.f;
#pragma unroll
        for (int nb = 0; nb < 16; nb++) {
            sa[nb][0] = __expf(sa[nb][0] - mn0);
            sa[nb][1] = __expf(sa[nb][1] - mn0);
            sa[nb][2] = __expf(sa[nb][2] - mn1);
            sa[nb][3] = __expf(sa[nb][3] - mn1);
            ls0 += sa[nb][0] + sa[nb][1];
            ls1 += sa[nb][2] + sa[nb][3];
        }
        ls0 += __shfl_xor_sync(0xffffffffu, ls0, 1);
        ls0 += __shfl_xor_sync(0xffffffffu, ls0, 2);
        ls1 += __shfl_xor_sync(0xffffffffu, ls1, 1);
        ls1 += __shfl_xor_sync(0xffffffffu, ls1, 2);
        l0 = l0 * al0 + ls0;
        l1 = l1 * al1 + ls1;

#pragma unroll
        for (int j = 0; j < 8; j++) {
            oa[j][0] *= al0; oa[j][1] *= al0;
            oa[j][2] *= al1; oa[j][3] *= al1;
        }

        // ---- O += P V (x3 split); P packed per key-block inside the loop ----
#pragma unroll
        for (int kb2 = 0; kb2 < 8; kb2++) {
            uint32_t pAh[4], pAl[4];
#pragma unroll
            for (int half = 0; half < 2; half++) {
                float v0a = sa[kb2 * 2][half * 2], v1a = sa[kb2 * 2][half * 2 + 1];
                float v0b = sa[kb2 * 2 + 1][half * 2], v1b = sa[kb2 * 2 + 1][half * 2 + 1];
                __nv_bfloat16 h0a = __float2bfloat16(v0a), h1a = __float2bfloat16(v1a);
                __nv_bfloat16 h0b = __float2bfloat16(v0b), h1b = __float2bfloat16(v1b);
                pAh[half]     = pack_bf2(__bfloat162float(h0a), __bfloat162float(h1a));
                pAh[2 + half] = pack_bf2(__bfloat162float(h0b), __bfloat162float(h1b));
                pAl[half]     = pack_bf2(v0a - __bfloat162float(h0a), v1a - __bfloat162float(h1a));
                pAl[2 + half] = pack_bf2(v0b - __bfloat162float(h0b), v1b - __bfloat162float(h1b));
            }
#pragma unroll
            for (int db = 0; db < 4; db++) {
                uint32_t vh4[4], vl4[4];
                int row = kb2 * 16 + ((g & 1) << 3) + rl;
                int gr = db * 2 + (g >> 1);
                int off = row * 128 + gr * 16;
                uint32_t sw = (uint32_t)(off ^ ((off >> 3) & 0x70));
                ldsm_x4t(vh4[0], vh4[1], vh4[2], vh4[3], stg + FV_H + sw);
                ldsm_x4t(vl4[0], vl4[1], vl4[2], vl4[3], stg + FV_L + sw);
                MMA16816(oa[db * 2], pAh, &vh4[0]);
                MMA16816(oa[db * 2], pAh, &vl4[0]);
                MMA16816(oa[db * 2], pAl, &vh4[0]);
                MMA16816(oa[db * 2 + 1], pAh, &vh4[2]);
                MMA16816(oa[db * 2 + 1], pAh, &vl4[2]);
                MMA16816(oa[db * 2 + 1], pAl, &vh4[2]);
            }
        }
    }

    // ---- epilogue ----
    float inv0 = 1.0f / l0, inv1 = 1.0f / l1;
    float* Og = (comp ? g_o2 : g_o1) + ((size_t)(b * S_) + qr0) * (H_ * DH_) + h * 64;
#pragma unroll
    for (int j = 0; j < 8; j++) {
        int col = j * 8 + (lane & 3) * 2;
        *(float2*)&Og[col] = make_float2(oa[j][0] * inv0, oa[j][1] * inv0);
        *(float2*)&Og[(size_t)8 * (H_ * DH_) + col] = make_float2(oa[j][2] * inv1, oa[j][3] * inv1);
    }
}

// ---------------- combine + groupnorm stats ---------------------------------
__global__ void __launch_bounds__(256) combine_stats_kernel() {
    const int bh = blockIdx.x >> 3;
    const int slice = blockIdx.x & 7;
    const int b = bh / H_, h = bh % H_;
    const float lam = g_lambda;
    double s = 0.0, ss = 0.0;
    const int base_row = b * S_ + slice * 256;
    for (int f = threadIdx.x; f < 256 * (DH_ / 4); f += 256) {
        int row = f >> 4, c = (f & 15) * 4;
        size_t e = (size_t)(base_row + row) * (H_ * DH_) + h * DH_ + c;
        float4 a = *(const float4*)&g_o1[e];
        float4 cc = *(const float4*)&g_o2[e];
        float4 y;
        y.x = a.x - lam * cc.x; y.y = a.y - lam * cc.y;
        y.z = a.z - lam * cc.z; y.w = a.w - lam * cc.w;
        *(float4*)&g_o[e] = y;
        s += (double)y.x + y.y + y.z + y.w;
        ss += (double)y.x * y.x + (double)y.y * y.y + (double)y.z * y.z + (double)y.w * y.w;
    }
    __shared__ double sh_s[256], sh_ss[256];
    sh_s[threadIdx.x] = s; sh_ss[threadIdx.x] = ss;
    __syncthreads();
    for (int st = 128; st > 0; st >>= 1) {
        if (threadIdx.x < st) {
            sh_s[threadIdx.x] += sh_s[threadIdx.x + st];
            sh_ss[threadIdx.x] += sh_ss[threadIdx.x + st];
        }
        __syncthreads();
    }
    if (threadIdx.x == 0) {
        atomicAdd(&g_sum[bh], sh_s[0]);
        atomicAdd(&g_sumsq[bh], sh_ss[0]);
    }
}

// ---------------- normalize + emit bf16 hi/lo -------------------------------
__global__ void __launch_bounds__(256) gn_apply_kernel(const float* __restrict__ gamma,
                                                       const float* __restrict__ beta) {
    int f = blockIdx.x * blockDim.x + threadIdx.x;
    if (f >= (B_ * S_ * H_ * DH_) / 4) return;
    int e = f * 4;
    int c = e % (H_ * DH_);
    int row = e / (H_ * DH_);
    int b = row / S_;
    int h = c / DH_;
    const double n = (double)S_ * DH_;
    double sm = g_sum[b * H_ + h], sq = g_sumsq[b * H_ + h];
    double meand = sm / n;
    float mean = (float)meand;
    float inv = rsqrtf((float)(sq / n - meand * meand) + EPS_);
    float4 x = *(const float4*)&g_o[e];
    float4 gm = *(const float4*)&gamma[c];
    float4 bt = *(const float4*)&beta[c];
    const float post = 1.0f - LAMBDA_INIT;
    float y[4];
    y[0] = ((x.x - mean) * inv * gm.x + bt.x) * post;
    y[1] = ((x.y - mean) * inv * gm.y + bt.y) * post;
    y[2] = ((x.z - mean) * inv * gm.z + bt.z) * post;
    y[3] = ((x.w - mean) * inv * gm.w + bt.w) * post;
    __nv_bfloat16 hh[4], ll[4];
#pragma unroll
    for (int j = 0; j < 4; j++) {
        hh[j] = __float2bfloat16(y[j]);
        ll[j] = __float2bfloat16(y[j] - __bfloat162float(hh[j]));
    }
    *(uint2*)&g_nh[e] = *(uint2*)hh;
    *(uint2*)&g_nl[e] = *(uint2*)ll;
}

// ---------------- launch ----------------------------------------------------
extern "C" void kernel_launch(void* const* d_in, const int* in_sizes, int n_in,
                              void* d_out, int out_size) {
    const float* x     = (const float*)d_in[0];
    const float* amask = (const float*)d_in[1];
    const float* Wq = (const float*)d_in[3];
    const float* Wk = (const float*)d_in[4];
    const float* Wv = (const float*)d_in[5];
    const float* Wo = (const float*)d_in[6];
    const float* lq1 = (const float*)d_in[7];
    const float* lq2 = (const float*)d_in[8];
    const float* lk1 = (const float*)d_in[9];
    const float* lk2 = (const float*)d_in[10];
    const float* gam = (const float*)d_in[11];
    const float* bet = (const float*)d_in[12];
    float* out = (float*)d_out;

    __nv_bfloat16 *woh, *wol, *nh, *nl;
    cudaGetSymbolAddress((void**)&woh, g_woh); cudaGetSymbolAddress((void**)&wol, g_wol);
    cudaGetSymbolAddress((void**)&nh, g_nh);   cudaGetSymbolAddress((void**)&nl, g_nl);

    const int M = B_ * S_;  // 4096

    // 0: lambda + zero stats
    lam_kernel<<<1, 1>>>(lq1, lq2, lk1, lk2);
    // 1: all fp32->bf16 hi/lo splits
    cvt_all<<<N4_TOT / 256, 256>>>(x, Wq, Wk, Wv, Wo);
    // 2: fused QKV projection
    cudaFuncSetAttribute(gemm_qkv, cudaFuncAttributeMaxDynamicSharedMemorySize, G_SMEM);
    gemm_qkv<<<dim3(40, M / 128), 256, G_SMEM>>>();
    // 3: flash attention (profiled)
    cudaFuncSetAttribute(flashmma_kernel, cudaFuncAttributeMaxDynamicSharedMemorySize, FL_SMEM);
    flashmma_kernel<<<dim3(S_ / 128, B_ * H_ * 2), 256, FL_SMEM>>>(amask);
    // 4: combine + stats
    combine_stats_kernel<<<B_ * H_ * 8, 256>>>();
    // 5: normalize + split
    gn_apply_kernel<<<(B_ * S_ * H_ * DH_ / 4 + 255) / 256, 256>>>(gam, bet);
    // 6: output projection
    cudaFuncSetAttribute(gemm_o, cudaFuncAttributeMaxDynamicSharedMemorySize, G_SMEM);
    gemm_o<<<dim3(D_ / 128, M / 128), 256, G_SMEM>>>(nh, nl, woh, wol, out, M, D_, H_ * DH_);
}

// round 9
// speedup vs baseline: 8.0939x; 1.0375x over previous
#include <cuda_runtime.h>
#include <cuda_bf16.h>
#include <math.h>
#include <cstdint>

#define B_  2
#define S_  2048
#define D_  1024
#define H_  16
#define DH_ 64
#define QKDIM 2048
#define NEGV (-1000000000.0f)
#define LAMBDA_INIT 0.8f
#define EPS_ 1e-5f

// ---------------- scratch (device globals) ---------------------------------
__device__ float g_o1[(size_t)B_ * S_ * H_ * DH_];
__device__ float g_o2[(size_t)B_ * S_ * H_ * DH_];
__device__ float g_o [(size_t)B_ * S_ * H_ * DH_];
__device__ float g_lambda;
__device__ double g_sum[B_ * H_], g_sumsq[B_ * H_];

// bf16 split buffers
__device__ __nv_bfloat16 g_xh[(size_t)B_ * S_ * D_], g_xl[(size_t)B_ * S_ * D_];
__device__ __nv_bfloat16 g_wqh[QKDIM * D_], g_wql[QKDIM * D_];
__device__ __nv_bfloat16 g_wkh[QKDIM * D_], g_wkl[QKDIM * D_];
__device__ __nv_bfloat16 g_wvh[(H_ * DH_) * D_], g_wvl[(H_ * DH_) * D_];
__device__ __nv_bfloat16 g_woh[D_ * (H_ * DH_)], g_wol[D_ * (H_ * DH_)];
__device__ __nv_bfloat16 g_nh[(size_t)B_ * S_ * H_ * DH_], g_nl[(size_t)B_ * S_ * H_ * DH_];
__device__ __nv_bfloat16 g_qh[(size_t)B_ * S_ * QKDIM], g_ql[(size_t)B_ * S_ * QKDIM];
__device__ __nv_bfloat16 g_kh[(size_t)B_ * S_ * QKDIM], g_kl[(size_t)B_ * S_ * QKDIM];
__device__ __nv_bfloat16 g_vh[(size_t)B_ * S_ * H_ * DH_], g_vl[(size_t)B_ * S_ * H_ * DH_];

// ---------------- helpers ---------------------------------------------------
__device__ __forceinline__ uint32_t smem_u32(const void* p) {
    uint32_t a;
    asm("{ .reg .u64 t; cvta.to.shared.u64 t, %1; cvt.u32.u64 %0, t; }" : "=r"(a) : "l"(p));
    return a;
}
#define CP16(dst, src) \
    asm volatile("cp.async.cg.shared.global [%0], [%1], 16;" :: "r"(dst), "l"(src) : "memory")
#define CP_COMMIT() asm volatile("cp.async.commit_group;" ::: "memory")
#define CP_WAIT1()  asm volatile("cp.async.wait_group 1;" ::: "memory")
#define CP_WAIT0()  asm volatile("cp.async.wait_group 0;" ::: "memory")

__device__ __forceinline__ void ldsm_x4(uint32_t& r0, uint32_t& r1, uint32_t& r2, uint32_t& r3,
                                        uint32_t addr) {
    asm volatile("ldmatrix.sync.aligned.m8n8.x4.shared.b16 {%0,%1,%2,%3}, [%4];"
                 : "=r"(r0), "=r"(r1), "=r"(r2), "=r"(r3) : "r"(addr));
}
__device__ __forceinline__ void ldsm_x4t(uint32_t& r0, uint32_t& r1, uint32_t& r2, uint32_t& r3,
                                         uint32_t addr) {
    asm volatile("ldmatrix.sync.aligned.m8n8.x4.trans.shared.b16 {%0,%1,%2,%3}, [%4];"
                 : "=r"(r0), "=r"(r1), "=r"(r2), "=r"(r3) : "r"(addr));
}
#define MMA16816(d, a, b) \
    asm volatile("mma.sync.aligned.m16n8k16.row.col.f32.bf16.bf16.f32 " \
                 "{%0,%1,%2,%3}, {%4,%5,%6,%7}, {%8,%9}, {%0,%1,%2,%3};" \
                 : "+f"((d)[0]), "+f"((d)[1]), "+f"((d)[2]), "+f"((d)[3]) \
                 : "r"((a)[0]), "r"((a)[1]), "r"((a)[2]), "r"((a)[3]), \
                   "r"((b)[0]), "r"((b)[1]))

__device__ __forceinline__ uint32_t pack_bf2(float lo, float hi) {
    __nv_bfloat162 t = __floats2bfloat162_rn(lo, hi);
    return *(uint32_t*)&t;
}

// ---------------- lambda + zero stats ---------------------------------------
__global__ void lam_kernel(const float* __restrict__ lq1, const float* __restrict__ lq2,
                           const float* __restrict__ lk1, const float* __restrict__ lk2) {
    float d1 = 0.f, d2 = 0.f;
    for (int i = 0; i < DH_; i++) { d1 += lq1[i] * lk1[i]; d2 += lq2[i] * lk2[i]; }
    g_lambda = expf(d1) - expf(d2) + LAMBDA_INIT;
    for (int i = 0; i < B_ * H_; i++) { g_sum[i] = 0.0; g_sumsq[i] = 0.0; }
}

// ---------------- fused fp32 -> bf16 hi/lo split of all operands ------------
#define N4_X  (B_ * S_ * D_ / 4)
#define N4_WQ (QKDIM * D_ / 4)
#define N4_WV (H_ * DH_ * D_ / 4)
#define N4_TOT (N4_X + 2 * N4_WQ + 2 * N4_WV)

__device__ __forceinline__ void split4(const float* src, __nv_bfloat16* h, __nv_bfloat16* l,
                                       size_t i) {
    float4 v = ((const float4*)src)[i];
    float vv[4] = {v.x, v.y, v.z, v.w};
    __nv_bfloat16 hh[4], ll[4];
#pragma unroll
    for (int j = 0; j < 4; j++) {
        hh[j] = __float2bfloat16(vv[j]);
        ll[j] = __float2bfloat16(vv[j] - __bfloat162float(hh[j]));
    }
    *(uint2*)&h[i * 4] = *(uint2*)hh;
    *(uint2*)&l[i * 4] = *(uint2*)ll;
}

__global__ void __launch_bounds__(256) cvt_all(
    const float* __restrict__ x,  const float* __restrict__ Wq,
    const float* __restrict__ Wk, const float* __restrict__ Wv,
    const float* __restrict__ Wo) {
    int i = blockIdx.x * 256 + threadIdx.x;
    if (i < N4_X) { split4(x, g_xh, g_xl, i); return; }
    i -= N4_X;
    if (i < N4_WQ) { split4(Wq, g_wqh, g_wql, i); return; }
    i -= N4_WQ;
    if (i < N4_WQ) { split4(Wk, g_wkh, g_wkl, i); return; }
    i -= N4_WQ;
    if (i < N4_WV) { split4(Wv, g_wvh, g_wvl, i); return; }
    i -= N4_WV;
    if (i < N4_WV) { split4(Wo, g_woh, g_wol, i); return; }
}

// ---------------- GEMM stage loader -----------------------------------------
#define GSTAGE 32768
#define G_SMEM (3 * GSTAGE)

__device__ __forceinline__ void g_issue(
    const __nv_bfloat16* __restrict__ Ah, const __nv_bfloat16* __restrict__ Al,
    const __nv_bfloat16* __restrict__ Bh, const __nv_bfloat16* __restrict__ Bl,
    uint32_t sbuf, int tid, int bm, int bn, int K, int c) {
#pragma unroll
    for (int i = 0; i < 2; i++) {
        int ch = tid + i * 256;
        int p = ch >> 3, c16 = ch & 7;
        int r = (p << 1) + (c16 >> 2);
        int kb = (c16 & 3) * 8;
        int off = p * 128 + c16 * 16;
        uint32_t dst = sbuf + (off ^ ((off >> 3) & 0x70));
        size_t ga = (size_t)(bm + r) * K + c * 32 + kb;
        size_t gb = (size_t)(bn + r) * K + c * 32 + kb;
        CP16(dst,         Ah + ga);
        CP16(dst + 8192,  Al + ga);
        CP16(dst + 16384, Bh + gb);
        CP16(dst + 24576, Bl + gb);
    }
    CP_COMMIT();
}

__device__ __forceinline__ void g_chunk(uint32_t sbuf, int wm, int wn, int g, int rl,
                                        float acc[2][8][4]) {
#pragma unroll
    for (int ks = 0; ks < 2; ks++) {
        uint32_t ah[2][4], al[2][4];
#pragma unroll
        for (int mb = 0; mb < 2; mb++) {
            int r = wm + mb * 16 + ((g & 1) << 3) + rl;
            int c16 = ((r & 1) << 2) + ks * 2 + (g >> 1);
            int off = (r >> 1) * 128 + c16 * 16;
            uint32_t sw = (uint32_t)(off ^ ((off >> 3) & 0x70));
            ldsm_x4(ah[mb][0], ah[mb][1], ah[mb][2], ah[mb][3], sbuf + sw);
            ldsm_x4(al[mb][0], al[mb][1], al[mb][2], al[mb][3], sbuf + 8192 + sw);
        }
        uint32_t bh[4][4], bl[4][4];
#pragma unroll
        for (int np = 0; np < 4; np++) {
            int r = wn + np * 16 + ((g >> 1) << 3) + rl;
            int c16 = ((r & 1) << 2) + ks * 2 + (g & 1);
            int off = (r >> 1) * 128 + c16 * 16;
            uint32_t sw = (uint32_t)(off ^ ((off >> 3) & 0x70));
            ldsm_x4(bh[np][0], bh[np][1], bh[np][2], bh[np][3], sbuf + 16384 + sw);
            ldsm_x4(bl[np][0], bl[np][1], bl[np][2], bl[np][3], sbuf + 24576 + sw);
        }
#pragma unroll
        for (int mb = 0; mb < 2; mb++)
#pragma unroll
            for (int j = 0; j < 8; j++) {
                MMA16816(acc[mb][j], ah[mb], &bh[j >> 1][(j & 1) * 2]);
                MMA16816(acc[mb][j], ah[mb], &bl[j >> 1][(j & 1) * 2]);
                MMA16816(acc[mb][j], al[mb], &bh[j >> 1][(j & 1) * 2]);
            }
    }
}

// ---------------- fused QKV projection (bf16 hi/lo out) ---------------------
__global__ void __launch_bounds__(256, 2) gemm_qkv() {
    extern __shared__ char smem[];
    const uint32_t sbase = smem_u32(smem);
    const int tid = threadIdx.x, wid = tid >> 5, lane = tid & 31;
    const int nt = blockIdx.x;
    const int bm = blockIdx.y * 128;
    const int wm = (wid & 3) * 32;
    const int wn = (wid >> 2) * 64;
    const int g = lane >> 3, rl = lane & 7;
    const int K = D_;

    const __nv_bfloat16 *Ah = g_xh, *Al = g_xl, *Bh, *Bl;
    __nv_bfloat16 *Oh, *Ol;
    int N, bn;
    if (nt < 16)      { Bh = g_wqh; Bl = g_wql; Oh = g_qh; Ol = g_ql; N = QKDIM; bn = nt * 128; }
    else if (nt < 32) { Bh = g_wkh; Bl = g_wkl; Oh = g_kh; Ol = g_kl; N = QKDIM; bn = (nt - 16) * 128; }
    else              { Bh = g_wvh; Bl = g_wvl; Oh = g_vh; Ol = g_vl; N = H_ * DH_; bn = (nt - 32) * 128; }

    float acc[2][8][4];
#pragma unroll
    for (int a = 0; a < 2; a++)
#pragma unroll
        for (int b = 0; b < 8; b++)
#pragma unroll
            for (int d = 0; d < 4; d++) acc[a][b][d] = 0.f;

    const int nch = K >> 5;
    g_issue(Ah, Al, Bh, Bl, sbase, tid, bm, bn, K, 0);
    g_issue(Ah, Al, Bh, Bl, sbase + GSTAGE, tid, bm, bn, K, 1);

    for (int c = 0; c < nch; c++) {
        if (c + 1 < nch) { CP_WAIT1(); } else { CP_WAIT0(); }
        __syncthreads();
        if (c + 2 < nch)
            g_issue(Ah, Al, Bh, Bl, sbase + (uint32_t)((c + 2) % 3) * GSTAGE, tid, bm, bn, K, c + 2);
        g_chunk(sbase + (uint32_t)(c % 3) * GSTAGE, wm, wn, g, rl, acc);
    }

#pragma unroll
    for (int mb = 0; mb < 2; mb++) {
        int row0 = bm + wm + mb * 16 + (lane >> 2);
#pragma unroll
        for (int j = 0; j < 8; j++) {
            int col = bn + wn + j * 8 + (lane & 3) * 2;
#pragma unroll
            for (int rr = 0; rr < 2; rr++) {
                float v0 = acc[mb][j][rr * 2], v1 = acc[mb][j][rr * 2 + 1];
                __nv_bfloat16 h0 = __float2bfloat16(v0), h1 = __float2bfloat16(v1);
                __nv_bfloat16 l0 = __float2bfloat16(v0 - __bfloat162float(h0));
                __nv_bfloat16 l1 = __float2bfloat16(v1 - __bfloat162float(h1));
                size_t idx = (size_t)(row0 + rr * 8) * N + col;
                __nv_bfloat162 hp; hp.x = h0; hp.y = h1;
                __nv_bfloat162 lp; lp.x = l0; lp.y = l1;
                *(__nv_bfloat162*)&Oh[idx] = hp;
                *(__nv_bfloat162*)&Ol[idx] = lp;
            }
        }
    }
}

// ---------------- output projection (fp32 out) ------------------------------
__global__ void __launch_bounds__(256, 2) gemm_o(
    const __nv_bfloat16* __restrict__ Ah, const __nv_bfloat16* __restrict__ Al,
    const __nv_bfloat16* __restrict__ Bh, const __nv_bfloat16* __restrict__ Bl,
    float* __restrict__ Cf, int M, int N, int K) {
    extern __shared__ char smem[];
    const uint32_t sbase = smem_u32(smem);
    const int tid = threadIdx.x, wid = tid >> 5, lane = tid & 31;
    const int bm = blockIdx.y * 128, bn = blockIdx.x * 128;
    const int wm = (wid & 3) * 32;
    const int wn = (wid >> 2) * 64;
    const int g = lane >> 3, rl = lane & 7;

    float acc[2][8][4];
#pragma unroll
    for (int a = 0; a < 2; a++)
#pragma unroll
        for (int b = 0; b < 8; b++)
#pragma unroll
            for (int d = 0; d < 4; d++) acc[a][b][d] = 0.f;

    const int nch = K >> 5;
    g_issue(Ah, Al, Bh, Bl, sbase, tid, bm, bn, K, 0);
    g_issue(Ah, Al, Bh, Bl, sbase + GSTAGE, tid, bm, bn, K, 1);

    for (int c = 0; c < nch; c++) {
        if (c + 1 < nch) { CP_WAIT1(); } else { CP_WAIT0(); }
        __syncthreads();
        if (c + 2 < nch)
            g_issue(Ah, Al, Bh, Bl, sbase + (uint32_t)((c + 2) % 3) * GSTAGE, tid, bm, bn, K, c + 2);
        g_chunk(sbase + (uint32_t)(c % 3) * GSTAGE, wm, wn, g, rl, acc);
    }

#pragma unroll
    for (int mb = 0; mb < 2; mb++) {
        int row0 = bm + wm + mb * 16 + (lane >> 2);
#pragma unroll
        for (int j = 0; j < 8; j++) {
            int col = bn + wn + j * 8 + (lane & 3) * 2;
            *(float2*)&Cf[(size_t)row0 * N + col]       = make_float2(acc[mb][j][0], acc[mb][j][1]);
            *(float2*)&Cf[(size_t)(row0 + 8) * N + col] = make_float2(acc[mb][j][2], acc[mb][j][3]);
        }
    }
}

// ---------------- flash attention: 4 warps, 64-q tiles, 2 CTAs/SM -----------
// grid (32, B*H*2) = 2048 CTAs, 128 threads. 3-stage 64-key pipeline;
// Q staging overlays stage 2 (consumed into regs at kt=0).
#define FSTG_SZ 33024
#define FK_H 0
#define FK_L 8192
#define FV_H 16384
#define FV_L 24576
#define FAM  32768
#define FQ_H (2 * FSTG_SZ)
#define FQ_L (2 * FSTG_SZ + 8192)
#define FL_SMEM (3 * FSTG_SZ)   // 99072

__device__ __forceinline__ void f_issue_stage(uint32_t stg, int tid, int b, int h, int comp,
                                              int kt, const float* __restrict__ amask) {
    const char* Khg = (const char*)(g_kh + ((size_t)(b * S_) + kt * 64) * QKDIM + h * 128 + comp * 64);
    const char* Klg = (const char*)(g_kl + ((size_t)(b * S_) + kt * 64) * QKDIM + h * 128 + comp * 64);
    const char* Vhg = (const char*)(g_vh + ((size_t)(b * S_) + kt * 64) * (H_ * DH_) + h * 64);
    const char* Vlg = (const char*)(g_vl + ((size_t)(b * S_) + kt * 64) * (H_ * DH_) + h * 64);
#pragma unroll
    for (int i = 0; i < 4; i++) {
        int t = tid + i * 128;              // 0..511 : row(0..63) x gran(0..7)
        int row = t >> 3, gr = t & 7;
        int off = row * 128 + gr * 16;
        uint32_t sw = (uint32_t)(off ^ ((off >> 3) & 0x70));
        CP16(stg + FK_H + sw, Khg + (size_t)row * (QKDIM * 2) + gr * 16);
        CP16(stg + FK_L + sw, Klg + (size_t)row * (QKDIM * 2) + gr * 16);
        CP16(stg + FV_H + sw, Vhg + (size_t)row * (H_ * DH_ * 2) + gr * 16);
        CP16(stg + FV_L + sw, Vlg + (size_t)row * (H_ * DH_ * 2) + gr * 16);
    }
    if (tid < 16)
        CP16(stg + FAM + tid * 16, amask + b * S_ + kt * 64 + tid * 4);
    CP_COMMIT();
}

__global__ void __launch_bounds__(128) flashmma_kernel(const float* __restrict__ amask) {
    extern __shared__ char fsm[];
    const uint32_t sb = smem_u32(fsm);
    const int tid = threadIdx.x, wid = tid >> 5, lane = tid & 31;
    const int g = lane >> 3, rl = lane & 7;
    const int qt = (gridDim.x - 1) - blockIdx.x;
    const int z = blockIdx.y;
    const int comp = z & 1;
    const int bh = z >> 1;
    const int b = bh / H_, h = bh % H_;
    const float slope = exp2f(-8.0f * (float)(h + 1) / (float)H_);
    const float scale = 0.125f;
    const int nkt = qt + 1;

    // ---- prologue: Q (hi/lo) into FQ region, grouped with stage 0 ----
    {
        const char* Qhg = (const char*)(g_qh + ((size_t)(b * S_) + qt * 64) * QKDIM + h * 128 + comp * 64);
        const char* Qlg = (const char*)(g_ql + ((size_t)(b * S_) + qt * 64) * QKDIM + h * 128 + comp * 64);
#pragma unroll
        for (int i = 0; i < 4; i++) {
            int t = tid + i * 128;          // 0..511 : row(0..63) x gran(0..7)
            int row = t >> 3, gr = t & 7;
            int off = row * 128 + gr * 16;
            uint32_t sw = (uint32_t)(off ^ ((off >> 3) & 0x70));
            CP16(sb + FQ_H + sw, Qhg + (size_t)row * (QKDIM * 2) + gr * 16);
            CP16(sb + FQ_L + sw, Qlg + (size_t)row * (QKDIM * 2) + gr * 16);
        }
    }
    f_issue_stage(sb, tid, b, h, comp, 0, amask);            // commit: group {Q, stage0}
    if (nkt > 1) f_issue_stage(sb + FSTG_SZ, tid, b, h, comp, 1, amask);

    float oa[8][4];
#pragma unroll
    for (int j = 0; j < 8; j++)
#pragma unroll
        for (int d = 0; d < 4; d++) oa[j][d] = 0.f;
    float m0 = -1e30f, m1 = -1e30f, l0 = 0.f, l1 = 0.f;
    uint32_t qAh[4][4], qAl[4][4];

    const int qr0 = qt * 64 + wid * 16 + (lane >> 2);

    for (int kt = 0; kt < nkt; kt++) {
        if (kt + 1 < nkt) { CP_WAIT1(); } else { CP_WAIT0(); }
        __syncthreads();
        if (kt == 0) {
            // hoist Q fragments to registers (once); Q region is reused as stage 2
#pragma unroll
            for (int kb = 0; kb < 4; kb++) {
                int row = wid * 16 + ((g & 1) << 3) + rl;
                int gr = kb * 2 + (g >> 1);
                int off = row * 128 + gr * 16;
                uint32_t sw = (uint32_t)(off ^ ((off >> 3) & 0x70));
                ldsm_x4(qAh[kb][0], qAh[kb][1], qAh[kb][2], qAh[kb][3], sb + FQ_H + sw);
                ldsm_x4(qAl[kb][0], qAl[kb][1], qAl[kb][2], qAl[kb][3], sb + FQ_L + sw);
            }
            if (nkt > 2) __syncthreads();   // all warps done reading Q before stage2 write
        }
        if (kt + 2 < nkt)
            f_issue_stage(sb + (uint32_t)((kt + 2) % 3) * FSTG_SZ, tid, b, h, comp, kt + 2, amask);
        uint32_t stg = sb + (uint32_t)(kt % 3) * FSTG_SZ;

        // ---- S = Q K^T (x3 split), 64 keys ----
        float sa[8][4];
#pragma unroll
        for (int j = 0; j < 8; j++)
#pragma unroll
            for (int d = 0; d < 4; d++) sa[j][d] = 0.f;
#pragma unroll
        for (int kb = 0; kb < 4; kb++) {
#pragma unroll
            for (int nb2 = 0; nb2 < 4; nb2++) {
                uint32_t kh4[4], kl4[4];
                int row = nb2 * 16 + ((g >> 1) << 3) + rl;
                int gr = kb * 2 + (g & 1);
                int off = row * 128 + gr * 16;
                uint32_t sw = (uint32_t)(off ^ ((off >> 3) & 0x70));
                ldsm_x4(kh4[0], kh4[1], kh4[2], kh4[3], stg + FK_H + sw);
                ldsm_x4(kl4[0], kl4[1], kl4[2], kl4[3], stg + FK_L + sw);
                MMA16816(sa[nb2 * 2], qAh[kb], &kh4[0]);
                MMA16816(sa[nb2 * 2], qAh[kb], &kl4[0]);
                MMA16816(sa[nb2 * 2], qAl[kb], &kh4[0]);
                MMA16816(sa[nb2 * 2 + 1], qAh[kb], &kh4[2]);
                MMA16816(sa[nb2 * 2 + 1], qAh[kb], &kl4[2]);
                MMA16816(sa[nb2 * 2 + 1], qAl[kb], &kh4[2]);
            }
        }

        // ---- bias + masks ----
        const float* ams = (const float*)(fsm + (stg - sb) + FAM);
        const int kcb = kt * 64;
#pragma unroll
        for (int nb = 0; nb < 8; nb++) {
            int kc = nb * 8 + (lane & 3) * 2;
            float a0 = (1.0f - ams[kc]) * NEGV;
            float a1 = (1.0f - ams[kc + 1]) * NEGV;
            int k0 = kcb + kc, k1 = k0 + 1;
            float b00 = a0 - slope * (float)(qr0 - k0) + ((k0 > qr0) ? NEGV : 0.f);
            float b01 = a1 - slope * (float)(qr0 - k1) + ((k1 > qr0) ? NEGV : 0.f);
            float b10 = a0 - slope * (float)(qr0 + 8 - k0) + ((k0 > qr0 + 8) ? NEGV : 0.f);
            float b11 = a1 - slope * (float)(qr0 + 8 - k1) + ((k1 > qr0 + 8) ? NEGV : 0.f);
            sa[nb][0] = sa[nb][0] * scale + b00;
            sa[nb][1] = sa[nb][1] * scale + b01;
            sa[nb][2] = sa[nb][2] * scale + b10;
            sa[nb][3] = sa[nb][3] * scale + b11;
        }

        // ---- online softmax ----
        float mx0 = -1e30f, mx1 = -1e30f;
#pragma unroll
        for (int nb = 0; nb < 8; nb++) {
            mx0 = fmaxf(mx0, fmaxf(sa[nb][0], sa[nb][1]));
            mx1 = fmaxf(mx1, fmaxf(sa[nb][2], sa[nb][3]));
        }
        mx0 = fmaxf(mx0, __shfl_xor_sync(0xffffffffu, mx0, 1));
        mx0 = fmaxf(mx0, __shfl_xor_sync(0xffffffffu, mx0, 2));
        mx1 = fmaxf(mx1, __shfl_xor_sync(0xffffffffu, mx1, 1));
        mx1 = fmaxf(mx1, __shfl_xor_sync(0xffffffffu, mx1, 2));
        float mn0 = fmaxf(m0, mx0), mn1 = fmaxf(m1, mx1);
        float al0 = __expf(m0 - mn0), al1 = __expf(m1 - mn1);
        m0 = mn0; m1 = mn1;
        float ls0 = 0.f, ls1 = 0.f;
#pragma unroll
        for (int nb = 0; nb < 8; nb++) {
            sa[nb][0] = __expf(sa[nb][0] - mn0);
            sa[nb][1] = __expf(sa[nb][1] - mn0);
            sa[nb][2] = __expf(sa[nb][2] - mn1);
            sa[nb][3] = __expf(sa[nb][3] - mn1);
            ls0 += sa[nb][0] + sa[nb][1];
            ls1 += sa[nb][2] + sa[nb][3];
        }
        ls0 += __shfl_xor_sync(0xffffffffu, ls0, 1);
        ls0 += __shfl_xor_sync(0xffffffffu, ls0, 2);
        ls1 += __shfl_xor_sync(0xffffffffu, ls1, 1);
        ls1 += __shfl_xor_sync(0xffffffffu, ls1, 2);
        l0 = l0 * al0 + ls0;
        l1 = l1 * al1 + ls1;

#pragma unroll
        for (int j = 0; j < 8; j++) {
            oa[j][0] *= al0; oa[j][1] *= al0;
            oa[j][2] *= al1; oa[j][3] *= al1;
        }

        // ---- O += P V (x3 split); P packed per key-block inside the loop ----
#pragma unroll
        for (int kb2 = 0; kb2 < 4; kb2++) {
            uint32_t pAh[4], pAl[4];
#pragma unroll
            for (int half = 0; half < 2; half++) {
                float v0a = sa[kb2 * 2][half * 2], v1a = sa[kb2 * 2][half * 2 + 1];
                float v0b = sa[kb2 * 2 + 1][half * 2], v1b = sa[kb2 * 2 + 1][half * 2 + 1];
                __nv_bfloat16 h0a = __float2bfloat16(v0a), h1a = __float2bfloat16(v1a);
                __nv_bfloat16 h0b = __float2bfloat16(v0b), h1b = __float2bfloat16(v1b);
                pAh[half]     = pack_bf2(__bfloat162float(h0a), __bfloat162float(h1a));
                pAh[2 + half] = pack_bf2(__bfloat162float(h0b), __bfloat162float(h1b));
                pAl[half]     = pack_bf2(v0a - __bfloat162float(h0a), v1a - __bfloat162float(h1a));
                pAl[2 + half] = pack_bf2(v0b - __bfloat162float(h0b), v1b - __bfloat162float(h1b));
            }
#pragma unroll
            for (int db = 0; db < 4; db++) {
                uint32_t vh4[4], vl4[4];
                int row = kb2 * 16 + ((g & 1) << 3) + rl;
                int gr = db * 2 + (g >> 1);
                int off = row * 128 + gr * 16;
                uint32_t sw = (uint32_t)(off ^ ((off >> 3) & 0x70));
                ldsm_x4t(vh4[0], vh4[1], vh4[2], vh4[3], stg + FV_H + sw);
                ldsm_x4t(vl4[0], vl4[1], vl4[2], vl4[3], stg + FV_L + sw);
                MMA16816(oa[db * 2], pAh, &vh4[0]);
                MMA16816(oa[db * 2], pAh, &vl4[0]);
                MMA16816(oa[db * 2], pAl, &vh4[0]);
                MMA16816(oa[db * 2 + 1], pAh, &vh4[2]);
                MMA16816(oa[db * 2 + 1], pAh, &vl4[2]);
                MMA16816(oa[db * 2 + 1], pAl, &vh4[2]);
            }
        }
    }

    // ---- epilogue ----
    float inv0 = 1.0f / l0, inv1 = 1.0f / l1;
    float* Og = (comp ? g_o2 : g_o1) + ((size_t)(b * S_) + qr0) * (H_ * DH_) + h * 64;
#pragma unroll
    for (int j = 0; j < 8; j++) {
        int col = j * 8 + (lane & 3) * 2;
        *(float2*)&Og[col] = make_float2(oa[j][0] * inv0, oa[j][1] * inv0);
        *(float2*)&Og[(size_t)8 * (H_ * DH_) + col] = make_float2(oa[j][2] * inv1, oa[j][3] * inv1);
    }
}

// ---------------- combine + groupnorm stats ---------------------------------
__global__ void __launch_bounds__(256) combine_stats_kernel() {
    const int bh = blockIdx.x >> 3;
    const int slice = blockIdx.x & 7;
    const int b = bh / H_, h = bh % H_;
    const float lam = g_lambda;
    double s = 0.0, ss = 0.0;
    const int base_row = b * S_ + slice * 256;
    for (int f = threadIdx.x; f < 256 * (DH_ / 4); f += 256) {
        int row = f >> 4, c = (f & 15) * 4;
        size_t e = (size_t)(base_row + row) * (H_ * DH_) + h * DH_ + c;
        float4 a = *(const float4*)&g_o1[e];
        float4 cc = *(const float4*)&g_o2[e];
        float4 y;
        y.x = a.x - lam * cc.x; y.y = a.y - lam * cc.y;
        y.z = a.z - lam * cc.z; y.w = a.w - lam * cc.w;
        *(float4*)&g_o[e] = y;
        s += (double)y.x + y.y + y.z + y.w;
        ss += (double)y.x * y.x + (double)y.y * y.y + (double)y.z * y.z + (double)y.w * y.w;
    }
    __shared__ double sh_s[256], sh_ss[256];
    sh_s[threadIdx.x] = s; sh_ss[threadIdx.x] = ss;
    __syncthreads();
    for (int st = 128; st > 0; st >>= 1) {
        if (threadIdx.x < st) {
            sh_s[threadIdx.x] += sh_s[threadIdx.x + st];
            sh_ss[threadIdx.x] += sh_ss[threadIdx.x + st];
        }
        __syncthreads();
    }
    if (threadIdx.x == 0) {
        atomicAdd(&g_sum[bh], sh_s[0]);
        atomicAdd(&g_sumsq[bh], sh_ss[0]);
    }
}

// ---------------- normalize + emit bf16 hi/lo -------------------------------
__global__ void __launch_bounds__(256) gn_apply_kernel(const float* __restrict__ gamma,
                                                       const float* __restrict__ beta) {
    int f = blockIdx.x * blockDim.x + threadIdx.x;
    if (f >= (B_ * S_ * H_ * DH_) / 4) return;
    int e = f * 4;
    int c = e % (H_ * DH_);
    int row = e / (H_ * DH_);
    int b = row / S_;
    int h = c / DH_;
    const double n = (double)S_ * DH_;
    double sm = g_sum[b * H_ + h], sq = g_sumsq[b * H_ + h];
    double meand = sm / n;
    float mean = (float)meand;
    float inv = rsqrtf((float)(sq / n - meand * meand) + EPS_);
    float4 x = *(const float4*)&g_o[e];
    float4 gm = *(const float4*)&gamma[c];
    float4 bt = *(const float4*)&beta[c];
    const float post = 1.0f - LAMBDA_INIT;
    float y[4];
    y[0] = ((x.x - mean) * inv * gm.x + bt.x) * post;
    y[1] = ((x.y - mean) * inv * gm.y + bt.y) * post;
    y[2] = ((x.z - mean) * inv * gm.z + bt.z) * post;
    y[3] = ((x.w - mean) * inv * gm.w + bt.w) * post;
    __nv_bfloat16 hh[4], ll[4];
#pragma unroll
    for (int j = 0; j < 4; j++) {
        hh[j] = __float2bfloat16(y[j]);
        ll[j] = __float2bfloat16(y[j] - __bfloat162float(hh[j]));
    }
    *(uint2*)&g_nh[e] = *(uint2*)hh;
    *(uint2*)&g_nl[e] = *(uint2*)ll;
}

// ---------------- launch ----------------------------------------------------
extern "C" void kernel_launch(void* const* d_in, const int* in_sizes, int n_in,
                              void* d_out, int out_size) {
    const float* x     = (const float*)d_in[0];
    const float* amask = (const float*)d_in[1];
    const float* Wq = (const float*)d_in[3];
    const float* Wk = (const float*)d_in[4];
    const float* Wv = (const float*)d_in[5];
    const float* Wo = (const float*)d_in[6];
    const float* lq1 = (const float*)d_in[7];
    const float* lq2 = (const float*)d_in[8];
    const float* lk1 = (const float*)d_in[9];
    const float* lk2 = (const float*)d_in[10];
    const float* gam = (const float*)d_in[11];
    const float* bet = (const float*)d_in[12];
    float* out = (float*)d_out;

    __nv_bfloat16 *woh, *wol, *nh, *nl;
    cudaGetSymbolAddress((void**)&woh, g_woh); cudaGetSymbolAddress((void**)&wol, g_wol);
    cudaGetSymbolAddress((void**)&nh, g_nh);   cudaGetSymbolAddress((void**)&nl, g_nl);

    const int M = B_ * S_;  // 4096

    // 0: lambda + zero stats
    lam_kernel<<<1, 1>>>(lq1, lq2, lk1, lk2);
    // 1: all fp32->bf16 hi/lo splits
    cvt_all<<<N4_TOT / 256, 256>>>(x, Wq, Wk, Wv, Wo);
    // 2: fused QKV projection
    cudaFuncSetAttribute(gemm_qkv, cudaFuncAttributeMaxDynamicSharedMemorySize, G_SMEM);
    gemm_qkv<<<dim3(40, M / 128), 256, G_SMEM>>>();
    // 3: flash attention (profiled)
    cudaFuncSetAttribute(flashmma_kernel, cudaFuncAttributeMaxDynamicSharedMemorySize, FL_SMEM);
    flashmma_kernel<<<dim3(S_ / 64, B_ * H_ * 2), 128, FL_SMEM>>>(amask);
    // 4: combine + stats
    combine_stats_kernel<<<B_ * H_ * 8, 256>>>();
    // 5: normalize + split
    gn_apply_kernel<<<(B_ * S_ * H_ * DH_ / 4 + 255) / 256, 256>>>(gam, bet);
    // 6: output projection
    cudaFuncSetAttribute(gemm_o, cudaFuncAttributeMaxDynamicSharedMemorySize, G_SMEM);
    gemm_o<<<dim3(D_ / 128, M / 128), 256, G_SMEM>>>(nh, nl, woh, wol, out, M, D_, H_ * DH_);
}

// round 11
// speedup vs baseline: 8.6237x; 1.0654x over previous
#include <cuda_runtime.h>
#include <cuda_bf16.h>
#include <math.h>
#include <cstdint>

#define B_  2
#define S_  2048
#define D_  1024
#define H_  16
#define DH_ 64
#define QKDIM 2048
#define NEGV (-1000000000.0f)
#define LOG2E 1.44269504f
#define NEGV2 (-1.44269504e9f)
#define LAMBDA_INIT 0.8f
#define EPS_ 1e-5f

// ---------------- scratch (device globals) ---------------------------------
__device__ float g_o1[(size_t)B_ * S_ * H_ * DH_];
__device__ float g_o2[(size_t)B_ * S_ * H_ * DH_];
__device__ float g_o [(size_t)B_ * S_ * H_ * DH_];
__device__ float g_lambda;
__device__ double g_sum[B_ * H_], g_sumsq[B_ * H_];

// bf16 split buffers
__device__ __nv_bfloat16 g_xh[(size_t)B_ * S_ * D_], g_xl[(size_t)B_ * S_ * D_];
__device__ __nv_bfloat16 g_wqh[QKDIM * D_], g_wql[QKDIM * D_];
__device__ __nv_bfloat16 g_wkh[QKDIM * D_], g_wkl[QKDIM * D_];
__device__ __nv_bfloat16 g_wvh[(H_ * DH_) * D_], g_wvl[(H_ * DH_) * D_];
__device__ __nv_bfloat16 g_woh[D_ * (H_ * DH_)], g_wol[D_ * (H_ * DH_)];
__device__ __nv_bfloat16 g_nh[(size_t)B_ * S_ * H_ * DH_], g_nl[(size_t)B_ * S_ * H_ * DH_];
__device__ __nv_bfloat16 g_qh[(size_t)B_ * S_ * QKDIM], g_ql[(size_t)B_ * S_ * QKDIM];
__device__ __nv_bfloat16 g_kh[(size_t)B_ * S_ * QKDIM], g_kl[(size_t)B_ * S_ * QKDIM];
__device__ __nv_bfloat16 g_vh[(size_t)B_ * S_ * H_ * DH_], g_vl[(size_t)B_ * S_ * H_ * DH_];

// ---------------- helpers ---------------------------------------------------
__device__ __forceinline__ uint32_t smem_u32(const void* p) {
    uint32_t a;
    asm("{ .reg .u64 t; cvta.to.shared.u64 t, %1; cvt.u32.u64 %0, t; }" : "=r"(a) : "l"(p));
    return a;
}
__device__ __forceinline__ float fast_exp2(float x) {
    float r;
    asm("ex2.approx.ftz.f32 %0, %1;" : "=f"(r) : "f"(x));
    return r;
}
#define CP16(dst, src) \
    asm volatile("cp.async.cg.shared.global [%0], [%1], 16;" :: "r"(dst), "l"(src) : "memory")
#define CP_COMMIT() asm volatile("cp.async.commit_group;" ::: "memory")
#define CP_WAIT1()  asm volatile("cp.async.wait_group 1;" ::: "memory")
#define CP_WAIT0()  asm volatile("cp.async.wait_group 0;" ::: "memory")

__device__ __forceinline__ void ldsm_x4(uint32_t& r0, uint32_t& r1, uint32_t& r2, uint32_t& r3,
                                        uint32_t addr) {
    asm volatile("ldmatrix.sync.aligned.m8n8.x4.shared.b16 {%0,%1,%2,%3}, [%4];"
                 : "=r"(r0), "=r"(r1), "=r"(r2), "=r"(r3) : "r"(addr));
}
__device__ __forceinline__ void ldsm_x4t(uint32_t& r0, uint32_t& r1, uint32_t& r2, uint32_t& r3,
                                         uint32_t addr) {
    asm volatile("ldmatrix.sync.aligned.m8n8.x4.trans.shared.b16 {%0,%1,%2,%3}, [%4];"
                 : "=r"(r0), "=r"(r1), "=r"(r2), "=r"(r3) : "r"(addr));
}
#define MMA16816(d, a, b) \
    asm volatile("mma.sync.aligned.m16n8k16.row.col.f32.bf16.bf16.f32 " \
                 "{%0,%1,%2,%3}, {%4,%5,%6,%7}, {%8,%9}, {%0,%1,%2,%3};" \
                 : "+f"((d)[0]), "+f"((d)[1]), "+f"((d)[2]), "+f"((d)[3]) \
                 : "r"((a)[0]), "r"((a)[1]), "r"((a)[2]), "r"((a)[3]), \
                   "r"((b)[0]), "r"((b)[1]))

__device__ __forceinline__ uint32_t pack_bf2(float lo, float hi) {
    __nv_bfloat162 t = __floats2bfloat162_rn(lo, hi);
    return *(uint32_t*)&t;
}

// ---------------- lambda + zero stats ---------------------------------------
__global__ void lam_kernel(const float* __restrict__ lq1, const float* __restrict__ lq2,
                           const float* __restrict__ lk1, const float* __restrict__ lk2) {
    float d1 = 0.f, d2 = 0.f;
    for (int i = 0; i < DH_; i++) { d1 += lq1[i] * lk1[i]; d2 += lq2[i] * lk2[i]; }
    g_lambda = expf(d1) - expf(d2) + LAMBDA_INIT;
    for (int i = 0; i < B_ * H_; i++) { g_sum[i] = 0.0; g_sumsq[i] = 0.0; }
}

// ---------------- fused fp32 -> bf16 hi/lo split of all operands ------------
#define N4_X  (B_ * S_ * D_ / 4)
#define N4_WQ (QKDIM * D_ / 4)
#define N4_WV (H_ * DH_ * D_ / 4)
#define N4_TOT (N4_X + 2 * N4_WQ + 2 * N4_WV)

__device__ __forceinline__ void split4(const float* src, __nv_bfloat16* h, __nv_bfloat16* l,
                                       size_t i) {
    float4 v = ((const float4*)src)[i];
    float vv[4] = {v.x, v.y, v.z, v.w};
    __nv_bfloat16 hh[4], ll[4];
#pragma unroll
    for (int j = 0; j < 4; j++) {
        hh[j] = __float2bfloat16(vv[j]);
        ll[j] = __float2bfloat16(vv[j] - __bfloat162float(hh[j]));
    }
    *(uint2*)&h[i * 4] = *(uint2*)hh;
    *(uint2*)&l[i * 4] = *(uint2*)ll;
}

__global__ void __launch_bounds__(256) cvt_all(
    const float* __restrict__ x,  const float* __restrict__ Wq,
    const float* __restrict__ Wk, const float* __restrict__ Wv,
    const float* __restrict__ Wo) {
    int i = blockIdx.x * 256 + threadIdx.x;
    if (i < N4_X) { split4(x, g_xh, g_xl, i); return; }
    i -= N4_X;
    if (i < N4_WQ) { split4(Wq, g_wqh, g_wql, i); return; }
    i -= N4_WQ;
    if (i < N4_WQ) { split4(Wk, g_wkh, g_wkl, i); return; }
    i -= N4_WQ;
    if (i < N4_WV) { split4(Wv, g_wvh, g_wvl, i); return; }
    i -= N4_WV;
    if (i < N4_WV) { split4(Wo, g_woh, g_wol, i); return; }
}

// ---------------- GEMM stage loader -----------------------------------------
#define GSTAGE 32768
#define G_SMEM (3 * GSTAGE)

__device__ __forceinline__ void g_issue(
    const __nv_bfloat16* __restrict__ Ah, const __nv_bfloat16* __restrict__ Al,
    const __nv_bfloat16* __restrict__ Bh, const __nv_bfloat16* __restrict__ Bl,
    uint32_t sbuf, int tid, int bm, int bn, int K, int c) {
#pragma unroll
    for (int i = 0; i < 2; i++) {
        int ch = tid + i * 256;
        int p = ch >> 3, c16 = ch & 7;
        int r = (p << 1) + (c16 >> 2);
        int kb = (c16 & 3) * 8;
        int off = p * 128 + c16 * 16;
        uint32_t dst = sbuf + (off ^ ((off >> 3) & 0x70));
        size_t ga = (size_t)(bm + r) * K + c * 32 + kb;
        size_t gb = (size_t)(bn + r) * K + c * 32 + kb;
        CP16(dst,         Ah + ga);
        CP16(dst + 8192,  Al + ga);
        CP16(dst + 16384, Bh + gb);
        CP16(dst + 24576, Bl + gb);
    }
    CP_COMMIT();
}

__device__ __forceinline__ void g_chunk(uint32_t sbuf, int wm, int wn, int g, int rl,
                                        float acc[2][8][4]) {
#pragma unroll
    for (int ks = 0; ks < 2; ks++) {
        uint32_t ah[2][4], al[2][4];
#pragma unroll
        for (int mb = 0; mb < 2; mb++) {
            int r = wm + mb * 16 + ((g & 1) << 3) + rl;
            int c16 = ((r & 1) << 2) + ks * 2 + (g >> 1);
            int off = (r >> 1) * 128 + c16 * 16;
            uint32_t sw = (uint32_t)(off ^ ((off >> 3) & 0x70));
            ldsm_x4(ah[mb][0], ah[mb][1], ah[mb][2], ah[mb][3], sbuf + sw);
            ldsm_x4(al[mb][0], al[mb][1], al[mb][2], al[mb][3], sbuf + 8192 + sw);
        }
        uint32_t bh[4][4], bl[4][4];
#pragma unroll
        for (int np = 0; np < 4; np++) {
            int r = wn + np * 16 + ((g >> 1) << 3) + rl;
            int c16 = ((r & 1) << 2) + ks * 2 + (g & 1);
            int off = (r >> 1) * 128 + c16 * 16;
            uint32_t sw = (uint32_t)(off ^ ((off >> 3) & 0x70));
            ldsm_x4(bh[np][0], bh[np][1], bh[np][2], bh[np][3], sbuf + 16384 + sw);
            ldsm_x4(bl[np][0], bl[np][1], bl[np][2], bl[np][3], sbuf + 24576 + sw);
        }
#pragma unroll
        for (int mb = 0; mb < 2; mb++)
#pragma unroll
            for (int j = 0; j < 8; j++) {
                MMA16816(acc[mb][j], ah[mb], &bh[j >> 1][(j & 1) * 2]);
                MMA16816(acc[mb][j], ah[mb], &bl[j >> 1][(j & 1) * 2]);
                MMA16816(acc[mb][j], al[mb], &bh[j >> 1][(j & 1) * 2]);
            }
    }
}

// ---------------- fused QKV projection (bf16 hi/lo out) ---------------------
__global__ void __launch_bounds__(256, 2) gemm_qkv() {
    extern __shared__ char smem[];
    const uint32_t sbase = smem_u32(smem);
    const int tid = threadIdx.x, wid = tid >> 5, lane = tid & 31;
    const int nt = blockIdx.x;
    const int bm = blockIdx.y * 128;
    const int wm = (wid & 3) * 32;
    const int wn = (wid >> 2) * 64;
    const int g = lane >> 3, rl = lane & 7;
    const int K = D_;

    const __nv_bfloat16 *Ah = g_xh, *Al = g_xl, *Bh, *Bl;
    __nv_bfloat16 *Oh, *Ol;
    int N, bn;
    if (nt < 16)      { Bh = g_wqh; Bl = g_wql; Oh = g_qh; Ol = g_ql; N = QKDIM; bn = nt * 128; }
    else if (nt < 32) { Bh = g_wkh; Bl = g_wkl; Oh = g_kh; Ol = g_kl; N = QKDIM; bn = (nt - 16) * 128; }
    else              { Bh = g_wvh; Bl = g_wvl; Oh = g_vh; Ol = g_vl; N = H_ * DH_; bn = (nt - 32) * 128; }

    float acc[2][8][4];
#pragma unroll
    for (int a = 0; a < 2; a++)
#pragma unroll
        for (int b = 0; b < 8; b++)
#pragma unroll
            for (int d = 0; d < 4; d++) acc[a][b][d] = 0.f;

    const int nch = K >> 5;
    g_issue(Ah, Al, Bh, Bl, sbase, tid, bm, bn, K, 0);
    g_issue(Ah, Al, Bh, Bl, sbase + GSTAGE, tid, bm, bn, K, 1);

    for (int c = 0; c < nch; c++) {
        if (c + 1 < nch) { CP_WAIT1(); } else { CP_WAIT0(); }
        __syncthreads();
        if (c + 2 < nch)
            g_issue(Ah, Al, Bh, Bl, sbase + (uint32_t)((c + 2) % 3) * GSTAGE, tid, bm, bn, K, c + 2);
        g_chunk(sbase + (uint32_t)(c % 3) * GSTAGE, wm, wn, g, rl, acc);
    }

#pragma unroll
    for (int mb = 0; mb < 2; mb++) {
        int row0 = bm + wm + mb * 16 + (lane >> 2);
#pragma unroll
        for (int j = 0; j < 8; j++) {
            int col = bn + wn + j * 8 + (lane & 3) * 2;
#pragma unroll
            for (int rr = 0; rr < 2; rr++) {
                float v0 = acc[mb][j][rr * 2], v1 = acc[mb][j][rr * 2 + 1];
                __nv_bfloat16 h0 = __float2bfloat16(v0), h1 = __float2bfloat16(v1);
                __nv_bfloat16 l0 = __float2bfloat16(v0 - __bfloat162float(h0));
                __nv_bfloat16 l1 = __float2bfloat16(v1 - __bfloat162float(h1));
                size_t idx = (size_t)(row0 + rr * 8) * N + col;
                __nv_bfloat162 hp; hp.x = h0; hp.y = h1;
                __nv_bfloat162 lp; lp.x = l0; lp.y = l1;
                *(__nv_bfloat162*)&Oh[idx] = hp;
                *(__nv_bfloat162*)&Ol[idx] = lp;
            }
        }
    }
}

// ---------------- output projection (fp32 out) ------------------------------
__global__ void __launch_bounds__(256, 2) gemm_o(
    const __nv_bfloat16* __restrict__ Ah, const __nv_bfloat16* __restrict__ Al,
    const __nv_bfloat16* __restrict__ Bh, const __nv_bfloat16* __restrict__ Bl,
    float* __restrict__ Cf, int M, int N, int K) {
    extern __shared__ char smem[];
    const uint32_t sbase = smem_u32(smem);
    const int tid = threadIdx.x, wid = tid >> 5, lane = tid & 31;
    const int bm = blockIdx.y * 128, bn = blockIdx.x * 128;
    const int wm = (wid & 3) * 32;
    const int wn = (wid >> 2) * 64;
    const int g = lane >> 3, rl = lane & 7;

    float acc[2][8][4];
#pragma unroll
    for (int a = 0; a < 2; a++)
#pragma unroll
        for (int b = 0; b < 8; b++)
#pragma unroll
            for (int d = 0; d < 4; d++) acc[a][b][d] = 0.f;

    const int nch = K >> 5;
    g_issue(Ah, Al, Bh, Bl, sbase, tid, bm, bn, K, 0);
    g_issue(Ah, Al, Bh, Bl, sbase + GSTAGE, tid, bm, bn, K, 1);

    for (int c = 0; c < nch; c++) {
        if (c + 1 < nch) { CP_WAIT1(); } else { CP_WAIT0(); }
        __syncthreads();
        if (c + 2 < nch)
            g_issue(Ah, Al, Bh, Bl, sbase + (uint32_t)((c + 2) % 3) * GSTAGE, tid, bm, bn, K, c + 2);
        g_chunk(sbase + (uint32_t)(c % 3) * GSTAGE, wm, wn, g, rl, acc);
    }

#pragma unroll
    for (int mb = 0; mb < 2; mb++) {
        int row0 = bm + wm + mb * 16 + (lane >> 2);
#pragma unroll
        for (int j = 0; j < 8; j++) {
            int col = bn + wn + j * 8 + (lane & 3) * 2;
            *(float2*)&Cf[(size_t)row0 * N + col]       = make_float2(acc[mb][j][0], acc[mb][j][1]);
            *(float2*)&Cf[(size_t)(row0 + 8) * N + col] = make_float2(acc[mb][j][2], acc[mb][j][3]);
        }
    }
}

// ---------------- flash attention: 4 warps, 64-q tiles, 2 CTAs/SM -----------
// Reversed key order (diagonal tile first), base-2 softmax, lane-local l sums.
#define FSTG_SZ 33024
#define FK_H 0
#define FK_L 8192
#define FV_H 16384
#define FV_L 24576
#define FAM  32768
#define FQ_H (2 * FSTG_SZ)
#define FQ_L (2 * FSTG_SZ + 8192)
#define FL_SMEM (3 * FSTG_SZ)   // 99072

__device__ __forceinline__ void f_issue_stage(uint32_t stg, int tid, int b, int h, int comp,
                                              int kt, const float* __restrict__ amask) {
    const char* Khg = (const char*)(g_kh + ((size_t)(b * S_) + kt * 64) * QKDIM + h * 128 + comp * 64);
    const char* Klg = (const char*)(g_kl + ((size_t)(b * S_) + kt * 64) * QKDIM + h * 128 + comp * 64);
    const char* Vhg = (const char*)(g_vh + ((size_t)(b * S_) + kt * 64) * (H_ * DH_) + h * 64);
    const char* Vlg = (const char*)(g_vl + ((size_t)(b * S_) + kt * 64) * (H_ * DH_) + h * 64);
#pragma unroll
    for (int i = 0; i < 4; i++) {
        int t = tid + i * 128;
        int row = t >> 3, gr = t & 7;
        int off = row * 128 + gr * 16;
        uint32_t sw = (uint32_t)(off ^ ((off >> 3) & 0x70));
        CP16(stg + FK_H + sw, Khg + (size_t)row * (QKDIM * 2) + gr * 16);
        CP16(stg + FK_L + sw, Klg + (size_t)row * (QKDIM * 2) + gr * 16);
        CP16(stg + FV_H + sw, Vhg + (size_t)row * (H_ * DH_ * 2) + gr * 16);
        CP16(stg + FV_L + sw, Vlg + (size_t)row * (H_ * DH_ * 2) + gr * 16);
    }
    if (tid < 16)
        CP16(stg + FAM + tid * 16, amask + b * S_ + kt * 64 + tid * 4);
    CP_COMMIT();
}

__global__ void __launch_bounds__(128) flashmma_kernel(const float* __restrict__ amask) {
    extern __shared__ char fsm[];
    const uint32_t sb = smem_u32(fsm);
    const int tid = threadIdx.x, wid = tid >> 5, lane = tid & 31;
    const int g = lane >> 3, rl = lane & 7;
    const int qt = (gridDim.x - 1) - blockIdx.x;
    const int z = blockIdx.y;
    const int comp = z & 1;
    const int bh = z >> 1;
    const int b = bh / H_, h = bh % H_;
    const float slope2 = exp2f(-8.0f * (float)(h + 1) / (float)H_) * LOG2E;
    const float scale2 = 0.125f * LOG2E;
    const int nkt = qt + 1;

    // ---- prologue: Q (hi/lo) into FQ region, grouped with stage 0 ----
    {
        const char* Qhg = (const char*)(g_qh + ((size_t)(b * S_) + qt * 64) * QKDIM + h * 128 + comp * 64);
        const char* Qlg = (const char*)(g_ql + ((size_t)(b * S_) + qt * 64) * QKDIM + h * 128 + comp * 64);
#pragma unroll
        for (int i = 0; i < 4; i++) {
            int t = tid + i * 128;
            int row = t >> 3, gr = t & 7;
            int off = row * 128 + gr * 16;
            uint32_t sw = (uint32_t)(off ^ ((off >> 3) & 0x70));
            CP16(sb + FQ_H + sw, Qhg + (size_t)row * (QKDIM * 2) + gr * 16);
            CP16(sb + FQ_L + sw, Qlg + (size_t)row * (QKDIM * 2) + gr * 16);
        }
    }
    f_issue_stage(sb, tid, b, h, comp, qt, amask);           // it=0 tile (diagonal)
    if (nkt > 1) f_issue_stage(sb + FSTG_SZ, tid, b, h, comp, qt - 1, amask);

    float oa[8][4];
#pragma unroll
    for (int j = 0; j < 8; j++)
#pragma unroll
        for (int d = 0; d < 4; d++) oa[j][d] = 0.f;
    float m0 = -1e30f, m1 = -1e30f, l0 = 0.f, l1 = 0.f;
    uint32_t qAh[4][4], qAl[4][4];

    const int qr0 = qt * 64 + wid * 16 + (lane >> 2);
    const float d8 = -8.0f * slope2;

    // hoisted column constants: slope2 * (col offset within tile)
    float cst0[8], cst1[8];
#pragma unroll
    for (int nb = 0; nb < 8; nb++) {
        cst0[nb] = slope2 * (float)(nb * 8 + (lane & 3) * 2);
        cst1[nb] = cst0[nb] + slope2;
    }
    // base0 = slope2 * (ktile*64 - qr0); starts at ktile = qt
    float base0 = -slope2 * (float)(wid * 16 + (lane >> 2));
    const float base_step = 64.0f * slope2;

    for (int it = 0; it < nkt; it++) {
        const int ktile = qt - it;
        if (it + 1 < nkt) { CP_WAIT1(); } else { CP_WAIT0(); }
        __syncthreads();
        if (it == 0) {
            // hoist Q fragments to registers (once); Q region is reused as stage 2
#pragma unroll
            for (int kb = 0; kb < 4; kb++) {
                int row = wid * 16 + ((g & 1) << 3) + rl;
                int gr = kb * 2 + (g >> 1);
                int off = row * 128 + gr * 16;
                uint32_t sw = (uint32_t)(off ^ ((off >> 3) & 0x70));
                ldsm_x4(qAh[kb][0], qAh[kb][1], qAh[kb][2], qAh[kb][3], sb + FQ_H + sw);
                ldsm_x4(qAl[kb][0], qAl[kb][1], qAl[kb][2], qAl[kb][3], sb + FQ_L + sw);
            }
            if (nkt > 2) __syncthreads();
        }
        if (it + 2 < nkt)
            f_issue_stage(sb + (uint32_t)((it + 2) % 3) * FSTG_SZ, tid, b, h, comp, qt - (it + 2), amask);
        uint32_t stg = sb + (uint32_t)(it % 3) * FSTG_SZ;

        // ---- S = Q K^T (x3 split), 64 keys ----
        float sa[8][4];
#pragma unroll
        for (int j = 0; j < 8; j++)
#pragma unroll
            for (int d = 0; d < 4; d++) sa[j][d] = 0.f;
#pragma unroll
        for (int kb = 0; kb < 4; kb++) {
#pragma unroll
            for (int nb2 = 0; nb2 < 4; nb2++) {
                uint32_t kh4[4], kl4[4];
                int row = nb2 * 16 + ((g >> 1) << 3) + rl;
                int gr = kb * 2 + (g & 1);
                int off = row * 128 + gr * 16;
                uint32_t sw = (uint32_t)(off ^ ((off >> 3) & 0x70));
                ldsm_x4(kh4[0], kh4[1], kh4[2], kh4[3], stg + FK_H + sw);
                ldsm_x4(kl4[0], kl4[1], kl4[2], kl4[3], stg + FK_L + sw);
                MMA16816(sa[nb2 * 2], qAh[kb], &kh4[0]);
                MMA16816(sa[nb2 * 2], qAh[kb], &kl4[0]);
                MMA16816(sa[nb2 * 2], qAl[kb], &kh4[0]);
                MMA16816(sa[nb2 * 2 + 1], qAh[kb], &kh4[2]);
                MMA16816(sa[nb2 * 2 + 1], qAh[kb], &kl4[2]);
                MMA16816(sa[nb2 * 2 + 1], qAl[kb], &kh4[2]);
            }
        }

        // ---- bias + masks (base-2 domain) ----
        const float* ams = (const float*)(fsm + (stg - sb) + FAM);
        float colc[8][2];
#pragma unroll
        for (int nb = 0; nb < 8; nb++) {
            int kc = nb * 8 + (lane & 3) * 2;
            colc[nb][0] = fmaf(1.0f - ams[kc],     NEGV2, base0 + cst0[nb]);
            colc[nb][1] = fmaf(1.0f - ams[kc + 1], NEGV2, base0 + cst1[nb]);
        }
#pragma unroll
        for (int nb = 0; nb < 8; nb++) {
            sa[nb][0] = fmaf(sa[nb][0], scale2, colc[nb][0]);
            sa[nb][1] = fmaf(sa[nb][1], scale2, colc[nb][1]);
            sa[nb][2] = fmaf(sa[nb][2], scale2, colc[nb][0] + d8);
            sa[nb][3] = fmaf(sa[nb][3], scale2, colc[nb][1] + d8);
        }
        if (it == 0) {
            // causal mask (diagonal tile only)
            const int kcb = ktile * 64;
#pragma unroll
            for (int nb = 0; nb < 8; nb++) {
                int k0 = kcb + nb * 8 + (lane & 3) * 2;
                if (k0 > qr0)         sa[nb][0] += NEGV2;
                if (k0 + 1 > qr0)     sa[nb][1] += NEGV2;
                if (k0 > qr0 + 8)     sa[nb][2] += NEGV2;
                if (k0 + 1 > qr0 + 8) sa[nb][3] += NEGV2;
            }
        }
        base0 -= base_step;

        // ---- online softmax (base 2; l kept lane-local) ----
        float mx0 = -1e30f, mx1 = -1e30f;
#pragma unroll
        for (int nb = 0; nb < 8; nb++) {
            mx0 = fmaxf(mx0, fmaxf(sa[nb][0], sa[nb][1]));
            mx1 = fmaxf(mx1, fmaxf(sa[nb][2], sa[nb][3]));
        }
        mx0 = fmaxf(mx0, __shfl_xor_sync(0xffffffffu, mx0, 1));
        mx0 = fmaxf(mx0, __shfl_xor_sync(0xffffffffu, mx0, 2));
        mx1 = fmaxf(mx1, __shfl_xor_sync(0xffffffffu, mx1, 1));
        mx1 = fmaxf(mx1, __shfl_xor_sync(0xffffffffu, mx1, 2));
        float mn0 = fmaxf(m0, mx0), mn1 = fmaxf(m1, mx1);
        float al0 = fast_exp2(m0 - mn0), al1 = fast_exp2(m1 - mn1);
        m0 = mn0; m1 = mn1;
        float ls0 = 0.f, ls1 = 0.f;
#pragma unroll
        for (int nb = 0; nb < 8; nb++) {
            sa[nb][0] = fast_exp2(sa[nb][0] - mn0);
            sa[nb][1] = fast_exp2(sa[nb][1] - mn0);
            sa[nb][2] = fast_exp2(sa[nb][2] - mn1);
            sa[nb][3] = fast_exp2(sa[nb][3] - mn1);
            ls0 += sa[nb][0] + sa[nb][1];
            ls1 += sa[nb][2] + sa[nb][3];
        }
        l0 = l0 * al0 + ls0;
        l1 = l1 * al1 + ls1;

        // rescale O unless max unchanged warp-wide
        bool noresc = __all_sync(0xffffffffu, (al0 == 1.0f) && (al1 == 1.0f));
        if (!noresc) {
#pragma unroll
            for (int j = 0; j < 8; j++) {
                oa[j][0] *= al0; oa[j][1] *= al0;
                oa[j][2] *= al1; oa[j][3] *= al1;
            }
        }

        // ---- O += P V (x3 split); P packed per key-block ----
#pragma unroll
        for (int kb2 = 0; kb2 < 4; kb2++) {
            uint32_t pAh[4], pAl[4];
#pragma unroll
            for (int half = 0; half < 2; half++) {
                float v0a = sa[kb2 * 2][half * 2], v1a = sa[kb2 * 2][half * 2 + 1];
                float v0b = sa[kb2 * 2 + 1][half * 2], v1b = sa[kb2 * 2 + 1][half * 2 + 1];
                __nv_bfloat16 h0a = __float2bfloat16(v0a), h1a = __float2bfloat16(v1a);
                __nv_bfloat16 h0b = __float2bfloat16(v0b), h1b = __float2bfloat16(v1b);
                pAh[half]     = pack_bf2(__bfloat162float(h0a), __bfloat162float(h1a));
                pAh[2 + half] = pack_bf2(__bfloat162float(h0b), __bfloat162float(h1b));
                pAl[half]     = pack_bf2(v0a - __bfloat162float(h0a), v1a - __bfloat162float(h1a));
                pAl[2 + half] = pack_bf2(v0b - __bfloat162float(h0b), v1b - __bfloat162float(h1b));
            }
#pragma unroll
            for (int db = 0; db < 4; db++) {
                uint32_t vh4[4], vl4[4];
                int row = kb2 * 16 + ((g & 1) << 3) + rl;
                int gr = db * 2 + (g >> 1);
                int off = row * 128 + gr * 16;
                uint32_t sw = (uint32_t)(off ^ ((off >> 3) & 0x70));
                ldsm_x4t(vh4[0], vh4[1], vh4[2], vh4[3], stg + FV_H + sw);
                ldsm_x4t(vl4[0], vl4[1], vl4[2], vl4[3], stg + FV_L + sw);
                MMA16816(oa[db * 2], pAh, &vh4[0]);
                MMA16816(oa[db * 2], pAh, &vl4[0]);
                MMA16816(oa[db * 2], pAl, &vh4[0]);
                MMA16816(oa[db * 2 + 1], pAh, &vh4[2]);
                MMA16816(oa[db * 2 + 1], pAh, &vl4[2]);
                MMA16816(oa[db * 2 + 1], pAl, &vh4[2]);
            }
        }
    }

    // ---- epilogue: reduce lane-local l, then write ----
    l0 += __shfl_xor_sync(0xffffffffu, l0, 1);
    l0 += __shfl_xor_sync(0xffffffffu, l0, 2);
    l1 += __shfl_xor_sync(0xffffffffu, l1, 1);
    l1 += __shfl_xor_sync(0xffffffffu, l1, 2);
    float inv0 = 1.0f / l0, inv1 = 1.0f / l1;
    float* Og = (comp ? g_o2 : g_o1) + ((size_t)(b * S_) + qr0) * (H_ * DH_) + h * 64;
#pragma unroll
    for (int j = 0; j < 8; j++) {
        int col = j * 8 + (lane & 3) * 2;
        *(float2*)&Og[col] = make_float2(oa[j][0] * inv0, oa[j][1] * inv0);
        *(float2*)&Og[(size_t)8 * (H_ * DH_) + col] = make_float2(oa[j][2] * inv1, oa[j][3] * inv1);
    }
}

// ---------------- combine + groupnorm stats ---------------------------------
__global__ void __launch_bounds__(256) combine_stats_kernel() {
    const int bh = blockIdx.x >> 3;
    const int slice = blockIdx.x & 7;
    const int b = bh / H_, h = bh % H_;
    const float lam = g_lambda;
    double s = 0.0, ss = 0.0;
    const int base_row = b * S_ + slice * 256;
    for (int f = threadIdx.x; f < 256 * (DH_ / 4); f += 256) {
        int row = f >> 4, c = (f & 15) * 4;
        size_t e = (size_t)(base_row + row) * (H_ * DH_) + h * DH_ + c;
        float4 a = *(const float4*)&g_o1[e];
        float4 cc = *(const float4*)&g_o2[e];
        float4 y;
        y.x = a.x - lam * cc.x; y.y = a.y - lam * cc.y;
        y.z = a.z - lam * cc.z; y.w = a.w - lam * cc.w;
        *(float4*)&g_o[e] = y;
        s += (double)y.x + y.y + y.z + y.w;
        ss += (double)y.x * y.x + (double)y.y * y.y + (double)y.z * y.z + (double)y.w * y.w;
    }
    __shared__ double sh_s[256], sh_ss[256];
    sh_s[threadIdx.x] = s; sh_ss[threadIdx.x] = ss;
    __syncthreads();
    for (int st = 128; st > 0; st >>= 1) {
        if (threadIdx.x < st) {
            sh_s[threadIdx.x] += sh_s[threadIdx.x + st];
            sh_ss[threadIdx.x] += sh_ss[threadIdx.x + st];
        }
        __syncthreads();
    }
    if (threadIdx.x == 0) {
        atomicAdd(&g_sum[bh], sh_s[0]);
        atomicAdd(&g_sumsq[bh], sh_ss[0]);
    }
}

// ---------------- normalize + emit bf16 hi/lo -------------------------------
__global__ void __launch_bounds__(256) gn_apply_kernel(const float* __restrict__ gamma,
                                                       const float* __restrict__ beta) {
    int f = blockIdx.x * blockDim.x + threadIdx.x;
    if (f >= (B_ * S_ * H_ * DH_) / 4) return;
    int e = f * 4;
    int c = e % (H_ * DH_);
    int row = e / (H_ * DH_);
    int b = row / S_;
    int h = c / DH_;
    const double n = (double)S_ * DH_;
    double sm = g_sum[b * H_ + h], sq = g_sumsq[b * H_ + h];
    double meand = sm / n;
    float mean = (float)meand;
    float inv = rsqrtf((float)(sq / n - meand * meand) + EPS_);
    float4 x = *(const float4*)&g_o[e];
    float4 gm = *(const float4*)&gamma[c];
    float4 bt = *(const float4*)&beta[c];
    const float post = 1.0f - LAMBDA_INIT;
    float y[4];
    y[0] = ((x.x - mean) * inv * gm.x + bt.x) * post;
    y[1] = ((x.y - mean) * inv * gm.y + bt.y) * post;
    y[2] = ((x.z - mean) * inv * gm.z + bt.z) * post;
    y[3] = ((x.w - mean) * inv * gm.w + bt.w) * post;
    __nv_bfloat16 hh[4], ll[4];
#pragma unroll
    for (int j = 0; j < 4; j++) {
        hh[j] = __float2bfloat16(y[j]);
        ll[j] = __float2bfloat16(y[j] - __bfloat162float(hh[j]));
    }
    *(uint2*)&g_nh[e] = *(uint2*)hh;
    *(uint2*)&g_nl[e] = *(uint2*)ll;
}

// ---------------- launch ----------------------------------------------------
extern "C" void kernel_launch(void* const* d_in, const int* in_sizes, int n_in,
                              void* d_out, int out_size) {
    const float* x     = (const float*)d_in[0];
    const float* amask = (const float*)d_in[1];
    const float* Wq = (const float*)d_in[3];
    const float* Wk = (const float*)d_in[4];
    const float* Wv = (const float*)d_in[5];
    const float* Wo = (const float*)d_in[6];
    const float* lq1 = (const float*)d_in[7];
    const float* lq2 = (const float*)d_in[8];
    const float* lk1 = (const float*)d_in[9];
    const float* lk2 = (const float*)d_in[10];
    const float* gam = (const float*)d_in[11];
    const float* bet = (const float*)d_in[12];
    float* out = (float*)d_out;

    __nv_bfloat16 *woh, *wol, *nh, *nl;
    cudaGetSymbolAddress((void**)&woh, g_woh); cudaGetSymbolAddress((void**)&wol, g_wol);
    cudaGetSymbolAddress((void**)&nh, g_nh);   cudaGetSymbolAddress((void**)&nl, g_nl);

    const int M = B_ * S_;  // 4096

    // 0: lambda + zero stats
    lam_kernel<<<1, 1>>>(lq1, lq2, lk1, lk2);
    // 1: all fp32->bf16 hi/lo splits
    cvt_all<<<N4_TOT / 256, 256>>>(x, Wq, Wk, Wv, Wo);
    // 2: fused QKV projection
    cudaFuncSetAttribute(gemm_qkv, cudaFuncAttributeMaxDynamicSharedMemorySize, G_SMEM);
    gemm_qkv<<<dim3(40, M / 128), 256, G_SMEM>>>();
    // 3: flash attention (profiled)
    cudaFuncSetAttribute(flashmma_kernel, cudaFuncAttributeMaxDynamicSharedMemorySize, FL_SMEM);
    flashmma_kernel<<<dim3(S_ / 64, B_ * H_ * 2), 128, FL_SMEM>>>(amask);
    // 4: combine + stats
    combine_stats_kernel<<<B_ * H_ * 8, 256>>>();
    // 5: normalize + split
    gn_apply_kernel<<<(B_ * S_ * H_ * DH_ / 4 + 255) / 256, 256>>>(gam, bet);
    // 6: output projection
    cudaFuncSetAttribute(gemm_o, cudaFuncAttributeMaxDynamicSharedMemorySize, G_SMEM);
    gemm_o<<<dim3(D_ / 128, M / 128), 256, G_SMEM>>>(nh, nl, woh, wol, out, M, D_, H_ * DH_);
}